// round 1
// baseline (speedup 1.0000x reference)
#include <cuda_runtime.h>
#include <math.h>

// ---------------- problem constants ----------------
#define BSZ     8
#define SENC    3072
#define PRED    1024
#define ENCIN   40
#define DMODEL  128
#define NHEADS  4
#define DHEAD   32
#define NHASH   4
#define NBUCK   64
#define BUCKETSZ 64
#define NLAYERS 2
#define DFF     512
#define COUT    4
#define NCLASS  3
#define MARK    4
#define TLEN    4096
#define BHN     (BSZ*NHEADS)          // 32
#define MROWS   (BSZ*TLEN)            // 32768
#define NCHUNK  (NHASH*TLEN/BUCKETSZ) // 256
#define ITEMS   (NHASH*TLEN)          // 16384 per bh

// ---------------- scratch (device globals; no allocation allowed) ----------------
__device__ float g_h[MROWS*DMODEL];       // activations (B,T,D)
__device__ float g_res[MROWS*DMODEL];     // pre-LN residual buffer
__device__ float g_ff[MROWS*DFF];         // FFN intermediate; also reused for "rotated"
__device__ float g_qk[BHN*TLEN*DHEAD];    // shared q/k per head
__device__ float g_v[BHN*TLEN*DHEAD];
__device__ float g_so[(long)BHN*ITEMS*DHEAD]; // attention out per sorted pos
__device__ float g_lse[BHN*ITEMS];
__device__ int   g_st[BHN*ITEMS];         // sorted position -> t
__device__ int   g_pos[BHN*ITEMS];        // (h,t) -> sorted position
__device__ unsigned char g_bkt[BHN*ITEMS];
__device__ int   g_base[BHN*256];
__device__ float g_attn[MROWS*DMODEL];

// ---------------- embedding ----------------
__global__ void embed_kernel(const float* __restrict__ xe, const float* __restrict__ xme,
                             const float* __restrict__ xd, const float* __restrict__ xmd,
                             const float* __restrict__ convw, const float* __restrict__ tw) {
  int bt = blockIdx.x; int b = bt / TLEN; int t = bt % TLEN;
  int d = threadIdx.x;                    // 128 threads, one per output dim
  __shared__ float sx[3][ENCIN];
  __shared__ float sm[MARK];
  for (int i = d; i < 3*ENCIN; i += 128) {
    int k = i / ENCIN, c = i % ENCIN;
    int tt = t - 1 + k; tt = (tt + TLEN) % TLEN;  // circular pad
    float v = (tt < SENC) ? xe[(b*SENC + tt)*ENCIN + c]
                          : xd[(b*PRED + (tt - SENC))*ENCIN + c];
    sx[k][c] = v;
  }
  if (d < MARK)
    sm[d] = (t < SENC) ? xme[(b*SENC + t)*MARK + d]
                       : xmd[(b*PRED + (t - SENC))*MARK + d];
  __syncthreads();
  float acc = 0.f;
  #pragma unroll
  for (int k = 0; k < 3; k++)
    #pragma unroll
    for (int c = 0; c < ENCIN; c++)
      acc += sx[k][c] * convw[(k*ENCIN + c)*DMODEL + d];
  #pragma unroll
  for (int m = 0; m < MARK; m++) acc += sm[m] * tw[m*DMODEL + d];
  // sinusoidal PE
  int i2 = (d >> 1) * 2;
  float div = expf((float)i2 * (-logf(10000.f) / (float)DMODEL));
  float ang = (float)t * div;
  acc += (d & 1) ? cosf(ang) : sinf(ang);
  g_h[(bt)*DMODEL + d] = acc;
}

// ---------------- generic fp32 GEMM (M,N mult of 64; K mult of 16) ----------------
// EPI: 0 = none, 2 = +bias +residual, 3 = +bias, exact GELU
// SPLIT: 1 = scatter output into (b, head, t, dh) layout
template<int EPI, int SPLIT>
__global__ void __launch_bounds__(256) gemm_kernel(
    const float* __restrict__ A, const float* __restrict__ B,
    const float* __restrict__ bias, const float* __restrict__ R,
    float* __restrict__ C, int M, int N, int K) {
  __shared__ float As[16][65];
  __shared__ float Bs[16][64];
  int tid = threadIdx.x;
  int tx = tid & 15, ty = tid >> 4;
  int bm = blockIdx.y * 64, bn = blockIdx.x * 64;
  float acc[4][4] = {};
  for (int k0 = 0; k0 < K; k0 += 16) {
    #pragma unroll
    for (int i = 0; i < 4; i++) {
      int r = ty + i*16;
      As[tx][r] = A[(bm + r)*K + k0 + tx];
    }
    #pragma unroll
    for (int i = 0; i < 4; i++) {
      int kk = (tid >> 6) + i*4;
      int c = tid & 63;
      Bs[kk][c] = B[(k0 + kk)*N + bn + c];
    }
    __syncthreads();
    #pragma unroll
    for (int kk = 0; kk < 16; kk++) {
      float a[4], bb[4];
      #pragma unroll
      for (int i = 0; i < 4; i++) a[i] = As[kk][ty + i*16];
      #pragma unroll
      for (int j = 0; j < 4; j++) bb[j] = Bs[kk][tx + j*16];
      #pragma unroll
      for (int i = 0; i < 4; i++)
        #pragma unroll
        for (int j = 0; j < 4; j++)
          acc[i][j] += a[i]*bb[j];
    }
    __syncthreads();
  }
  #pragma unroll
  for (int i = 0; i < 4; i++) {
    int r = bm + ty + i*16;
    #pragma unroll
    for (int j = 0; j < 4; j++) {
      int c = bn + tx + j*16;
      float v = acc[i][j];
      if (EPI >= 2) v += bias[c];
      if (EPI == 2) v += R[r*N + c];
      if (EPI == 3) v = 0.5f*v*(1.f + erff(v*0.70710678118f));
      if (SPLIT) {
        int b = r / TLEN, t = r % TLEN;
        int hd = c >> 5, dh = c & 31;
        C[((b*NHEADS + hd)*TLEN + t)*DHEAD + dh] = v;
      } else {
        C[r*N + c] = v;
      }
    }
  }
}

// ---------------- bucket argmax over [rotated, -rotated] ----------------
// rotated stored in g_ff as (BHN*TLEN, 128) row-major; segment h = cols [h*32, h*32+32)
__global__ void bucket_argmax_kernel() {
  int tid = threadIdx.x;        // 128 threads = 4 warps
  int lane = tid & 31;
  long row = (long)blockIdx.x * 4 + (tid >> 5);   // bh*TLEN + t
  int bh = (int)(row >> 12);
  int t  = (int)(row & (TLEN - 1));
  const float* rp = g_ff + row * 128;
  #pragma unroll
  for (int h = 0; h < NHASH; h++) {
    float v = rp[h*32 + lane];
    float val; int bi;
    if (v >= -v) { val = v; bi = lane; } else { val = -v; bi = lane + 32; }
    #pragma unroll
    for (int off = 16; off; off >>= 1) {
      float ov = __shfl_xor_sync(0xffffffffu, val, off);
      int   oi = __shfl_xor_sync(0xffffffffu, bi,  off);
      if (ov > val || (ov == val && oi < bi)) { val = ov; bi = oi; }
    }
    if (lane == 0) g_bkt[(bh*NHASH + h)*TLEN + t] = (unsigned char)bi;
  }
}

// ---------------- counting-sort: histogram + exclusive scan ----------------
__global__ void hist_kernel() {
  __shared__ int cnt[256];
  int bh = blockIdx.x, tid = threadIdx.x;   // 256 threads
  cnt[tid] = 0; __syncthreads();
  const unsigned char* bp = g_bkt + bh*ITEMS;
  for (int i = tid; i < ITEMS; i += 256) {
    int gb = ((i >> 12) << 6) + bp[i];      // global bucket = h*64 + local
    atomicAdd(&cnt[gb], 1);
  }
  __syncthreads();
  if (tid == 0) {
    int s = 0;
    #pragma unroll 8
    for (int j = 0; j < 256; j++) { g_base[bh*256 + j] = s; s += cnt[j]; }
  }
}

// stable placement: one block per (bh, hash); 32 warps, each warp owns 2 buckets
__global__ void __launch_bounds__(1024) place_kernel() {
  int bhh = blockIdx.x;
  int bh = bhh >> 2, h = bhh & 3;
  int warp = threadIdx.x >> 5, lane = threadIdx.x & 31;
  const unsigned char* bp = g_bkt + (bh*NHASH + h)*TLEN;
  #pragma unroll
  for (int s = 0; s < 2; s++) {
    int lb = warp*2 + s;
    int base = g_base[bh*256 + h*64 + lb];
    for (int t0 = 0; t0 < TLEN; t0 += 32) {
      int my = bp[t0 + lane];
      unsigned mask = __ballot_sync(0xffffffffu, my == lb);
      if (my == lb) {
        int p = base + __popc(mask & ((1u << lane) - 1u));
        g_st[bh*ITEMS + p] = t0 + lane;
        g_pos[(bh*NHASH + h)*TLEN + t0 + lane] = p;
      }
      base += __popc(mask);
    }
  }
}

// ---------------- chunked LSH attention: one CTA per (bh, chunk) ----------------
__global__ void __launch_bounds__(256) attn_kernel() {
  int bh = blockIdx.x >> 8;
  int c  = blockIdx.x & 255;
  int pc = (c + NCHUNK - 1) & 255;            // look one chunk back (rolled)
  __shared__ float s_q[64][33];
  __shared__ float s_k[128][33];
  __shared__ float s_v[128][33];
  __shared__ float s_inv[128];
  __shared__ int   s_qt[64];
  __shared__ int   s_kt[128];
  int tid = threadIdx.x;
  if (tid < 64) {
    s_qt[tid] = g_st[bh*ITEMS + c*64 + tid];
  } else if (tid < 192) {
    int j = tid - 64;
    int p = (j < 64) ? (c*64 + j) : (pc*64 + (j - 64));
    s_kt[j] = g_st[bh*ITEMS + p];
  }
  __syncthreads();
  for (int idx = tid; idx < 64*32; idx += 256) {
    int i = idx >> 5, d = idx & 31;
    s_q[i][d] = g_qk[((long)bh*TLEN + s_qt[i])*DHEAD + d];
  }
  for (int idx = tid; idx < 128*32; idx += 256) {
    int j = idx >> 5, d = idx & 31;
    int t = s_kt[j];
    s_k[j][d] = g_qk[((long)bh*TLEN + t)*DHEAD + d];
    s_v[j][d] = g_v[((long)bh*TLEN + t)*DHEAD + d];
  }
  __syncthreads();
  if (tid < 128) {
    float s = 0.f;
    #pragma unroll
    for (int d = 0; d < 32; d++) { float x = s_k[tid][d]; s += x*x; }
    s_inv[tid] = 1.f / fmaxf(sqrtf(s), 1e-12f);
  }
  __syncthreads();

  int row = tid >> 2, sub = tid & 3;
  int j0 = sub * 32;
  float qreg[32];
  #pragma unroll
  for (int d = 0; d < 32; d++) qreg[d] = s_q[row][d];
  int qt = s_qt[row];

  float dots[32];
  float m = -1e30f;
  #pragma unroll 4
  for (int jj = 0; jj < 32; jj++) {
    int j = j0 + jj;
    float dot = 0.f;
    #pragma unroll
    for (int d = 0; d < 32; d++) dot += qreg[d] * s_k[j][d];
    dot = (s_kt[j] == qt) ? -5e4f : dot * s_inv[j] * 0.17677669529663689f;
    dots[jj] = dot;
    m = fmaxf(m, dot);
  }
  m = fmaxf(m, __shfl_xor_sync(0xffffffffu, m, 1));
  m = fmaxf(m, __shfl_xor_sync(0xffffffffu, m, 2));
  float ssum = 0.f;
  #pragma unroll
  for (int jj = 0; jj < 32; jj++) { dots[jj] = expf(dots[jj] - m); ssum += dots[jj]; }
  ssum += __shfl_xor_sync(0xffffffffu, ssum, 1);
  ssum += __shfl_xor_sync(0xffffffffu, ssum, 2);
  float lse = m + logf(ssum);
  float inv = 1.f / ssum;

  float out[32];
  #pragma unroll
  for (int d = 0; d < 32; d++) out[d] = 0.f;
  #pragma unroll 4
  for (int jj = 0; jj < 32; jj++) {
    float p = dots[jj];
    int j = j0 + jj;
    #pragma unroll
    for (int d = 0; d < 32; d++) out[d] += p * s_v[j][d];
  }
  __syncthreads();    // all reads of s_q/s_k/s_v finished -> safe to reuse s_q
  #pragma unroll
  for (int d = 0; d < 32; d++) {
    float o = out[d];
    o += __shfl_xor_sync(0xffffffffu, o, 1);
    o += __shfl_xor_sync(0xffffffffu, o, 2);
    out[d] = o * inv;
  }
  if (sub == 0) {
    #pragma unroll
    for (int d = 0; d < 32; d++) s_q[row][d] = out[d];
    g_lse[bh*ITEMS + c*64 + row] = lse;
  }
  __syncthreads();
  for (int idx = tid; idx < 64*32; idx += 256) {
    int i = idx >> 5, d = idx & 31;
    g_so[((long)bh*ITEMS + c*64 + i)*DHEAD + d] = s_q[i][d];
  }
}

// ---------------- cross-hash combine + unsort + head merge ----------------
__global__ void combine_kernel() {
  int tid = threadIdx.x;                      // 128 threads = 4 warps
  int lane = tid & 31;
  long gw = (long)blockIdx.x * 4 + (tid >> 5);   // bh*TLEN + t
  int bh = (int)(gw >> 12);
  int t  = (int)(gw & (TLEN - 1));
  float lse[NHASH], val[NHASH];
  int pidx[NHASH];
  #pragma unroll
  for (int h = 0; h < NHASH; h++) {
    pidx[h] = g_pos[(bh*NHASH + h)*TLEN + t];
    lse[h]  = g_lse[bh*ITEMS + pidx[h]];
    val[h]  = g_so[((long)bh*ITEMS + pidx[h])*DHEAD + lane];
  }
  float m = lse[0];
  #pragma unroll
  for (int h = 1; h < NHASH; h++) m = fmaxf(m, lse[h]);
  float acc = 0.f, wsum = 0.f;
  #pragma unroll
  for (int h = 0; h < NHASH; h++) {
    float w = expf(lse[h] - m);
    acc += w * val[h]; wsum += w;
  }
  int b = bh >> 2, head = bh & 3;
  g_attn[((long)b*TLEN + t)*DMODEL + head*DHEAD + lane] = acc / wsum;
}

// ---------------- layernorm (one CTA per row) ----------------
__global__ void ln_kernel(const float* __restrict__ in, float* __restrict__ out,
                          const float* __restrict__ g, const float* __restrict__ bb) {
  int row = blockIdx.x, d = threadIdx.x;      // 128 threads
  __shared__ float red[4];
  float x = in[(long)row*DMODEL + d];
  float s = x;
  #pragma unroll
  for (int off = 16; off; off >>= 1) s += __shfl_xor_sync(0xffffffffu, s, off);
  if ((d & 31) == 0) red[d >> 5] = s;
  __syncthreads();
  float mean = (red[0]+red[1]+red[2]+red[3]) * (1.f/DMODEL);
  float dv = x - mean;
  float s2 = dv*dv;
  #pragma unroll
  for (int off = 16; off; off >>= 1) s2 += __shfl_xor_sync(0xffffffffu, s2, off);
  __syncthreads();
  if ((d & 31) == 0) red[d >> 5] = s2;
  __syncthreads();
  float var = (red[0]+red[1]+red[2]+red[3]) * (1.f/DMODEL);
  out[(long)row*DMODEL + d] = dv * rsqrtf(var + 1e-5f) * g[d] + bb[d];
}

// ---------------- final projection + pooled logits + softmax ----------------
__global__ void head_kernel(const float* __restrict__ projw, const float* __restrict__ projb,
                            const float* __restrict__ fcw, const float* __restrict__ fcb,
                            float* __restrict__ dout) {
  int b = blockIdx.x, tid = threadIdx.x;      // 128 threads
  float lg0 = 0.f, lg1 = 0.f, lg2 = 0.f;
  for (int tt = tid; tt < PRED; tt += 128) {
    const float* hr = g_h /*unused*/ + 0;     // silence
    const float* hh = g_res + ((long)b*TLEN + SENC + tt)*DMODEL;
    float o4[4];
    #pragma unroll
    for (int cc = 0; cc < 4; cc++) {
      float a = projb[cc];
      #pragma unroll 8
      for (int d = 0; d < DMODEL; d++) a += hh[d]*projw[d*4 + cc];
      o4[cc] = a;
    }
    #pragma unroll
    for (int cc = 0; cc < 4; cc++) {
      int idx = (tt*4 + cc)*3;
      lg0 += o4[cc]*fcw[idx+0];
      lg1 += o4[cc]*fcw[idx+1];
      lg2 += o4[cc]*fcw[idx+2];
    }
    (void)hr;
  }
  __shared__ float red[3][128];
  red[0][tid] = lg0; red[1][tid] = lg1; red[2][tid] = lg2;
  __syncthreads();
  for (int off = 64; off; off >>= 1) {
    if (tid < off) {
      red[0][tid] += red[0][tid+off];
      red[1][tid] += red[1][tid+off];
      red[2][tid] += red[2][tid+off];
    }
    __syncthreads();
  }
  if (tid == 0) {
    float l0 = red[0][0]+fcb[0], l1 = red[1][0]+fcb[1], l2 = red[2][0]+fcb[2];
    float mx = fmaxf(l0, fmaxf(l1, l2));
    float e0 = expf(l0-mx), e1 = expf(l1-mx), e2 = expf(l2-mx);
    float is = 1.f/(e0+e1+e2);
    dout[b*3+0] = e0*is; dout[b*3+1] = e1*is; dout[b*3+2] = e2*is;
  }
}

// ---------------- host launch ----------------
extern "C" void kernel_launch(void* const* d_in, const int* in_sizes, int n_in,
                              void* d_out, int out_size) {
  const float* x_enc      = (const float*)d_in[0];
  const float* x_mark_enc = (const float*)d_in[1];
  const float* x_dec      = (const float*)d_in[2];
  const float* x_mark_dec = (const float*)d_in[3];
  const float* conv_w     = (const float*)d_in[4];
  const float* timef_w    = (const float*)d_in[5];
  const float* Wqk        = (const float*)d_in[6];
  const float* Wv         = (const float*)d_in[7];
  const float* Wo         = (const float*)d_in[8];
  const float* bo         = (const float*)d_in[9];
  const float* rot        = (const float*)d_in[10];
  const float* ln1_g      = (const float*)d_in[11];
  const float* ln1_b      = (const float*)d_in[12];
  const float* ln2_g      = (const float*)d_in[13];
  const float* ln2_b      = (const float*)d_in[14];
  const float* w1         = (const float*)d_in[15];
  const float* b1         = (const float*)d_in[16];
  const float* w2         = (const float*)d_in[17];
  const float* b2         = (const float*)d_in[18];
  const float* lnf_g      = (const float*)d_in[19];
  const float* lnf_b      = (const float*)d_in[20];
  const float* proj_w     = (const float*)d_in[21];
  const float* proj_b     = (const float*)d_in[22];
  const float* fc1_w      = (const float*)d_in[23];
  const float* fc1_b      = (const float*)d_in[24];
  (void)in_sizes; (void)n_in; (void)out_size;

  void* p;
  cudaGetSymbolAddress(&p, g_h);    float* ph    = (float*)p;
  cudaGetSymbolAddress(&p, g_res);  float* pres  = (float*)p;
  cudaGetSymbolAddress(&p, g_ff);   float* pff   = (float*)p;
  cudaGetSymbolAddress(&p, g_qk);   float* pqk   = (float*)p;
  cudaGetSymbolAddress(&p, g_v);    float* pv    = (float*)p;
  cudaGetSymbolAddress(&p, g_attn); float* pattn = (float*)p;

  // embedding
  embed_kernel<<<MROWS, 128>>>(x_enc, x_mark_enc, x_dec, x_mark_dec, conv_w, timef_w);

  for (int l = 0; l < NLAYERS; l++) {
    const float* Wqk_l = Wqk + (long)l*DMODEL*DMODEL;
    const float* Wv_l  = Wv  + (long)l*DMODEL*DMODEL;
    const float* Wo_l  = Wo  + (long)l*DMODEL*DMODEL;
    const float* bo_l  = bo  + l*DMODEL;
    const float* rot_l = rot + (long)l*DHEAD*NHASH*(NBUCK/2);
    const float* w1_l  = w1 + (long)l*DMODEL*DFF;
    const float* b1_l  = b1 + l*DFF;
    const float* w2_l  = w2 + (long)l*DFF*DMODEL;
    const float* b2_l  = b2 + l*DMODEL;

    // qk / v projections with head-split scatter
    gemm_kernel<0,1><<<dim3(2,512), 256>>>(ph, Wqk_l, nullptr, nullptr, pqk, MROWS, DMODEL, DMODEL);
    gemm_kernel<0,1><<<dim3(2,512), 256>>>(ph, Wv_l,  nullptr, nullptr, pv,  MROWS, DMODEL, DMODEL);

    // rotations: (BHN*TLEN, 32) @ (32, 128) -> g_ff, then argmax
    gemm_kernel<0,0><<<dim3(2,2048), 256>>>(pqk, rot_l, nullptr, nullptr, pff, BHN*TLEN, 128, DHEAD);
    bucket_argmax_kernel<<<BHN*TLEN/4, 128>>>();

    // stable counting sort
    hist_kernel<<<BHN, 256>>>();
    place_kernel<<<BHN*NHASH, 1024>>>();

    // chunked attention + cross-hash combine
    attn_kernel<<<BHN*NCHUNK, 256>>>();
    combine_kernel<<<BHN*TLEN/4, 128>>>();

    // output projection + residual, LN1
    gemm_kernel<2,0><<<dim3(2,512), 256>>>(pattn, Wo_l, bo_l, ph, pres, MROWS, DMODEL, DMODEL);
    ln_kernel<<<MROWS, 128>>>(pres, ph, ln1_g + l*DMODEL, ln1_b + l*DMODEL);

    // FFN
    gemm_kernel<3,0><<<dim3(8,512), 256>>>(ph, w1_l, b1_l, nullptr, pff, MROWS, DFF, DMODEL);
    gemm_kernel<2,0><<<dim3(2,512), 256>>>(pff, w2_l, b2_l, ph, pres, MROWS, DMODEL, DFF);
    ln_kernel<<<MROWS, 128>>>(pres, ph, ln2_g + l*DMODEL, ln2_b + l*DMODEL);
  }

  // final LN + head
  ln_kernel<<<MROWS, 128>>>(ph, pres, lnf_g, lnf_b);
  head_kernel<<<BSZ, 128>>>(proj_w, proj_b, fc1_w, fc1_b, (float*)d_out);
}

// round 2
// speedup vs baseline: 2.5261x; 2.5261x over previous
#include <cuda_runtime.h>
#include <math.h>

// ---------------- problem constants ----------------
#define BSZ     8
#define SENC    3072
#define PRED    1024
#define ENCIN   40
#define DMODEL  128
#define NHEADS  4
#define DHEAD   32
#define NHASH   4
#define NBUCK   64
#define BUCKETSZ 64
#define NLAYERS 2
#define DFF     512
#define COUT    4
#define NCLASS  3
#define MARK    4
#define TLEN    4096
#define BHN     (BSZ*NHEADS)          // 32
#define MROWS   (BSZ*TLEN)            // 32768
#define NCHUNK  (NHASH*TLEN/BUCKETSZ) // 256
#define ITEMS   (NHASH*TLEN)          // 16384 per bh
#define ATTN_SCALE 0.17677669529663689f

// ---------------- scratch (device globals; no allocation allowed) ----------------
__device__ float g_h[MROWS*DMODEL];
__device__ float g_res[MROWS*DMODEL];
__device__ float g_ff[MROWS*DFF];
__device__ float g_qk[BHN*TLEN*DHEAD];
__device__ float g_v[BHN*TLEN*DHEAD];
__device__ float g_so[(long)BHN*ITEMS*DHEAD];
__device__ float g_lse[BHN*ITEMS];
__device__ int   g_st[BHN*ITEMS];
__device__ int   g_pos[BHN*ITEMS];
__device__ unsigned char g_bkt[BHN*ITEMS];
__device__ int   g_base[BHN*256];
__device__ float g_attn[MROWS*DMODEL];

// ---------------- embedding ----------------
__global__ void embed_kernel(const float* __restrict__ xe, const float* __restrict__ xme,
                             const float* __restrict__ xd, const float* __restrict__ xmd,
                             const float* __restrict__ convw, const float* __restrict__ tw) {
  int bt = blockIdx.x; int b = bt / TLEN; int t = bt % TLEN;
  int d = threadIdx.x;
  __shared__ float sx[3][ENCIN];
  __shared__ float sm[MARK];
  for (int i = d; i < 3*ENCIN; i += 128) {
    int k = i / ENCIN, c = i % ENCIN;
    int tt = t - 1 + k; tt = (tt + TLEN) % TLEN;
    float v = (tt < SENC) ? xe[(b*SENC + tt)*ENCIN + c]
                          : xd[(b*PRED + (tt - SENC))*ENCIN + c];
    sx[k][c] = v;
  }
  if (d < MARK)
    sm[d] = (t < SENC) ? xme[(b*SENC + t)*MARK + d]
                       : xmd[(b*PRED + (t - SENC))*MARK + d];
  __syncthreads();
  float acc = 0.f;
  #pragma unroll
  for (int k = 0; k < 3; k++)
    #pragma unroll
    for (int c = 0; c < ENCIN; c++)
      acc += sx[k][c] * convw[(k*ENCIN + c)*DMODEL + d];
  #pragma unroll
  for (int m = 0; m < MARK; m++) acc += sm[m] * tw[m*DMODEL + d];
  int i2 = (d >> 1) * 2;
  float div = expf((float)i2 * (-logf(10000.f) / (float)DMODEL));
  float ang = (float)t * div;
  acc += (d & 1) ? cosf(ang) : sinf(ang);
  g_h[(bt)*DMODEL + d] = acc;
}

// ---------------- 128x128x16 fp32 GEMM, 8x8 microtile, double-buffered ----------------
// EPI: 0 none, 2 = +bias +residual, 3 = +bias + exact GELU
// SPLIT: scatter into (b, head, t, dh)
template<int EPI, int SPLIT>
__global__ void __launch_bounds__(256) gemm128(
    const float* __restrict__ A, const float* __restrict__ B,
    const float* __restrict__ bias, const float* __restrict__ R,
    float* __restrict__ C, int M, int N, int K) {
  __shared__ __align__(16) float As[2][16][132];
  __shared__ __align__(16) float Bs[2][16][128];
  int tid = threadIdx.x;
  int bm = blockIdx.y * 128, bn = blockIdx.x * 128;
  int tx = tid & 15, ty = tid >> 4;
  int ar = tid >> 2, ac = tid & 3;       // A loader
  int br = tid >> 5, bc = tid & 31;      // B loader
  const float* Ap0 = A + (long)(bm + ar) * K + ac * 4;
  const float* Ap1 = A + (long)(bm + ar + 64) * K + ac * 4;
  const float* Bp  = B + (long)br * N + bn + bc * 4;
  float acc[8][8] = {};
  int ntiles = K >> 4;
  float4 a0, a1, b0, b1;
  a0 = *(const float4*)(Ap0);
  a1 = *(const float4*)(Ap1);
  b0 = *(const float4*)(Bp);
  b1 = *(const float4*)(Bp + 8 * (long)N);
  int buf = 0;
  for (int t = 0; t < ntiles; t++) {
    As[buf][ac*4+0][ar] = a0.x; As[buf][ac*4+1][ar] = a0.y;
    As[buf][ac*4+2][ar] = a0.z; As[buf][ac*4+3][ar] = a0.w;
    As[buf][ac*4+0][ar+64] = a1.x; As[buf][ac*4+1][ar+64] = a1.y;
    As[buf][ac*4+2][ar+64] = a1.z; As[buf][ac*4+3][ar+64] = a1.w;
    *(float4*)&Bs[buf][br][bc*4] = b0;
    *(float4*)&Bs[buf][br+8][bc*4] = b1;
    __syncthreads();
    if (t + 1 < ntiles) {
      a0 = *(const float4*)(Ap0 + (t+1)*16);
      a1 = *(const float4*)(Ap1 + (t+1)*16);
      b0 = *(const float4*)(Bp + (long)((t+1)*16) * N);
      b1 = *(const float4*)(Bp + (long)((t+1)*16 + 8) * N);
    }
    #pragma unroll
    for (int kk = 0; kk < 16; kk++) {
      float4 av0 = *(const float4*)&As[buf][kk][ty*4];
      float4 av1 = *(const float4*)&As[buf][kk][ty*4+64];
      float4 bv0 = *(const float4*)&Bs[buf][kk][tx*4];
      float4 bv1 = *(const float4*)&Bs[buf][kk][tx*4+64];
      float am[8] = {av0.x,av0.y,av0.z,av0.w,av1.x,av1.y,av1.z,av1.w};
      float bm_[8] = {bv0.x,bv0.y,bv0.z,bv0.w,bv1.x,bv1.y,bv1.z,bv1.w};
      #pragma unroll
      for (int i = 0; i < 8; i++)
        #pragma unroll
        for (int j = 0; j < 8; j++)
          acc[i][j] += am[i] * bm_[j];
    }
    buf ^= 1;
  }
  // epilogue
  #pragma unroll
  for (int ih = 0; ih < 2; ih++) {
    #pragma unroll
    for (int qi = 0; qi < 4; qi++) {
      int r = bm + ty*4 + qi + ih*64;
      #pragma unroll
      for (int jh = 0; jh < 2; jh++) {
        int cb = bn + tx*4 + jh*64;
        float4 v;
        v.x = acc[ih*4+qi][jh*4+0];
        v.y = acc[ih*4+qi][jh*4+1];
        v.z = acc[ih*4+qi][jh*4+2];
        v.w = acc[ih*4+qi][jh*4+3];
        if (EPI >= 2) {
          const float4 bb = *(const float4*)&bias[cb];
          v.x += bb.x; v.y += bb.y; v.z += bb.z; v.w += bb.w;
        }
        if (EPI == 2) {
          const float4 rr = *(const float4*)&R[(long)r*N + cb];
          v.x += rr.x; v.y += rr.y; v.z += rr.z; v.w += rr.w;
        }
        if (EPI == 3) {
          v.x = 0.5f*v.x*(1.f + erff(v.x*0.70710678118f));
          v.y = 0.5f*v.y*(1.f + erff(v.y*0.70710678118f));
          v.z = 0.5f*v.z*(1.f + erff(v.z*0.70710678118f));
          v.w = 0.5f*v.w*(1.f + erff(v.w*0.70710678118f));
        }
        if (SPLIT) {
          int b = r / TLEN, t = r % TLEN;
          int hd = cb >> 5, dh = cb & 31;
          *(float4*)&C[(((long)b*NHEADS + hd)*TLEN + t)*DHEAD + dh] = v;
        } else {
          *(float4*)&C[(long)r*N + cb] = v;
        }
      }
    }
  }
}

// ---------------- bucket argmax ----------------
__global__ void bucket_argmax_kernel() {
  int tid = threadIdx.x;
  int lane = tid & 31;
  long row = (long)blockIdx.x * 4 + (tid >> 5);
  int bh = (int)(row >> 12);
  int t  = (int)(row & (TLEN - 1));
  const float* rp = g_ff + row * 128;
  #pragma unroll
  for (int h = 0; h < NHASH; h++) {
    float v = rp[h*32 + lane];
    float val; int bi;
    if (v >= -v) { val = v; bi = lane; } else { val = -v; bi = lane + 32; }
    #pragma unroll
    for (int off = 16; off; off >>= 1) {
      float ov = __shfl_xor_sync(0xffffffffu, val, off);
      int   oi = __shfl_xor_sync(0xffffffffu, bi,  off);
      if (ov > val || (ov == val && oi < bi)) { val = ov; bi = oi; }
    }
    if (lane == 0) g_bkt[(bh*NHASH + h)*TLEN + t] = (unsigned char)bi;
  }
}

// ---------------- counting sort ----------------
__global__ void hist_kernel() {
  __shared__ int cnt[256];
  int bh = blockIdx.x, tid = threadIdx.x;
  cnt[tid] = 0; __syncthreads();
  const unsigned char* bp = g_bkt + bh*ITEMS;
  for (int i = tid; i < ITEMS; i += 256) {
    int gb = ((i >> 12) << 6) + bp[i];
    atomicAdd(&cnt[gb], 1);
  }
  __syncthreads();
  if (tid == 0) {
    int s = 0;
    #pragma unroll 8
    for (int j = 0; j < 256; j++) { g_base[bh*256 + j] = s; s += cnt[j]; }
  }
}

__global__ void __launch_bounds__(1024) place_kernel() {
  int bhh = blockIdx.x;
  int bh = bhh >> 2, h = bhh & 3;
  int warp = threadIdx.x >> 5, lane = threadIdx.x & 31;
  const unsigned char* bp = g_bkt + (bh*NHASH + h)*TLEN;
  #pragma unroll
  for (int s = 0; s < 2; s++) {
    int lb = warp*2 + s;
    int base = g_base[bh*256 + h*64 + lb];
    for (int t0 = 0; t0 < TLEN; t0 += 32) {
      int my = bp[t0 + lane];
      unsigned mask = __ballot_sync(0xffffffffu, my == lb);
      if (my == lb) {
        int p = base + __popc(mask & ((1u << lane) - 1u));
        g_st[bh*ITEMS + p] = t0 + lane;
        g_pos[(bh*NHASH + h)*TLEN + t0 + lane] = p;
      }
      base += __popc(mask);
    }
  }
}

// ---------------- chunked LSH attention (two-phase, register tiled) ----------------
// dyn smem layout (floats):
//  qT   [32][68]   @ 0       (reused as red[64][32] in PV reduce)
//  kT   [32][132]  @ 2176    (normalized * ATTN_SCALE)
//  vS   [128][36]  @ 6400
//  pS   [128][68]  @ 11008
//  sum  [64]       @ 19712
//  qt   [64]  int  @ 19776
//  kt   [128] int  @ 19840
#define ATTN_SMEM_FLOATS 19968
__global__ void __launch_bounds__(256) attn_kernel() {
  extern __shared__ __align__(16) float smf[];
  float* qT = smf;
  float* kT = smf + 2176;
  float* vS = smf + 6400;
  float* pS = smf + 11008;
  float* sSum = smf + 19712;
  int* sQt = (int*)(smf + 19776);
  int* sKt = (int*)(smf + 19840);

  int bh = blockIdx.x >> 8;
  int c  = blockIdx.x & 255;
  int pc = (c + 255) & 255;
  int tid = threadIdx.x;

  if (tid < 64) {
    sQt[tid] = g_st[bh*ITEMS + c*64 + tid];
  } else if (tid < 192) {
    int j = tid - 64;
    int p = (j < 64) ? (c*64 + j) : (pc*64 + (j - 64));
    sKt[j] = g_st[bh*ITEMS + p];
  }
  __syncthreads();

  // V copy (row-major [j][d])
  {
    const float* gv = g_v + (long)bh*TLEN*DHEAD;
    for (int idx = tid; idx < 128*8; idx += 256) {
      int j = idx >> 3, f = idx & 7;
      float4 v4 = *(const float4*)(gv + (long)sKt[j]*DHEAD + f*4);
      *(float4*)&vS[j*36 + f*4] = v4;
    }
  }
  // Q transposed; K transposed + normalized + scaled
  if (tid < 64) {
    int i = tid;
    const float* gq = g_qk + ((long)bh*TLEN + sQt[i])*DHEAD;
    #pragma unroll
    for (int f = 0; f < 8; f++) {
      float4 v4 = *(const float4*)(gq + f*4);
      qT[(f*4+0)*68 + i] = v4.x;
      qT[(f*4+1)*68 + i] = v4.y;
      qT[(f*4+2)*68 + i] = v4.z;
      qT[(f*4+3)*68 + i] = v4.w;
    }
  } else if (tid < 192) {
    int j = tid - 64;
    const float* gk = g_qk + ((long)bh*TLEN + sKt[j])*DHEAD;
    float4 rowv[8];
    float ss = 0.f;
    #pragma unroll
    for (int f = 0; f < 8; f++) {
      rowv[f] = *(const float4*)(gk + f*4);
      ss += rowv[f].x*rowv[f].x + rowv[f].y*rowv[f].y
          + rowv[f].z*rowv[f].z + rowv[f].w*rowv[f].w;
    }
    float inv = ATTN_SCALE / fmaxf(sqrtf(ss), 1e-12f);
    #pragma unroll
    for (int f = 0; f < 8; f++) {
      kT[(f*4+0)*132 + j] = rowv[f].x * inv;
      kT[(f*4+1)*132 + j] = rowv[f].y * inv;
      kT[(f*4+2)*132 + j] = rowv[f].z * inv;
      kT[(f*4+3)*132 + j] = rowv[f].w * inv;
    }
  }
  __syncthreads();

  // ---- phase 1: dots (4q x 8k per thread) + softmax ----
  int qg = tid >> 4, kg = tid & 15;
  int i0 = qg*4, j0 = kg*8;
  float p[4][8] = {};
  #pragma unroll 8
  for (int d = 0; d < 32; d++) {
    float4 qv = *(const float4*)&qT[d*68 + i0];
    float4 k0 = *(const float4*)&kT[d*132 + j0];
    float4 k1 = *(const float4*)&kT[d*132 + j0 + 4];
    float qa[4] = {qv.x, qv.y, qv.z, qv.w};
    float ka[8] = {k0.x,k0.y,k0.z,k0.w,k1.x,k1.y,k1.z,k1.w};
    #pragma unroll
    for (int qi = 0; qi < 4; qi++)
      #pragma unroll
      for (int jj = 0; jj < 8; jj++)
        p[qi][jj] += qa[qi] * ka[jj];
  }
  int qt4[4], kt8[8];
  #pragma unroll
  for (int qi = 0; qi < 4; qi++) qt4[qi] = sQt[i0+qi];
  #pragma unroll
  for (int jj = 0; jj < 8; jj++) kt8[jj] = sKt[j0+jj];
  #pragma unroll
  for (int qi = 0; qi < 4; qi++)
    #pragma unroll
    for (int jj = 0; jj < 8; jj++)
      if (kt8[jj] == qt4[qi]) p[qi][jj] = -5e4f;

  float mx[4];
  #pragma unroll
  for (int qi = 0; qi < 4; qi++) {
    float m = p[qi][0];
    #pragma unroll
    for (int jj = 1; jj < 8; jj++) m = fmaxf(m, p[qi][jj]);
    #pragma unroll
    for (int off = 8; off; off >>= 1)
      m = fmaxf(m, __shfl_xor_sync(0xffffffffu, m, off));
    mx[qi] = m;
  }
  float sums[4] = {};
  #pragma unroll
  for (int qi = 0; qi < 4; qi++) {
    #pragma unroll
    for (int jj = 0; jj < 8; jj++) {
      p[qi][jj] = __expf(p[qi][jj] - mx[qi]);
      sums[qi] += p[qi][jj];
    }
    #pragma unroll
    for (int off = 8; off; off >>= 1)
      sums[qi] += __shfl_xor_sync(0xffffffffu, sums[qi], off);
  }
  if (kg == 0) {
    #pragma unroll
    for (int qi = 0; qi < 4; qi++) {
      sSum[i0+qi] = sums[qi];
      g_lse[bh*ITEMS + c*64 + i0 + qi] = mx[qi] + __logf(sums[qi]);
    }
  }
  // store p transposed [j][i]
  #pragma unroll
  for (int jj = 0; jj < 8; jj++) {
    float4 t4 = make_float4(p[0][jj], p[1][jj], p[2][jj], p[3][jj]);
    *(float4*)&pS[(j0+jj)*68 + i0] = t4;
  }
  __syncthreads();

  // ---- phase 2: PV (4q x 4d per thread, j split in halves) ----
  int jh = tid >> 7;
  int r2 = tid & 127;
  int dg = r2 >> 4, qg2 = r2 & 15;
  int qi0 = qg2*4, d0 = dg*4;
  float oacc[4][4] = {};
  int jstart = jh*64;
  #pragma unroll 4
  for (int j = jstart; j < jstart + 64; j++) {
    float4 pv = *(const float4*)&pS[j*68 + qi0];
    float4 vv = *(const float4*)&vS[j*36 + d0];
    float pa[4] = {pv.x, pv.y, pv.z, pv.w};
    float va[4] = {vv.x, vv.y, vv.z, vv.w};
    #pragma unroll
    for (int qi = 0; qi < 4; qi++)
      #pragma unroll
      for (int di = 0; di < 4; di++)
        oacc[qi][di] += pa[qi] * va[di];
  }
  float* red = qT;   // reuse as [64][32]
  if (jh == 1) {
    #pragma unroll
    for (int qi = 0; qi < 4; qi++)
      *(float4*)&red[(qi0+qi)*32 + d0] =
        make_float4(oacc[qi][0], oacc[qi][1], oacc[qi][2], oacc[qi][3]);
  }
  __syncthreads();
  if (jh == 0) {
    float* outp = g_so + ((long)bh*ITEMS + (long)c*64)*DHEAD;
    #pragma unroll
    for (int qi = 0; qi < 4; qi++) {
      float4 o = *(const float4*)&red[(qi0+qi)*32 + d0];
      float inv = 1.f / sSum[qi0+qi];
      float4 w = make_float4((oacc[qi][0]+o.x)*inv, (oacc[qi][1]+o.y)*inv,
                             (oacc[qi][2]+o.z)*inv, (oacc[qi][3]+o.w)*inv);
      *(float4*)&outp[(qi0+qi)*DHEAD + d0] = w;
    }
  }
}

// ---------------- cross-hash combine ----------------
__global__ void combine_kernel() {
  int tid = threadIdx.x;
  int lane = tid & 31;
  long gw = (long)blockIdx.x * 4 + (tid >> 5);
  int bh = (int)(gw >> 12);
  int t  = (int)(gw & (TLEN - 1));
  float lse[NHASH], val[NHASH];
  int pidx[NHASH];
  #pragma unroll
  for (int h = 0; h < NHASH; h++) {
    pidx[h] = g_pos[(bh*NHASH + h)*TLEN + t];
    lse[h]  = g_lse[bh*ITEMS + pidx[h]];
    val[h]  = g_so[((long)bh*ITEMS + pidx[h])*DHEAD + lane];
  }
  float m = lse[0];
  #pragma unroll
  for (int h = 1; h < NHASH; h++) m = fmaxf(m, lse[h]);
  float acc = 0.f, wsum = 0.f;
  #pragma unroll
  for (int h = 0; h < NHASH; h++) {
    float w = __expf(lse[h] - m);
    acc += w * val[h]; wsum += w;
  }
  int b = bh >> 2, head = bh & 3;
  g_attn[((long)b*TLEN + t)*DMODEL + head*DHEAD + lane] = acc / wsum;
}

// ---------------- layernorm ----------------
__global__ void ln_kernel(const float* __restrict__ in, float* __restrict__ out,
                          const float* __restrict__ g, const float* __restrict__ bb) {
  int row = blockIdx.x, d = threadIdx.x;
  __shared__ float red[4];
  float x = in[(long)row*DMODEL + d];
  float s = x;
  #pragma unroll
  for (int off = 16; off; off >>= 1) s += __shfl_xor_sync(0xffffffffu, s, off);
  if ((d & 31) == 0) red[d >> 5] = s;
  __syncthreads();
  float mean = (red[0]+red[1]+red[2]+red[3]) * (1.f/DMODEL);
  float dv = x - mean;
  float s2 = dv*dv;
  #pragma unroll
  for (int off = 16; off; off >>= 1) s2 += __shfl_xor_sync(0xffffffffu, s2, off);
  __syncthreads();
  if ((d & 31) == 0) red[d >> 5] = s2;
  __syncthreads();
  float var = (red[0]+red[1]+red[2]+red[3]) * (1.f/DMODEL);
  out[(long)row*DMODEL + d] = dv * rsqrtf(var + 1e-5f) * g[d] + bb[d];
}

// ---------------- final head ----------------
__global__ void head_kernel(const float* __restrict__ projw, const float* __restrict__ projb,
                            const float* __restrict__ fcw, const float* __restrict__ fcb,
                            float* __restrict__ dout) {
  int b = blockIdx.x, tid = threadIdx.x;
  float lg0 = 0.f, lg1 = 0.f, lg2 = 0.f;
  for (int tt = tid; tt < PRED; tt += 128) {
    const float* hh = g_res + ((long)b*TLEN + SENC + tt)*DMODEL;
    float o4[4];
    #pragma unroll
    for (int cc = 0; cc < 4; cc++) {
      float a = projb[cc];
      #pragma unroll 8
      for (int d = 0; d < DMODEL; d++) a += hh[d]*projw[d*4 + cc];
      o4[cc] = a;
    }
    #pragma unroll
    for (int cc = 0; cc < 4; cc++) {
      int idx = (tt*4 + cc)*3;
      lg0 += o4[cc]*fcw[idx+0];
      lg1 += o4[cc]*fcw[idx+1];
      lg2 += o4[cc]*fcw[idx+2];
    }
  }
  __shared__ float red[3][128];
  red[0][tid] = lg0; red[1][tid] = lg1; red[2][tid] = lg2;
  __syncthreads();
  for (int off = 64; off; off >>= 1) {
    if (tid < off) {
      red[0][tid] += red[0][tid+off];
      red[1][tid] += red[1][tid+off];
      red[2][tid] += red[2][tid+off];
    }
    __syncthreads();
  }
  if (tid == 0) {
    float l0 = red[0][0]+fcb[0], l1 = red[1][0]+fcb[1], l2 = red[2][0]+fcb[2];
    float mx = fmaxf(l0, fmaxf(l1, l2));
    float e0 = expf(l0-mx), e1 = expf(l1-mx), e2 = expf(l2-mx);
    float is = 1.f/(e0+e1+e2);
    dout[b*3+0] = e0*is; dout[b*3+1] = e1*is; dout[b*3+2] = e2*is;
  }
}

// ---------------- host launch ----------------
extern "C" void kernel_launch(void* const* d_in, const int* in_sizes, int n_in,
                              void* d_out, int out_size) {
  const float* x_enc      = (const float*)d_in[0];
  const float* x_mark_enc = (const float*)d_in[1];
  const float* x_dec      = (const float*)d_in[2];
  const float* x_mark_dec = (const float*)d_in[3];
  const float* conv_w     = (const float*)d_in[4];
  const float* timef_w    = (const float*)d_in[5];
  const float* Wqk        = (const float*)d_in[6];
  const float* Wv         = (const float*)d_in[7];
  const float* Wo         = (const float*)d_in[8];
  const float* bo         = (const float*)d_in[9];
  const float* rot        = (const float*)d_in[10];
  const float* ln1_g      = (const float*)d_in[11];
  const float* ln1_b      = (const float*)d_in[12];
  const float* ln2_g      = (const float*)d_in[13];
  const float* ln2_b      = (const float*)d_in[14];
  const float* w1         = (const float*)d_in[15];
  const float* b1         = (const float*)d_in[16];
  const float* w2         = (const float*)d_in[17];
  const float* b2         = (const float*)d_in[18];
  const float* lnf_g      = (const float*)d_in[19];
  const float* lnf_b      = (const float*)d_in[20];
  const float* proj_w     = (const float*)d_in[21];
  const float* proj_b     = (const float*)d_in[22];
  const float* fc1_w      = (const float*)d_in[23];
  const float* fc1_b      = (const float*)d_in[24];
  (void)in_sizes; (void)n_in; (void)out_size;

  void* p;
  cudaGetSymbolAddress(&p, g_h);    float* ph    = (float*)p;
  cudaGetSymbolAddress(&p, g_res);  float* pres  = (float*)p;
  cudaGetSymbolAddress(&p, g_ff);   float* pff   = (float*)p;
  cudaGetSymbolAddress(&p, g_qk);   float* pqk   = (float*)p;
  cudaGetSymbolAddress(&p, g_v);    float* pv    = (float*)p;
  cudaGetSymbolAddress(&p, g_attn); float* pattn = (float*)p;

  static int smem_set = 0;
  const int attn_smem = ATTN_SMEM_FLOATS * 4;
  cudaFuncSetAttribute(attn_kernel, cudaFuncAttributeMaxDynamicSharedMemorySize, attn_smem);
  (void)smem_set;

  embed_kernel<<<MROWS, 128>>>(x_enc, x_mark_enc, x_dec, x_mark_dec, conv_w, timef_w);

  for (int l = 0; l < NLAYERS; l++) {
    const float* Wqk_l = Wqk + (long)l*DMODEL*DMODEL;
    const float* Wv_l  = Wv  + (long)l*DMODEL*DMODEL;
    const float* Wo_l  = Wo  + (long)l*DMODEL*DMODEL;
    const float* bo_l  = bo  + l*DMODEL;
    const float* rot_l = rot + (long)l*DHEAD*NHASH*(NBUCK/2);
    const float* w1_l  = w1 + (long)l*DMODEL*DFF;
    const float* b1_l  = b1 + l*DFF;
    const float* w2_l  = w2 + (long)l*DFF*DMODEL;
    const float* b2_l  = b2 + l*DMODEL;

    gemm128<0,1><<<dim3(1,256), 256>>>(ph, Wqk_l, nullptr, nullptr, pqk, MROWS, DMODEL, DMODEL);
    gemm128<0,1><<<dim3(1,256), 256>>>(ph, Wv_l,  nullptr, nullptr, pv,  MROWS, DMODEL, DMODEL);

    gemm128<0,0><<<dim3(1,1024), 256>>>(pqk, rot_l, nullptr, nullptr, pff, BHN*TLEN, 128, DHEAD);
    bucket_argmax_kernel<<<BHN*TLEN/4, 128>>>();

    hist_kernel<<<BHN, 256>>>();
    place_kernel<<<BHN*NHASH, 1024>>>();

    attn_kernel<<<BHN*NCHUNK, 256, attn_smem>>>();
    combine_kernel<<<BHN*TLEN/4, 128>>>();

    gemm128<2,0><<<dim3(1,256), 256>>>(pattn, Wo_l, bo_l, ph, pres, MROWS, DMODEL, DMODEL);
    ln_kernel<<<MROWS, 128>>>(pres, ph, ln1_g + l*DMODEL, ln1_b + l*DMODEL);

    gemm128<3,0><<<dim3(4,256), 256>>>(ph, w1_l, b1_l, nullptr, pff, MROWS, DFF, DMODEL);
    gemm128<2,0><<<dim3(1,256), 256>>>(pff, w2_l, b2_l, ph, pres, MROWS, DMODEL, DFF);
    ln_kernel<<<MROWS, 128>>>(pres, ph, ln2_g + l*DMODEL, ln2_b + l*DMODEL);
  }

  ln_kernel<<<MROWS, 128>>>(ph, pres, lnf_g, lnf_b);
  head_kernel<<<BSZ, 128>>>(proj_w, proj_b, fc1_w, fc1_b, (float*)d_out);
}

// round 3
// speedup vs baseline: 2.9335x; 1.1613x over previous
#include <cuda_runtime.h>
#include <math.h>
#include <stdint.h>

// ---------------- problem constants ----------------
#define BSZ     8
#define SENC    3072
#define PRED    1024
#define ENCIN   40
#define DMODEL  128
#define NHEADS  4
#define DHEAD   32
#define NHASH   4
#define NBUCK   64
#define BUCKETSZ 64
#define NLAYERS 2
#define DFF     512
#define COUT    4
#define NCLASS  3
#define MARK    4
#define TLEN    4096
#define BHN     (BSZ*NHEADS)          // 32
#define MROWS   (BSZ*TLEN)            // 32768
#define NCHUNK  (NHASH*TLEN/BUCKETSZ) // 256
#define ITEMS   (NHASH*TLEN)          // 16384 per bh
#define ATTN_SCALE 0.17677669529663689f

// ---------------- scratch ----------------
__device__ float g_h[MROWS*DMODEL];
__device__ float g_res[MROWS*DMODEL];
__device__ float g_ff[MROWS*DFF];
__device__ float g_qk[BHN*TLEN*DHEAD];
__device__ float g_v[BHN*TLEN*DHEAD];
__device__ float g_so[(long)BHN*ITEMS*DHEAD];
__device__ float g_lse[BHN*ITEMS];
__device__ int   g_st[BHN*ITEMS];
__device__ int   g_pos[BHN*ITEMS];
__device__ unsigned char g_bkt[BHN*ITEMS];
__device__ int   g_base[BHN*256];
__device__ float g_attn[MROWS*DMODEL];

// ---------------- embedding ----------------
__global__ void embed_kernel(const float* __restrict__ xe, const float* __restrict__ xme,
                             const float* __restrict__ xd, const float* __restrict__ xmd,
                             const float* __restrict__ convw, const float* __restrict__ tw) {
  int bt = blockIdx.x; int b = bt / TLEN; int t = bt % TLEN;
  int d = threadIdx.x;
  __shared__ float sx[3][ENCIN];
  __shared__ float sm[MARK];
  for (int i = d; i < 3*ENCIN; i += 128) {
    int k = i / ENCIN, c = i % ENCIN;
    int tt = t - 1 + k; tt = (tt + TLEN) % TLEN;
    float v = (tt < SENC) ? xe[(b*SENC + tt)*ENCIN + c]
                          : xd[(b*PRED + (tt - SENC))*ENCIN + c];
    sx[k][c] = v;
  }
  if (d < MARK)
    sm[d] = (t < SENC) ? xme[(b*SENC + t)*MARK + d]
                       : xmd[(b*PRED + (t - SENC))*MARK + d];
  __syncthreads();
  float acc = 0.f;
  #pragma unroll
  for (int k = 0; k < 3; k++)
    #pragma unroll
    for (int c = 0; c < ENCIN; c++)
      acc += sx[k][c] * convw[(k*ENCIN + c)*DMODEL + d];
  #pragma unroll
  for (int m = 0; m < MARK; m++) acc += sm[m] * tw[m*DMODEL + d];
  int i2 = (d >> 1) * 2;
  float div = expf((float)i2 * (-logf(10000.f) / (float)DMODEL));
  float ang = (float)t * div;
  acc += (d & 1) ? cosf(ang) : sinf(ang);
  g_h[(bt)*DMODEL + d] = acc;
}

// ---------------- fp32 GEMM 128x128 (kept for bucket-critical paths) ----------------
template<int EPI, int SPLIT>
__global__ void __launch_bounds__(256) gemm128(
    const float* __restrict__ A, const float* __restrict__ B,
    const float* __restrict__ bias, const float* __restrict__ R,
    float* __restrict__ C, int M, int N, int K) {
  __shared__ __align__(16) float As[2][16][132];
  __shared__ __align__(16) float Bs[2][16][128];
  int tid = threadIdx.x;
  int bm = blockIdx.y * 128, bn = blockIdx.x * 128;
  int tx = tid & 15, ty = tid >> 4;
  int ar = tid >> 2, ac = tid & 3;
  int br = tid >> 5, bc = tid & 31;
  const float* Ap0 = A + (long)(bm + ar) * K + ac * 4;
  const float* Ap1 = A + (long)(bm + ar + 64) * K + ac * 4;
  const float* Bp  = B + (long)br * N + bn + bc * 4;
  float acc[8][8] = {};
  int ntiles = K >> 4;
  float4 a0, a1, b0, b1;
  a0 = *(const float4*)(Ap0);
  a1 = *(const float4*)(Ap1);
  b0 = *(const float4*)(Bp);
  b1 = *(const float4*)(Bp + 8 * (long)N);
  int buf = 0;
  for (int t = 0; t < ntiles; t++) {
    As[buf][ac*4+0][ar] = a0.x; As[buf][ac*4+1][ar] = a0.y;
    As[buf][ac*4+2][ar] = a0.z; As[buf][ac*4+3][ar] = a0.w;
    As[buf][ac*4+0][ar+64] = a1.x; As[buf][ac*4+1][ar+64] = a1.y;
    As[buf][ac*4+2][ar+64] = a1.z; As[buf][ac*4+3][ar+64] = a1.w;
    *(float4*)&Bs[buf][br][bc*4] = b0;
    *(float4*)&Bs[buf][br+8][bc*4] = b1;
    __syncthreads();
    if (t + 1 < ntiles) {
      a0 = *(const float4*)(Ap0 + (t+1)*16);
      a1 = *(const float4*)(Ap1 + (t+1)*16);
      b0 = *(const float4*)(Bp + (long)((t+1)*16) * N);
      b1 = *(const float4*)(Bp + (long)((t+1)*16 + 8) * N);
    }
    #pragma unroll
    for (int kk = 0; kk < 16; kk++) {
      float4 av0 = *(const float4*)&As[buf][kk][ty*4];
      float4 av1 = *(const float4*)&As[buf][kk][ty*4+64];
      float4 bv0 = *(const float4*)&Bs[buf][kk][tx*4];
      float4 bv1 = *(const float4*)&Bs[buf][kk][tx*4+64];
      float am[8] = {av0.x,av0.y,av0.z,av0.w,av1.x,av1.y,av1.z,av1.w};
      float bm_[8] = {bv0.x,bv0.y,bv0.z,bv0.w,bv1.x,bv1.y,bv1.z,bv1.w};
      #pragma unroll
      for (int i = 0; i < 8; i++)
        #pragma unroll
        for (int j = 0; j < 8; j++)
          acc[i][j] += am[i] * bm_[j];
    }
    buf ^= 1;
  }
  #pragma unroll
  for (int ih = 0; ih < 2; ih++) {
    #pragma unroll
    for (int qi = 0; qi < 4; qi++) {
      int r = bm + ty*4 + qi + ih*64;
      #pragma unroll
      for (int jh = 0; jh < 2; jh++) {
        int cb = bn + tx*4 + jh*64;
        float4 v;
        v.x = acc[ih*4+qi][jh*4+0];
        v.y = acc[ih*4+qi][jh*4+1];
        v.z = acc[ih*4+qi][jh*4+2];
        v.w = acc[ih*4+qi][jh*4+3];
        if (SPLIT) {
          int b = r / TLEN, t = r % TLEN;
          int hd = cb >> 5, dh = cb & 31;
          *(float4*)&C[(((long)b*NHEADS + hd)*TLEN + t)*DHEAD + dh] = v;
        } else {
          *(float4*)&C[(long)r*N + cb] = v;
        }
      }
    }
  }
}

// ---------------- TF32 tensor-core GEMM 128x128, mma.sync m16n8k8 ----------------
// EPI: 0 = none, 1 = +bias +residual +LayerNorm (N must be 128, grid.x==1, C may alias R),
//      3 = +bias + exact GELU
// SPLIT: scatter into (b, head, t, dh)
__device__ __forceinline__ uint32_t f2tf(float x) {
  uint32_t u; asm("cvt.rna.tf32.f32 %0, %1;" : "=r"(u) : "f"(x)); return u;
}
__device__ __forceinline__ void mma_tf32(float* c, const uint32_t* a, const uint32_t* b) {
  asm volatile(
    "mma.sync.aligned.m16n8k8.row.col.f32.tf32.tf32.f32 "
    "{%0,%1,%2,%3}, {%4,%5,%6,%7}, {%8,%9}, {%0,%1,%2,%3};\n"
    : "+f"(c[0]), "+f"(c[1]), "+f"(c[2]), "+f"(c[3])
    : "r"(a[0]), "r"(a[1]), "r"(a[2]), "r"(a[3]), "r"(b[0]), "r"(b[1]));
}

#define AS_STRIDE 20
#define BS_STRIDE 136
template<int EPI, int SPLIT>
__global__ void __launch_bounds__(256, 2) gemm_tf32(
    const float* __restrict__ A, const float* __restrict__ B,
    const float* __restrict__ bias, const float* __restrict__ R,
    const float* __restrict__ lng, const float* __restrict__ lnb,
    float* __restrict__ C, int M, int N, int K) {
  __shared__ uint32_t As[2][128][AS_STRIDE];
  __shared__ uint32_t Bs[2][16][BS_STRIDE];
  int tid = threadIdx.x;
  int warp = tid >> 5, lane = tid & 31;
  int wm = warp >> 2, wn = warp & 3;            // 2 x 4 warp grid
  int m_warp = wm * 64, n_warp = wn * 32;
  int g = lane >> 2, l4 = lane & 3;
  int bm = blockIdx.y * 128, bn = blockIdx.x * 128;

  int ar = tid >> 1, ac = (tid & 1) * 8;        // A loader: row ar, k cols ac..ac+7
  int bk = tid >> 5, bnn = (tid & 31) * 4;      // B loader: rows bk, bk+8
  const float* Ap = A + (long)(bm + ar) * K + ac;
  const float* Bp = B + (long)bk * N + bn + bnn;

  float acc[4][4][4] = {};
  int ntiles = K >> 4;
  float4 fa0, fa1, fb0, fb1;
  fa0 = *(const float4*)(Ap);
  fa1 = *(const float4*)(Ap + 4);
  fb0 = *(const float4*)(Bp);
  fb1 = *(const float4*)(Bp + 8 * (long)N);
  int buf = 0;
  for (int t = 0; t < ntiles; t++) {
    As[buf][ar][ac+0] = f2tf(fa0.x); As[buf][ar][ac+1] = f2tf(fa0.y);
    As[buf][ar][ac+2] = f2tf(fa0.z); As[buf][ar][ac+3] = f2tf(fa0.w);
    As[buf][ar][ac+4] = f2tf(fa1.x); As[buf][ar][ac+5] = f2tf(fa1.y);
    As[buf][ar][ac+6] = f2tf(fa1.z); As[buf][ar][ac+7] = f2tf(fa1.w);
    Bs[buf][bk][bnn+0] = f2tf(fb0.x); Bs[buf][bk][bnn+1] = f2tf(fb0.y);
    Bs[buf][bk][bnn+2] = f2tf(fb0.z); Bs[buf][bk][bnn+3] = f2tf(fb0.w);
    Bs[buf][bk+8][bnn+0] = f2tf(fb1.x); Bs[buf][bk+8][bnn+1] = f2tf(fb1.y);
    Bs[buf][bk+8][bnn+2] = f2tf(fb1.z); Bs[buf][bk+8][bnn+3] = f2tf(fb1.w);
    __syncthreads();
    if (t + 1 < ntiles) {
      fa0 = *(const float4*)(Ap + (t+1)*16);
      fa1 = *(const float4*)(Ap + (t+1)*16 + 4);
      fb0 = *(const float4*)(Bp + (long)((t+1)*16) * N);
      fb1 = *(const float4*)(Bp + (long)((t+1)*16 + 8) * N);
    }
    #pragma unroll
    for (int k8 = 0; k8 < 16; k8 += 8) {
      uint32_t afr[4][4], bfr[4][2];
      #pragma unroll
      for (int mf = 0; mf < 4; mf++) {
        int mr = m_warp + mf*16 + g;
        afr[mf][0] = As[buf][mr    ][k8 + l4];
        afr[mf][1] = As[buf][mr + 8][k8 + l4];
        afr[mf][2] = As[buf][mr    ][k8 + l4 + 4];
        afr[mf][3] = As[buf][mr + 8][k8 + l4 + 4];
      }
      #pragma unroll
      for (int nf = 0; nf < 4; nf++) {
        int nc = n_warp + nf*8 + g;
        bfr[nf][0] = Bs[buf][k8 + l4    ][nc];
        bfr[nf][1] = Bs[buf][k8 + l4 + 4][nc];
      }
      #pragma unroll
      for (int mf = 0; mf < 4; mf++)
        #pragma unroll
        for (int nf = 0; nf < 4; nf++)
          mma_tf32(acc[mf][nf], afr[mf], bfr[nf]);
    }
    buf ^= 1;
  }

  // ---------------- epilogue ----------------
  // acc[mf][nf][0..1] -> row r0 = m_warp+mf*16+g, cols 2*l4 + {0,1} of nf*8 block
  // acc[mf][nf][2..3] -> row r0+8
  if (EPI == 1) {
    // bias + residual, then row LayerNorm (N==128, full row in CTA)
    float* Ssum = (float*)As;          // [128][4]
    float* Ssq  = ((float*)As) + 512;  // [128][4]
    __syncthreads();                   // done with As/Bs
    float psum[4][2], psq[4][2];
    #pragma unroll
    for (int mf = 0; mf < 4; mf++) {
      #pragma unroll
      for (int hf = 0; hf < 2; hf++) {
        int r = bm + m_warp + mf*16 + g + hf*8;
        float s = 0.f, sq = 0.f;
        #pragma unroll
        for (int nf = 0; nf < 4; nf++) {
          int c = n_warp + nf*8 + 2*l4;
          #pragma unroll
          for (int p = 0; p < 2; p++) {
            float v = acc[mf][nf][hf*2+p] + bias[c+p] + R[(long)r*N + c + p];
            acc[mf][nf][hf*2+p] = v;
            s += v; sq += v*v;
          }
        }
        s  += __shfl_xor_sync(0xffffffffu, s, 1);
        s  += __shfl_xor_sync(0xffffffffu, s, 2);
        sq += __shfl_xor_sync(0xffffffffu, sq, 1);
        sq += __shfl_xor_sync(0xffffffffu, sq, 2);
        psum[mf][hf] = s; psq[mf][hf] = sq;
      }
    }
    if (l4 == 0) {
      #pragma unroll
      for (int mf = 0; mf < 4; mf++)
        #pragma unroll
        for (int hf = 0; hf < 2; hf++) {
          int rl = m_warp + mf*16 + g + hf*8;
          Ssum[rl*4 + wn] = psum[mf][hf];
          Ssq [rl*4 + wn] = psq[mf][hf];
        }
    }
    __syncthreads();
    #pragma unroll
    for (int mf = 0; mf < 4; mf++) {
      #pragma unroll
      for (int hf = 0; hf < 2; hf++) {
        int rl = m_warp + mf*16 + g + hf*8;
        int r = bm + rl;
        float s  = Ssum[rl*4+0] + Ssum[rl*4+1] + Ssum[rl*4+2] + Ssum[rl*4+3];
        float sq = Ssq [rl*4+0] + Ssq [rl*4+1] + Ssq [rl*4+2] + Ssq [rl*4+3];
        float mean = s * (1.f/128.f);
        float var = sq * (1.f/128.f) - mean*mean;
        float rstd = rsqrtf(var + 1e-5f);
        #pragma unroll
        for (int nf = 0; nf < 4; nf++) {
          int c = n_warp + nf*8 + 2*l4;
          float2 o;
          o.x = (acc[mf][nf][hf*2+0] - mean)*rstd*lng[c+0] + lnb[c+0];
          o.y = (acc[mf][nf][hf*2+1] - mean)*rstd*lng[c+1] + lnb[c+1];
          *(float2*)&C[(long)r*N + c] = o;
        }
      }
    }
  } else {
    #pragma unroll
    for (int mf = 0; mf < 4; mf++) {
      #pragma unroll
      for (int hf = 0; hf < 2; hf++) {
        int r = bm + m_warp + mf*16 + g + hf*8;
        #pragma unroll
        for (int nf = 0; nf < 4; nf++) {
          int c = bn + n_warp + nf*8 + 2*l4;
          float vx = acc[mf][nf][hf*2+0];
          float vy = acc[mf][nf][hf*2+1];
          if (EPI == 3) {
            vx += bias[c+0]; vy += bias[c+1];
            vx = 0.5f*vx*(1.f + erff(vx*0.70710678118f));
            vy = 0.5f*vy*(1.f + erff(vy*0.70710678118f));
          }
          if (SPLIT) {
            int b = r / TLEN, t = r % TLEN;
            int hd = c >> 5, dh = c & 31;
            *(float2*)&C[(((long)b*NHEADS + hd)*TLEN + t)*DHEAD + dh] = make_float2(vx, vy);
          } else {
            *(float2*)&C[(long)r*N + c] = make_float2(vx, vy);
          }
        }
      }
    }
  }
}

// ---------------- bucket argmax ----------------
__global__ void bucket_argmax_kernel() {
  int tid = threadIdx.x;
  int lane = tid & 31;
  long row = (long)blockIdx.x * 4 + (tid >> 5);
  int bh = (int)(row >> 12);
  int t  = (int)(row & (TLEN - 1));
  const float* rp = g_ff + row * 128;
  #pragma unroll
  for (int h = 0; h < NHASH; h++) {
    float v = rp[h*32 + lane];
    float val; int bi;
    if (v >= -v) { val = v; bi = lane; } else { val = -v; bi = lane + 32; }
    #pragma unroll
    for (int off = 16; off; off >>= 1) {
      float ov = __shfl_xor_sync(0xffffffffu, val, off);
      int   oi = __shfl_xor_sync(0xffffffffu, bi,  off);
      if (ov > val || (ov == val && oi < bi)) { val = ov; bi = oi; }
    }
    if (lane == 0) g_bkt[(bh*NHASH + h)*TLEN + t] = (unsigned char)bi;
  }
}

// ---------------- counting sort ----------------
__global__ void hist_kernel() {
  __shared__ int cnt[256];
  int bh = blockIdx.x, tid = threadIdx.x;
  cnt[tid] = 0; __syncthreads();
  const unsigned char* bp = g_bkt + bh*ITEMS;
  for (int i = tid; i < ITEMS; i += 256) {
    int gb = ((i >> 12) << 6) + bp[i];
    atomicAdd(&cnt[gb], 1);
  }
  __syncthreads();
  if (tid == 0) {
    int s = 0;
    #pragma unroll 8
    for (int j = 0; j < 256; j++) { g_base[bh*256 + j] = s; s += cnt[j]; }
  }
}

__global__ void __launch_bounds__(1024) place_kernel() {
  int bhh = blockIdx.x;
  int bh = bhh >> 2, h = bhh & 3;
  int warp = threadIdx.x >> 5, lane = threadIdx.x & 31;
  const unsigned char* bp = g_bkt + (bh*NHASH + h)*TLEN;
  #pragma unroll
  for (int s = 0; s < 2; s++) {
    int lb = warp*2 + s;
    int base = g_base[bh*256 + h*64 + lb];
    for (int t0 = 0; t0 < TLEN; t0 += 32) {
      int my = bp[t0 + lane];
      unsigned mask = __ballot_sync(0xffffffffu, my == lb);
      if (my == lb) {
        int p = base + __popc(mask & ((1u << lane) - 1u));
        g_st[bh*ITEMS + p] = t0 + lane;
        g_pos[(bh*NHASH + h)*TLEN + t0 + lane] = p;
      }
      base += __popc(mask);
    }
  }
}

// ---------------- chunked LSH attention (two-phase, register tiled) ----------------
#define ATTN_SMEM_FLOATS 19968
__global__ void __launch_bounds__(256) attn_kernel() {
  extern __shared__ __align__(16) float smf[];
  float* qT = smf;
  float* kT = smf + 2176;
  float* vS = smf + 6400;
  float* pS = smf + 11008;
  float* sSum = smf + 19712;
  int* sQt = (int*)(smf + 19776);
  int* sKt = (int*)(smf + 19840);

  int bh = blockIdx.x >> 8;
  int c  = blockIdx.x & 255;
  int pc = (c + 255) & 255;
  int tid = threadIdx.x;

  if (tid < 64) {
    sQt[tid] = g_st[bh*ITEMS + c*64 + tid];
  } else if (tid < 192) {
    int j = tid - 64;
    int p = (j < 64) ? (c*64 + j) : (pc*64 + (j - 64));
    sKt[j] = g_st[bh*ITEMS + p];
  }
  __syncthreads();

  {
    const float* gv = g_v + (long)bh*TLEN*DHEAD;
    for (int idx = tid; idx < 128*8; idx += 256) {
      int j = idx >> 3, f = idx & 7;
      float4 v4 = *(const float4*)(gv + (long)sKt[j]*DHEAD + f*4);
      *(float4*)&vS[j*36 + f*4] = v4;
    }
  }
  if (tid < 64) {
    int i = tid;
    const float* gq = g_qk + ((long)bh*TLEN + sQt[i])*DHEAD;
    #pragma unroll
    for (int f = 0; f < 8; f++) {
      float4 v4 = *(const float4*)(gq + f*4);
      qT[(f*4+0)*68 + i] = v4.x;
      qT[(f*4+1)*68 + i] = v4.y;
      qT[(f*4+2)*68 + i] = v4.z;
      qT[(f*4+3)*68 + i] = v4.w;
    }
  } else if (tid < 192) {
    int j = tid - 64;
    const float* gk = g_qk + ((long)bh*TLEN + sKt[j])*DHEAD;
    float4 rowv[8];
    float ss = 0.f;
    #pragma unroll
    for (int f = 0; f < 8; f++) {
      rowv[f] = *(const float4*)(gk + f*4);
      ss += rowv[f].x*rowv[f].x + rowv[f].y*rowv[f].y
          + rowv[f].z*rowv[f].z + rowv[f].w*rowv[f].w;
    }
    float inv = ATTN_SCALE / fmaxf(sqrtf(ss), 1e-12f);
    #pragma unroll
    for (int f = 0; f < 8; f++) {
      kT[(f*4+0)*132 + j] = rowv[f].x * inv;
      kT[(f*4+1)*132 + j] = rowv[f].y * inv;
      kT[(f*4+2)*132 + j] = rowv[f].z * inv;
      kT[(f*4+3)*132 + j] = rowv[f].w * inv;
    }
  }
  __syncthreads();

  int qg = tid >> 4, kg = tid & 15;
  int i0 = qg*4, j0 = kg*8;
  float p[4][8] = {};
  #pragma unroll 8
  for (int d = 0; d < 32; d++) {
    float4 qv = *(const float4*)&qT[d*68 + i0];
    float4 k0 = *(const float4*)&kT[d*132 + j0];
    float4 k1 = *(const float4*)&kT[d*132 + j0 + 4];
    float qa[4] = {qv.x, qv.y, qv.z, qv.w};
    float ka[8] = {k0.x,k0.y,k0.z,k0.w,k1.x,k1.y,k1.z,k1.w};
    #pragma unroll
    for (int qi = 0; qi < 4; qi++)
      #pragma unroll
      for (int jj = 0; jj < 8; jj++)
        p[qi][jj] += qa[qi] * ka[jj];
  }
  int qt4[4], kt8[8];
  #pragma unroll
  for (int qi = 0; qi < 4; qi++) qt4[qi] = sQt[i0+qi];
  #pragma unroll
  for (int jj = 0; jj < 8; jj++) kt8[jj] = sKt[j0+jj];
  #pragma unroll
  for (int qi = 0; qi < 4; qi++)
    #pragma unroll
    for (int jj = 0; jj < 8; jj++)
      if (kt8[jj] == qt4[qi]) p[qi][jj] = -5e4f;

  float mx[4];
  #pragma unroll
  for (int qi = 0; qi < 4; qi++) {
    float m = p[qi][0];
    #pragma unroll
    for (int jj = 1; jj < 8; jj++) m = fmaxf(m, p[qi][jj]);
    #pragma unroll
    for (int off = 8; off; off >>= 1)
      m = fmaxf(m, __shfl_xor_sync(0xffffffffu, m, off));
    mx[qi] = m;
  }
  float sums[4] = {};
  #pragma unroll
  for (int qi = 0; qi < 4; qi++) {
    #pragma unroll
    for (int jj = 0; jj < 8; jj++) {
      p[qi][jj] = __expf(p[qi][jj] - mx[qi]);
      sums[qi] += p[qi][jj];
    }
    #pragma unroll
    for (int off = 8; off; off >>= 1)
      sums[qi] += __shfl_xor_sync(0xffffffffu, sums[qi], off);
  }
  if (kg == 0) {
    #pragma unroll
    for (int qi = 0; qi < 4; qi++) {
      sSum[i0+qi] = sums[qi];
      g_lse[bh*ITEMS + c*64 + i0 + qi] = mx[qi] + __logf(sums[qi]);
    }
  }
  #pragma unroll
  for (int jj = 0; jj < 8; jj++) {
    float4 t4 = make_float4(p[0][jj], p[1][jj], p[2][jj], p[3][jj]);
    *(float4*)&pS[(j0+jj)*68 + i0] = t4;
  }
  __syncthreads();

  int jh = tid >> 7;
  int r2 = tid & 127;
  int dg = r2 >> 4, qg2 = r2 & 15;
  int qi0 = qg2*4, d0 = dg*4;
  float oacc[4][4] = {};
  int jstart = jh*64;
  #pragma unroll 4
  for (int j = jstart; j < jstart + 64; j++) {
    float4 pv = *(const float4*)&pS[j*68 + qi0];
    float4 vv = *(const float4*)&vS[j*36 + d0];
    float pa[4] = {pv.x, pv.y, pv.z, pv.w};
    float va[4] = {vv.x, vv.y, vv.z, vv.w};
    #pragma unroll
    for (int qi = 0; qi < 4; qi++)
      #pragma unroll
      for (int di = 0; di < 4; di++)
        oacc[qi][di] += pa[qi] * va[di];
  }
  float* red = qT;
  if (jh == 1) {
    #pragma unroll
    for (int qi = 0; qi < 4; qi++)
      *(float4*)&red[(qi0+qi)*32 + d0] =
        make_float4(oacc[qi][0], oacc[qi][1], oacc[qi][2], oacc[qi][3]);
  }
  __syncthreads();
  if (jh == 0) {
    float* outp = g_so + ((long)bh*ITEMS + (long)c*64)*DHEAD;
    #pragma unroll
    for (int qi = 0; qi < 4; qi++) {
      float4 o = *(const float4*)&red[(qi0+qi)*32 + d0];
      float inv = 1.f / sSum[qi0+qi];
      float4 w = make_float4((oacc[qi][0]+o.x)*inv, (oacc[qi][1]+o.y)*inv,
                             (oacc[qi][2]+o.z)*inv, (oacc[qi][3]+o.w)*inv);
      *(float4*)&outp[(qi0+qi)*DHEAD + d0] = w;
    }
  }
}

// ---------------- cross-hash combine ----------------
__global__ void combine_kernel() {
  int tid = threadIdx.x;
  int lane = tid & 31;
  long gw = (long)blockIdx.x * 4 + (tid >> 5);
  int bh = (int)(gw >> 12);
  int t  = (int)(gw & (TLEN - 1));
  float lse[NHASH], val[NHASH];
  int pidx[NHASH];
  #pragma unroll
  for (int h = 0; h < NHASH; h++) {
    pidx[h] = g_pos[(bh*NHASH + h)*TLEN + t];
    lse[h]  = g_lse[bh*ITEMS + pidx[h]];
    val[h]  = g_so[((long)bh*ITEMS + pidx[h])*DHEAD + lane];
  }
  float m = lse[0];
  #pragma unroll
  for (int h = 1; h < NHASH; h++) m = fmaxf(m, lse[h]);
  float acc = 0.f, wsum = 0.f;
  #pragma unroll
  for (int h = 0; h < NHASH; h++) {
    float w = __expf(lse[h] - m);
    acc += w * val[h]; wsum += w;
  }
  int b = bh >> 2, head = bh & 3;
  g_attn[((long)b*TLEN + t)*DMODEL + head*DHEAD + lane] = acc / wsum;
}

// ---------------- layernorm (final only) ----------------
__global__ void ln_kernel(const float* __restrict__ in, float* __restrict__ out,
                          const float* __restrict__ g, const float* __restrict__ bb) {
  int row = blockIdx.x, d = threadIdx.x;
  __shared__ float red[4];
  float x = in[(long)row*DMODEL + d];
  float s = x;
  #pragma unroll
  for (int off = 16; off; off >>= 1) s += __shfl_xor_sync(0xffffffffu, s, off);
  if ((d & 31) == 0) red[d >> 5] = s;
  __syncthreads();
  float mean = (red[0]+red[1]+red[2]+red[3]) * (1.f/DMODEL);
  float dv = x - mean;
  float s2 = dv*dv;
  #pragma unroll
  for (int off = 16; off; off >>= 1) s2 += __shfl_xor_sync(0xffffffffu, s2, off);
  __syncthreads();
  if ((d & 31) == 0) red[d >> 5] = s2;
  __syncthreads();
  float var = (red[0]+red[1]+red[2]+red[3]) * (1.f/DMODEL);
  out[(long)row*DMODEL + d] = dv * rsqrtf(var + 1e-5f) * g[d] + bb[d];
}

// ---------------- final head ----------------
__global__ void head_kernel(const float* __restrict__ projw, const float* __restrict__ projb,
                            const float* __restrict__ fcw, const float* __restrict__ fcb,
                            float* __restrict__ dout) {
  int b = blockIdx.x, tid = threadIdx.x;
  float lg0 = 0.f, lg1 = 0.f, lg2 = 0.f;
  for (int tt = tid; tt < PRED; tt += 128) {
    const float* hh = g_res + ((long)b*TLEN + SENC + tt)*DMODEL;
    float o4[4];
    #pragma unroll
    for (int cc = 0; cc < 4; cc++) {
      float a = projb[cc];
      #pragma unroll 8
      for (int d = 0; d < DMODEL; d++) a += hh[d]*projw[d*4 + cc];
      o4[cc] = a;
    }
    #pragma unroll
    for (int cc = 0; cc < 4; cc++) {
      int idx = (tt*4 + cc)*3;
      lg0 += o4[cc]*fcw[idx+0];
      lg1 += o4[cc]*fcw[idx+1];
      lg2 += o4[cc]*fcw[idx+2];
    }
  }
  __shared__ float red[3][128];
  red[0][tid] = lg0; red[1][tid] = lg1; red[2][tid] = lg2;
  __syncthreads();
  for (int off = 64; off; off >>= 1) {
    if (tid < off) {
      red[0][tid] += red[0][tid+off];
      red[1][tid] += red[1][tid+off];
      red[2][tid] += red[2][tid+off];
    }
    __syncthreads();
  }
  if (tid == 0) {
    float l0 = red[0][0]+fcb[0], l1 = red[1][0]+fcb[1], l2 = red[2][0]+fcb[2];
    float mx = fmaxf(l0, fmaxf(l1, l2));
    float e0 = expf(l0-mx), e1 = expf(l1-mx), e2 = expf(l2-mx);
    float is = 1.f/(e0+e1+e2);
    dout[b*3+0] = e0*is; dout[b*3+1] = e1*is; dout[b*3+2] = e2*is;
  }
}

// ---------------- host launch ----------------
extern "C" void kernel_launch(void* const* d_in, const int* in_sizes, int n_in,
                              void* d_out, int out_size) {
  const float* x_enc      = (const float*)d_in[0];
  const float* x_mark_enc = (const float*)d_in[1];
  const float* x_dec      = (const float*)d_in[2];
  const float* x_mark_dec = (const float*)d_in[3];
  const float* conv_w     = (const float*)d_in[4];
  const float* timef_w    = (const float*)d_in[5];
  const float* Wqk        = (const float*)d_in[6];
  const float* Wv         = (const float*)d_in[7];
  const float* Wo         = (const float*)d_in[8];
  const float* bo         = (const float*)d_in[9];
  const float* rot        = (const float*)d_in[10];
  const float* ln1_g      = (const float*)d_in[11];
  const float* ln1_b      = (const float*)d_in[12];
  const float* ln2_g      = (const float*)d_in[13];
  const float* ln2_b      = (const float*)d_in[14];
  const float* w1         = (const float*)d_in[15];
  const float* b1         = (const float*)d_in[16];
  const float* w2         = (const float*)d_in[17];
  const float* b2         = (const float*)d_in[18];
  const float* lnf_g      = (const float*)d_in[19];
  const float* lnf_b      = (const float*)d_in[20];
  const float* proj_w     = (const float*)d_in[21];
  const float* proj_b     = (const float*)d_in[22];
  const float* fc1_w      = (const float*)d_in[23];
  const float* fc1_b      = (const float*)d_in[24];
  (void)in_sizes; (void)n_in; (void)out_size;

  void* p;
  cudaGetSymbolAddress(&p, g_h);    float* ph    = (float*)p;
  cudaGetSymbolAddress(&p, g_res);  float* pres  = (float*)p;
  cudaGetSymbolAddress(&p, g_ff);   float* pff   = (float*)p;
  cudaGetSymbolAddress(&p, g_qk);   float* pqk   = (float*)p;
  cudaGetSymbolAddress(&p, g_v);    float* pv    = (float*)p;
  cudaGetSymbolAddress(&p, g_attn); float* pattn = (float*)p;

  const int attn_smem = ATTN_SMEM_FLOATS * 4;
  cudaFuncSetAttribute(attn_kernel, cudaFuncAttributeMaxDynamicSharedMemorySize, attn_smem);

  embed_kernel<<<MROWS, 128>>>(x_enc, x_mark_enc, x_dec, x_mark_dec, conv_w, timef_w);

  for (int l = 0; l < NLAYERS; l++) {
    const float* Wqk_l = Wqk + (long)l*DMODEL*DMODEL;
    const float* Wv_l  = Wv  + (long)l*DMODEL*DMODEL;
    const float* Wo_l  = Wo  + (long)l*DMODEL*DMODEL;
    const float* bo_l  = bo  + l*DMODEL;
    const float* rot_l = rot + (long)l*DHEAD*NHASH*(NBUCK/2);
    const float* w1_l  = w1 + (long)l*DMODEL*DFF;
    const float* b1_l  = b1 + l*DFF;
    const float* w2_l  = w2 + (long)l*DFF*DMODEL;
    const float* b2_l  = b2 + l*DMODEL;

    // qk projection in fp32 (bucket-critical), v in tf32
    gemm128<0,1><<<dim3(1,256), 256>>>(ph, Wqk_l, nullptr, nullptr, pqk, MROWS, DMODEL, DMODEL);
    gemm_tf32<0,1><<<dim3(1,256), 256>>>(ph, Wv_l, nullptr, nullptr, nullptr, nullptr, pv, MROWS, DMODEL, DMODEL);

    // rotations in fp32 (bucket-critical)
    gemm128<0,0><<<dim3(1,1024), 256>>>(pqk, rot_l, nullptr, nullptr, pff, BHN*TLEN, 128, DHEAD);
    bucket_argmax_kernel<<<BHN*TLEN/4, 128>>>();

    hist_kernel<<<BHN, 256>>>();
    place_kernel<<<BHN*NHASH, 1024>>>();

    attn_kernel<<<BHN*NCHUNK, 256, attn_smem>>>();
    combine_kernel<<<BHN*TLEN/4, 128>>>();

    // Wo + bias + residual + LN1 fused (in-place on g_h)
    gemm_tf32<1,0><<<dim3(1,256), 256>>>(pattn, Wo_l, bo_l, ph, ln1_g + l*DMODEL, ln1_b + l*DMODEL,
                                         ph, MROWS, DMODEL, DMODEL);
    // FFN1 + bias + GELU
    gemm_tf32<3,0><<<dim3(4,256), 256>>>(ph, w1_l, b1_l, nullptr, nullptr, nullptr, pff, MROWS, DFF, DMODEL);
    // FFN2 + bias + residual + LN2 fused (in-place on g_h)
    gemm_tf32<1,0><<<dim3(1,256), 256>>>(pff, w2_l, b2_l, ph, ln2_g + l*DMODEL, ln2_b + l*DMODEL,
                                         ph, MROWS, DMODEL, DFF);
  }

  ln_kernel<<<MROWS, 128>>>(ph, pres, lnf_g, lnf_b);
  head_kernel<<<BSZ, 128>>>(proj_w, proj_b, fc1_w, fc1_b, (float*)d_out);
}

// round 4
// speedup vs baseline: 3.5692x; 1.2167x over previous
#include <cuda_runtime.h>
#include <math.h>
#include <stdint.h>

// ---------------- problem constants ----------------
#define BSZ     8
#define SENC    3072
#define PRED    1024
#define ENCIN   40
#define DMODEL  128
#define NHEADS  4
#define DHEAD   32
#define NHASH   4
#define NBUCK   64
#define BUCKETSZ 64
#define NLAYERS 2
#define DFF     512
#define COUT    4
#define NCLASS  3
#define MARK    4
#define TLEN    4096
#define BHN     (BSZ*NHEADS)          // 32
#define MROWS   (BSZ*TLEN)            // 32768
#define NCHUNK  (NHASH*TLEN/BUCKETSZ) // 256
#define ITEMS   (NHASH*TLEN)          // 16384 per bh
#define ATTN_SCALE 0.17677669529663689f

// ---------------- scratch ----------------
__device__ float g_h[MROWS*DMODEL];
__device__ float g_res[MROWS*DMODEL];
__device__ float g_ff[MROWS*DFF];
__device__ float g_qk[BHN*TLEN*DHEAD];
__device__ float g_v[BHN*TLEN*DHEAD];
__device__ float g_so[(long)BHN*ITEMS*DHEAD];
__device__ float g_lse[BHN*ITEMS];
__device__ int   g_st[BHN*ITEMS];
__device__ int   g_pos[BHN*ITEMS];
__device__ unsigned char g_bkt[BHN*ITEMS];
__device__ int   g_base[BHN*256];
__device__ float g_attn[MROWS*DMODEL];

// ---------------- tf32 helpers ----------------
__device__ __forceinline__ uint32_t f2tf(float x) {
  uint32_t u; asm("cvt.rna.tf32.f32 %0, %1;" : "=r"(u) : "f"(x)); return u;
}
__device__ __forceinline__ void mma_tf32(float* c, const uint32_t* a, const uint32_t* b) {
  asm volatile(
    "mma.sync.aligned.m16n8k8.row.col.f32.tf32.tf32.f32 "
    "{%0,%1,%2,%3}, {%4,%5,%6,%7}, {%8,%9}, {%0,%1,%2,%3};\n"
    : "+f"(c[0]), "+f"(c[1]), "+f"(c[2]), "+f"(c[3])
    : "r"(a[0]), "r"(a[1]), "r"(a[2]), "r"(a[3]), "r"(b[0]), "r"(b[1]));
}

// ---------------- embedding ----------------
__global__ void embed_kernel(const float* __restrict__ xe, const float* __restrict__ xme,
                             const float* __restrict__ xd, const float* __restrict__ xmd,
                             const float* __restrict__ convw, const float* __restrict__ tw) {
  int bt = blockIdx.x; int b = bt / TLEN; int t = bt % TLEN;
  int d = threadIdx.x;
  __shared__ float sx[3][ENCIN];
  __shared__ float sm[MARK];
  for (int i = d; i < 3*ENCIN; i += 128) {
    int k = i / ENCIN, c = i % ENCIN;
    int tt = t - 1 + k; tt = (tt + TLEN) % TLEN;
    float v = (tt < SENC) ? xe[(b*SENC + tt)*ENCIN + c]
                          : xd[(b*PRED + (tt - SENC))*ENCIN + c];
    sx[k][c] = v;
  }
  if (d < MARK)
    sm[d] = (t < SENC) ? xme[(b*SENC + t)*MARK + d]
                       : xmd[(b*PRED + (t - SENC))*MARK + d];
  __syncthreads();
  float acc = 0.f;
  #pragma unroll
  for (int k = 0; k < 3; k++)
    #pragma unroll
    for (int c = 0; c < ENCIN; c++)
      acc += sx[k][c] * convw[(k*ENCIN + c)*DMODEL + d];
  #pragma unroll
  for (int m = 0; m < MARK; m++) acc += sm[m] * tw[m*DMODEL + d];
  int i2 = (d >> 1) * 2;
  float div = expf((float)i2 * (-logf(10000.f) / (float)DMODEL));
  float ang = (float)t * div;
  acc += (d & 1) ? cosf(ang) : sinf(ang);
  g_h[(bt)*DMODEL + d] = acc;
}

// ---------------- fp32 GEMM 128x128 (bucket-critical qk projection) ----------------
template<int SPLIT>
__global__ void __launch_bounds__(256) gemm128(
    const float* __restrict__ A, const float* __restrict__ B,
    float* __restrict__ C, int M, int N, int K) {
  __shared__ __align__(16) float As[2][16][132];
  __shared__ __align__(16) float Bs[2][16][128];
  int tid = threadIdx.x;
  int bm = blockIdx.y * 128, bn = blockIdx.x * 128;
  int tx = tid & 15, ty = tid >> 4;
  int ar = tid >> 2, ac = tid & 3;
  int br = tid >> 5, bc = tid & 31;
  const float* Ap0 = A + (long)(bm + ar) * K + ac * 4;
  const float* Ap1 = A + (long)(bm + ar + 64) * K + ac * 4;
  const float* Bp  = B + (long)br * N + bn + bc * 4;
  float acc[8][8] = {};
  int ntiles = K >> 4;
  float4 a0, a1, b0, b1;
  a0 = *(const float4*)(Ap0);
  a1 = *(const float4*)(Ap1);
  b0 = *(const float4*)(Bp);
  b1 = *(const float4*)(Bp + 8 * (long)N);
  int buf = 0;
  for (int t = 0; t < ntiles; t++) {
    As[buf][ac*4+0][ar] = a0.x; As[buf][ac*4+1][ar] = a0.y;
    As[buf][ac*4+2][ar] = a0.z; As[buf][ac*4+3][ar] = a0.w;
    As[buf][ac*4+0][ar+64] = a1.x; As[buf][ac*4+1][ar+64] = a1.y;
    As[buf][ac*4+2][ar+64] = a1.z; As[buf][ac*4+3][ar+64] = a1.w;
    *(float4*)&Bs[buf][br][bc*4] = b0;
    *(float4*)&Bs[buf][br+8][bc*4] = b1;
    __syncthreads();
    if (t + 1 < ntiles) {
      a0 = *(const float4*)(Ap0 + (t+1)*16);
      a1 = *(const float4*)(Ap1 + (t+1)*16);
      b0 = *(const float4*)(Bp + (long)((t+1)*16) * N);
      b1 = *(const float4*)(Bp + (long)((t+1)*16 + 8) * N);
    }
    #pragma unroll
    for (int kk = 0; kk < 16; kk++) {
      float4 av0 = *(const float4*)&As[buf][kk][ty*4];
      float4 av1 = *(const float4*)&As[buf][kk][ty*4+64];
      float4 bv0 = *(const float4*)&Bs[buf][kk][tx*4];
      float4 bv1 = *(const float4*)&Bs[buf][kk][tx*4+64];
      float am[8] = {av0.x,av0.y,av0.z,av0.w,av1.x,av1.y,av1.z,av1.w};
      float bm_[8] = {bv0.x,bv0.y,bv0.z,bv0.w,bv1.x,bv1.y,bv1.z,bv1.w};
      #pragma unroll
      for (int i = 0; i < 8; i++)
        #pragma unroll
        for (int j = 0; j < 8; j++)
          acc[i][j] += am[i] * bm_[j];
    }
    buf ^= 1;
  }
  #pragma unroll
  for (int ih = 0; ih < 2; ih++) {
    #pragma unroll
    for (int qi = 0; qi < 4; qi++) {
      int r = bm + ty*4 + qi + ih*64;
      #pragma unroll
      for (int jh = 0; jh < 2; jh++) {
        int cb = bn + tx*4 + jh*64;
        float4 v;
        v.x = acc[ih*4+qi][jh*4+0];
        v.y = acc[ih*4+qi][jh*4+1];
        v.z = acc[ih*4+qi][jh*4+2];
        v.w = acc[ih*4+qi][jh*4+3];
        if (SPLIT) {
          int b = r / TLEN, t = r % TLEN;
          int hd = cb >> 5, dh = cb & 31;
          *(float4*)&C[(((long)b*NHEADS + hd)*TLEN + t)*DHEAD + dh] = v;
        } else {
          *(float4*)&C[(long)r*N + cb] = v;
        }
      }
    }
  }
}

// ---------------- TF32 tensor-core GEMM 128x128 ----------------
// EPI: 0 none, 1 = +bias +residual +LayerNorm (N==128, grid.x==1, C may alias R), 3 = +bias +GELU
// SPLIT: scatter into (b, head, t, dh)
#define AS_STRIDE 20
#define BS_STRIDE 136
template<int EPI, int SPLIT>
__global__ void __launch_bounds__(256, 2) gemm_tf32(
    const float* __restrict__ A, const float* __restrict__ B,
    const float* __restrict__ bias, const float* __restrict__ R,
    const float* __restrict__ lng, const float* __restrict__ lnb,
    float* __restrict__ C, int M, int N, int K) {
  __shared__ uint32_t As[2][128][AS_STRIDE];
  __shared__ uint32_t Bs[2][16][BS_STRIDE];
  int tid = threadIdx.x;
  int warp = tid >> 5, lane = tid & 31;
  int wm = warp >> 2, wn = warp & 3;
  int m_warp = wm * 64, n_warp = wn * 32;
  int g = lane >> 2, l4 = lane & 3;
  int bm = blockIdx.y * 128, bn = blockIdx.x * 128;

  int ar = tid >> 1, ac = (tid & 1) * 8;
  int bk = tid >> 5, bnn = (tid & 31) * 4;
  const float* Ap = A + (long)(bm + ar) * K + ac;
  const float* Bp = B + (long)bk * N + bn + bnn;

  float acc[4][4][4] = {};
  int ntiles = K >> 4;
  float4 fa0, fa1, fb0, fb1;
  fa0 = *(const float4*)(Ap);
  fa1 = *(const float4*)(Ap + 4);
  fb0 = *(const float4*)(Bp);
  fb1 = *(const float4*)(Bp + 8 * (long)N);
  int buf = 0;
  for (int t = 0; t < ntiles; t++) {
    As[buf][ar][ac+0] = f2tf(fa0.x); As[buf][ar][ac+1] = f2tf(fa0.y);
    As[buf][ar][ac+2] = f2tf(fa0.z); As[buf][ar][ac+3] = f2tf(fa0.w);
    As[buf][ar][ac+4] = f2tf(fa1.x); As[buf][ar][ac+5] = f2tf(fa1.y);
    As[buf][ar][ac+6] = f2tf(fa1.z); As[buf][ar][ac+7] = f2tf(fa1.w);
    Bs[buf][bk][bnn+0] = f2tf(fb0.x); Bs[buf][bk][bnn+1] = f2tf(fb0.y);
    Bs[buf][bk][bnn+2] = f2tf(fb0.z); Bs[buf][bk][bnn+3] = f2tf(fb0.w);
    Bs[buf][bk+8][bnn+0] = f2tf(fb1.x); Bs[buf][bk+8][bnn+1] = f2tf(fb1.y);
    Bs[buf][bk+8][bnn+2] = f2tf(fb1.z); Bs[buf][bk+8][bnn+3] = f2tf(fb1.w);
    __syncthreads();
    if (t + 1 < ntiles) {
      fa0 = *(const float4*)(Ap + (t+1)*16);
      fa1 = *(const float4*)(Ap + (t+1)*16 + 4);
      fb0 = *(const float4*)(Bp + (long)((t+1)*16) * N);
      fb1 = *(const float4*)(Bp + (long)((t+1)*16 + 8) * N);
    }
    #pragma unroll
    for (int k8 = 0; k8 < 16; k8 += 8) {
      uint32_t afr[4][4], bfr[4][2];
      #pragma unroll
      for (int mf = 0; mf < 4; mf++) {
        int mr = m_warp + mf*16 + g;
        afr[mf][0] = As[buf][mr    ][k8 + l4];
        afr[mf][1] = As[buf][mr + 8][k8 + l4];
        afr[mf][2] = As[buf][mr    ][k8 + l4 + 4];
        afr[mf][3] = As[buf][mr + 8][k8 + l4 + 4];
      }
      #pragma unroll
      for (int nf = 0; nf < 4; nf++) {
        int nc = n_warp + nf*8 + g;
        bfr[nf][0] = Bs[buf][k8 + l4    ][nc];
        bfr[nf][1] = Bs[buf][k8 + l4 + 4][nc];
      }
      #pragma unroll
      for (int mf = 0; mf < 4; mf++)
        #pragma unroll
        for (int nf = 0; nf < 4; nf++)
          mma_tf32(acc[mf][nf], afr[mf], bfr[nf]);
    }
    buf ^= 1;
  }

  if (EPI == 1) {
    float* Ssum = (float*)As;
    float* Ssq  = ((float*)As) + 512;
    __syncthreads();
    float psum[4][2], psq[4][2];
    #pragma unroll
    for (int mf = 0; mf < 4; mf++) {
      #pragma unroll
      for (int hf = 0; hf < 2; hf++) {
        int r = bm + m_warp + mf*16 + g + hf*8;
        float s = 0.f, sq = 0.f;
        #pragma unroll
        for (int nf = 0; nf < 4; nf++) {
          int c = n_warp + nf*8 + 2*l4;
          #pragma unroll
          for (int p = 0; p < 2; p++) {
            float v = acc[mf][nf][hf*2+p] + bias[c+p] + R[(long)r*N + c + p];
            acc[mf][nf][hf*2+p] = v;
            s += v; sq += v*v;
          }
        }
        s  += __shfl_xor_sync(0xffffffffu, s, 1);
        s  += __shfl_xor_sync(0xffffffffu, s, 2);
        sq += __shfl_xor_sync(0xffffffffu, sq, 1);
        sq += __shfl_xor_sync(0xffffffffu, sq, 2);
        psum[mf][hf] = s; psq[mf][hf] = sq;
      }
    }
    if (l4 == 0) {
      #pragma unroll
      for (int mf = 0; mf < 4; mf++)
        #pragma unroll
        for (int hf = 0; hf < 2; hf++) {
          int rl = m_warp + mf*16 + g + hf*8;
          Ssum[rl*4 + wn] = psum[mf][hf];
          Ssq [rl*4 + wn] = psq[mf][hf];
        }
    }
    __syncthreads();
    #pragma unroll
    for (int mf = 0; mf < 4; mf++) {
      #pragma unroll
      for (int hf = 0; hf < 2; hf++) {
        int rl = m_warp + mf*16 + g + hf*8;
        int r = bm + rl;
        float s  = Ssum[rl*4+0] + Ssum[rl*4+1] + Ssum[rl*4+2] + Ssum[rl*4+3];
        float sq = Ssq [rl*4+0] + Ssq [rl*4+1] + Ssq [rl*4+2] + Ssq [rl*4+3];
        float mean = s * (1.f/128.f);
        float var = sq * (1.f/128.f) - mean*mean;
        float rstd = rsqrtf(var + 1e-5f);
        #pragma unroll
        for (int nf = 0; nf < 4; nf++) {
          int c = n_warp + nf*8 + 2*l4;
          float2 o;
          o.x = (acc[mf][nf][hf*2+0] - mean)*rstd*lng[c+0] + lnb[c+0];
          o.y = (acc[mf][nf][hf*2+1] - mean)*rstd*lng[c+1] + lnb[c+1];
          *(float2*)&C[(long)r*N + c] = o;
        }
      }
    }
  } else {
    #pragma unroll
    for (int mf = 0; mf < 4; mf++) {
      #pragma unroll
      for (int hf = 0; hf < 2; hf++) {
        int r = bm + m_warp + mf*16 + g + hf*8;
        #pragma unroll
        for (int nf = 0; nf < 4; nf++) {
          int c = bn + n_warp + nf*8 + 2*l4;
          float vx = acc[mf][nf][hf*2+0];
          float vy = acc[mf][nf][hf*2+1];
          if (EPI == 3) {
            vx += bias[c+0]; vy += bias[c+1];
            vx = 0.5f*vx*(1.f + erff(vx*0.70710678118f));
            vy = 0.5f*vy*(1.f + erff(vy*0.70710678118f));
          }
          if (SPLIT) {
            int b = r / TLEN, t = r % TLEN;
            int hd = c >> 5, dh = c & 31;
            *(float2*)&C[(((long)b*NHEADS + hd)*TLEN + t)*DHEAD + dh] = make_float2(vx, vy);
          } else {
            *(float2*)&C[(long)r*N + c] = make_float2(vx, vy);
          }
        }
      }
    }
  }
}

// ---------------- fused rotation + bucket argmax (fp32, bucket-critical) ----------------
// 8 warps per block, one row (bh,t) per warp; rot matrix staged in smem.
__global__ void __launch_bounds__(256) rot_argmax_kernel(const float* __restrict__ rot_l) {
  __shared__ float srot[32*128];
  int tid = threadIdx.x, lane = tid & 31, warp = tid >> 5;
  #pragma unroll
  for (int i = 0; i < 4; i++) {
    int idx = tid*4 + i*1024;
    *(float4*)&srot[idx] = *(const float4*)&rot_l[idx];
  }
  __syncthreads();
  long row = (long)blockIdx.x * 8 + warp;     // bh*TLEN + t
  int bh = (int)(row >> 12);
  int t  = (int)(row & (TLEN - 1));
  float qv = g_qk[row*DHEAD + lane];
  float acc[4] = {};
  #pragma unroll
  for (int d = 0; d < 32; d++) {
    float qd = __shfl_sync(0xffffffffu, qv, d);
    #pragma unroll
    for (int h = 0; h < 4; h++)
      acc[h] += qd * srot[d*128 + h*32 + lane];
  }
  #pragma unroll
  for (int h = 0; h < NHASH; h++) {
    float v = acc[h];
    float val; int bi;
    if (v >= -v) { val = v; bi = lane; } else { val = -v; bi = lane + 32; }
    #pragma unroll
    for (int off = 16; off; off >>= 1) {
      float ov = __shfl_xor_sync(0xffffffffu, val, off);
      int   oi = __shfl_xor_sync(0xffffffffu, bi,  off);
      if (ov > val || (ov == val && oi < bi)) { val = ov; bi = oi; }
    }
    if (lane == 0) g_bkt[(bh*NHASH + h)*TLEN + t] = (unsigned char)bi;
  }
}

// ---------------- counting sort ----------------
__global__ void hist_kernel() {
  __shared__ int cnt[256];
  int bh = blockIdx.x, tid = threadIdx.x;
  cnt[tid] = 0; __syncthreads();
  const unsigned char* bp = g_bkt + bh*ITEMS;
  for (int i = tid; i < ITEMS; i += 256) {
    int gb = ((i >> 12) << 6) + bp[i];
    atomicAdd(&cnt[gb], 1);
  }
  __syncthreads();
  if (tid == 0) {
    int s = 0;
    #pragma unroll 8
    for (int j = 0; j < 256; j++) { g_base[bh*256 + j] = s; s += cnt[j]; }
  }
}

__global__ void __launch_bounds__(1024) place_kernel() {
  int bhh = blockIdx.x;
  int bh = bhh >> 2, h = bhh & 3;
  int warp = threadIdx.x >> 5, lane = threadIdx.x & 31;
  const unsigned char* bp = g_bkt + (bh*NHASH + h)*TLEN;
  #pragma unroll
  for (int s = 0; s < 2; s++) {
    int lb = warp*2 + s;
    int base = g_base[bh*256 + h*64 + lb];
    for (int t0 = 0; t0 < TLEN; t0 += 32) {
      int my = bp[t0 + lane];
      unsigned mask = __ballot_sync(0xffffffffu, my == lb);
      if (my == lb) {
        int p = base + __popc(mask & ((1u << lane) - 1u));
        g_st[bh*ITEMS + p] = t0 + lane;
        g_pos[(bh*NHASH + h)*TLEN + t0 + lane] = p;
      }
      base += __popc(mask);
    }
  }
}

// ---------------- tensor-core LSH attention ----------------
// 128 threads (4 warps); warp w owns query rows [w*16, w*16+16).
// dyn smem (uint32 words):
//   qS  [64][36]  tf32 Q row-major          @ 0       (2304)
//   kTd [32][136] tf32 K^T [d][j], norm*scale folded  @ 2304  (4352)
//   vS  [128][36] tf32 V [j][d]             @ 6656    (4608)
//   pS  [64][132] tf32 P [i][j]             @ 11264   (8448)
//   sQt [64] int                            @ 19712
//   sKt [128] int                           @ 19776
#define ATTN_SMEM_WORDS 19904
__global__ void __launch_bounds__(128) attn_kernel() {
  extern __shared__ __align__(16) uint32_t smw[];
  uint32_t* qS  = smw;
  uint32_t* kTd = smw + 2304;
  uint32_t* vS  = smw + 6656;
  uint32_t* pS  = smw + 11264;
  int* sQt = (int*)(smw + 19712);
  int* sKt = (int*)(smw + 19776);

  int bh = blockIdx.x >> 8;
  int c  = blockIdx.x & 255;
  int pc = (c + 255) & 255;
  int tid = threadIdx.x;
  int lane = tid & 31, warp = tid >> 5;
  int g = lane >> 2, l4 = lane & 3;

  // ---- index loads ----
  {
    int p = (tid < 64) ? (c*64 + tid) : (pc*64 + (tid - 64));
    sKt[tid] = g_st[bh*ITEMS + p];
    if (tid < 64) sQt[tid] = sKt[tid];   // first 64 keys are the queries' chunk
  }
  __syncthreads();

  // ---- K (normalized*scale, transposed) and V loads: one row per thread ----
  {
    int j = tid;
    int t = sKt[j];
    const float* gk = g_qk + ((long)bh*TLEN + t)*DHEAD;
    const float* gv = g_v  + ((long)bh*TLEN + t)*DHEAD;
    float4 kr[8];
    float ss = 0.f;
    #pragma unroll
    for (int f = 0; f < 8; f++) {
      kr[f] = *(const float4*)(gk + f*4);
      ss += kr[f].x*kr[f].x + kr[f].y*kr[f].y + kr[f].z*kr[f].z + kr[f].w*kr[f].w;
    }
    float inv = ATTN_SCALE / fmaxf(sqrtf(ss), 1e-12f);
    #pragma unroll
    for (int f = 0; f < 8; f++) {
      kTd[(f*4+0)*136 + j] = f2tf(kr[f].x * inv);
      kTd[(f*4+1)*136 + j] = f2tf(kr[f].y * inv);
      kTd[(f*4+2)*136 + j] = f2tf(kr[f].z * inv);
      kTd[(f*4+3)*136 + j] = f2tf(kr[f].w * inv);
    }
    #pragma unroll
    for (int f = 0; f < 8; f++) {
      float4 vv = *(const float4*)(gv + f*4);
      uint4 u;
      u.x = f2tf(vv.x); u.y = f2tf(vv.y); u.z = f2tf(vv.z); u.w = f2tf(vv.w);
      *(uint4*)&vS[j*36 + f*4] = u;
    }
  }
  // ---- Q loads (rows 0..63) ----
  if (tid < 64) {
    const float* gq = g_qk + ((long)bh*TLEN + sQt[tid])*DHEAD;
    #pragma unroll
    for (int f = 0; f < 8; f++) {
      float4 qq = *(const float4*)(gq + f*4);
      uint4 u;
      u.x = f2tf(qq.x); u.y = f2tf(qq.y); u.z = f2tf(qq.z); u.w = f2tf(qq.w);
      *(uint4*)&qS[tid*36 + f*4] = u;
    }
  }
  __syncthreads();

  // ---- dots: S = Q*K^T  (m=64 per 4 warps, n=128, k=32) ----
  int mb = warp * 16;
  float s[16][4];
  #pragma unroll
  for (int nt = 0; nt < 16; nt++)
    #pragma unroll
    for (int p = 0; p < 4; p++) s[nt][p] = 0.f;
  #pragma unroll
  for (int k8 = 0; k8 < 32; k8 += 8) {
    uint32_t afr[4];
    afr[0] = qS[(mb + g    )*36 + k8 + l4];
    afr[1] = qS[(mb + g + 8)*36 + k8 + l4];
    afr[2] = qS[(mb + g    )*36 + k8 + l4 + 4];
    afr[3] = qS[(mb + g + 8)*36 + k8 + l4 + 4];
    #pragma unroll
    for (int nt = 0; nt < 16; nt++) {
      uint32_t bfr[2];
      bfr[0] = kTd[(k8 + l4    )*136 + nt*8 + g];
      bfr[1] = kTd[(k8 + l4 + 4)*136 + nt*8 + g];
      mma_tf32(s[nt], afr, bfr);
    }
  }

  // ---- self-mask + softmax (rows r0 = mb+g, r1 = mb+g+8) ----
  int r0 = mb + g, r1 = mb + g + 8;
  int qt0 = sQt[r0], qt1 = sQt[r1];
  float m0 = -1e30f, m1 = -1e30f;
  #pragma unroll
  for (int nt = 0; nt < 16; nt++) {
    int j0 = nt*8 + 2*l4;
    int kt0 = sKt[j0], kt1 = sKt[j0+1];
    if (kt0 == qt0) s[nt][0] = -5e4f;
    if (kt1 == qt0) s[nt][1] = -5e4f;
    if (kt0 == qt1) s[nt][2] = -5e4f;
    if (kt1 == qt1) s[nt][3] = -5e4f;
    m0 = fmaxf(m0, fmaxf(s[nt][0], s[nt][1]));
    m1 = fmaxf(m1, fmaxf(s[nt][2], s[nt][3]));
  }
  m0 = fmaxf(m0, __shfl_xor_sync(0xffffffffu, m0, 1));
  m0 = fmaxf(m0, __shfl_xor_sync(0xffffffffu, m0, 2));
  m1 = fmaxf(m1, __shfl_xor_sync(0xffffffffu, m1, 1));
  m1 = fmaxf(m1, __shfl_xor_sync(0xffffffffu, m1, 2));
  float sum0 = 0.f, sum1 = 0.f;
  #pragma unroll
  for (int nt = 0; nt < 16; nt++) {
    int j0 = nt*8 + 2*l4;
    uint32_t e00 = f2tf(__expf(s[nt][0] - m0));
    uint32_t e01 = f2tf(__expf(s[nt][1] - m0));
    uint32_t e10 = f2tf(__expf(s[nt][2] - m1));
    uint32_t e11 = f2tf(__expf(s[nt][3] - m1));
    sum0 += __uint_as_float(e00) + __uint_as_float(e01);
    sum1 += __uint_as_float(e10) + __uint_as_float(e11);
    *(uint2*)&pS[r0*132 + j0] = make_uint2(e00, e01);
    *(uint2*)&pS[r1*132 + j0] = make_uint2(e10, e11);
  }
  sum0 += __shfl_xor_sync(0xffffffffu, sum0, 1);
  sum0 += __shfl_xor_sync(0xffffffffu, sum0, 2);
  sum1 += __shfl_xor_sync(0xffffffffu, sum1, 1);
  sum1 += __shfl_xor_sync(0xffffffffu, sum1, 2);
  if (l4 == 0) {
    g_lse[bh*ITEMS + c*64 + r0] = m0 + __logf(sum0);
    g_lse[bh*ITEMS + c*64 + r1] = m1 + __logf(sum1);
  }
  __syncthreads();

  // ---- PV: O = P*V (m=64, n=32, k=128) ----
  float o[4][4];
  #pragma unroll
  for (int nt = 0; nt < 4; nt++)
    #pragma unroll
    for (int p = 0; p < 4; p++) o[nt][p] = 0.f;
  #pragma unroll
  for (int k8 = 0; k8 < 128; k8 += 8) {
    uint32_t afr[4];
    afr[0] = pS[(mb + g    )*132 + k8 + l4];
    afr[1] = pS[(mb + g + 8)*132 + k8 + l4];
    afr[2] = pS[(mb + g    )*132 + k8 + l4 + 4];
    afr[3] = pS[(mb + g + 8)*132 + k8 + l4 + 4];
    #pragma unroll
    for (int nt = 0; nt < 4; nt++) {
      uint32_t bfr[2];
      bfr[0] = vS[(k8 + l4    )*36 + nt*8 + g];
      bfr[1] = vS[(k8 + l4 + 4)*36 + nt*8 + g];
      mma_tf32(o[nt], afr, bfr);
    }
  }
  float inv0 = 1.f / sum0, inv1 = 1.f / sum1;
  float* outp = g_so + ((long)bh*ITEMS + (long)c*64)*DHEAD;
  #pragma unroll
  for (int nt = 0; nt < 4; nt++) {
    int d0 = nt*8 + 2*l4;
    *(float2*)&outp[r0*DHEAD + d0] = make_float2(o[nt][0]*inv0, o[nt][1]*inv0);
    *(float2*)&outp[r1*DHEAD + d0] = make_float2(o[nt][2]*inv1, o[nt][3]*inv1);
  }
}

// ---------------- cross-hash combine ----------------
__global__ void combine_kernel() {
  int tid = threadIdx.x;
  int lane = tid & 31;
  long gw = (long)blockIdx.x * 4 + (tid >> 5);
  int bh = (int)(gw >> 12);
  int t  = (int)(gw & (TLEN - 1));
  float lse[NHASH], val[NHASH];
  int pidx[NHASH];
  #pragma unroll
  for (int h = 0; h < NHASH; h++) {
    pidx[h] = g_pos[(bh*NHASH + h)*TLEN + t];
    lse[h]  = g_lse[bh*ITEMS + pidx[h]];
    val[h]  = g_so[((long)bh*ITEMS + pidx[h])*DHEAD + lane];
  }
  float m = lse[0];
  #pragma unroll
  for (int h = 1; h < NHASH; h++) m = fmaxf(m, lse[h]);
  float acc = 0.f, wsum = 0.f;
  #pragma unroll
  for (int h = 0; h < NHASH; h++) {
    float w = __expf(lse[h] - m);
    acc += w * val[h]; wsum += w;
  }
  int b = bh >> 2, head = bh & 3;
  g_attn[((long)b*TLEN + t)*DMODEL + head*DHEAD + lane] = acc / wsum;
}

// ---------------- layernorm (final only) ----------------
__global__ void ln_kernel(const float* __restrict__ in, float* __restrict__ out,
                          const float* __restrict__ g, const float* __restrict__ bb) {
  int row = blockIdx.x, d = threadIdx.x;
  __shared__ float red[4];
  float x = in[(long)row*DMODEL + d];
  float s = x;
  #pragma unroll
  for (int off = 16; off; off >>= 1) s += __shfl_xor_sync(0xffffffffu, s, off);
  if ((d & 31) == 0) red[d >> 5] = s;
  __syncthreads();
  float mean = (red[0]+red[1]+red[2]+red[3]) * (1.f/DMODEL);
  float dv = x - mean;
  float s2 = dv*dv;
  #pragma unroll
  for (int off = 16; off; off >>= 1) s2 += __shfl_xor_sync(0xffffffffu, s2, off);
  __syncthreads();
  if ((d & 31) == 0) red[d >> 5] = s2;
  __syncthreads();
  float var = (red[0]+red[1]+red[2]+red[3]) * (1.f/DMODEL);
  out[(long)row*DMODEL + d] = dv * rsqrtf(var + 1e-5f) * g[d] + bb[d];
}

// ---------------- final head ----------------
__global__ void head_kernel(const float* __restrict__ projw, const float* __restrict__ projb,
                            const float* __restrict__ fcw, const float* __restrict__ fcb,
                            float* __restrict__ dout) {
  int b = blockIdx.x, tid = threadIdx.x;
  float lg0 = 0.f, lg1 = 0.f, lg2 = 0.f;
  for (int tt = tid; tt < PRED; tt += 128) {
    const float* hh = g_res + ((long)b*TLEN + SENC + tt)*DMODEL;
    float o4[4];
    #pragma unroll
    for (int cc = 0; cc < 4; cc++) {
      float a = projb[cc];
      #pragma unroll 8
      for (int d = 0; d < DMODEL; d++) a += hh[d]*projw[d*4 + cc];
      o4[cc] = a;
    }
    #pragma unroll
    for (int cc = 0; cc < 4; cc++) {
      int idx = (tt*4 + cc)*3;
      lg0 += o4[cc]*fcw[idx+0];
      lg1 += o4[cc]*fcw[idx+1];
      lg2 += o4[cc]*fcw[idx+2];
    }
  }
  __shared__ float red[3][128];
  red[0][tid] = lg0; red[1][tid] = lg1; red[2][tid] = lg2;
  __syncthreads();
  for (int off = 64; off; off >>= 1) {
    if (tid < off) {
      red[0][tid] += red[0][tid+off];
      red[1][tid] += red[1][tid+off];
      red[2][tid] += red[2][tid+off];
    }
    __syncthreads();
  }
  if (tid == 0) {
    float l0 = red[0][0]+fcb[0], l1 = red[1][0]+fcb[1], l2 = red[2][0]+fcb[2];
    float mx = fmaxf(l0, fmaxf(l1, l2));
    float e0 = expf(l0-mx), e1 = expf(l1-mx), e2 = expf(l2-mx);
    float is = 1.f/(e0+e1+e2);
    dout[b*3+0] = e0*is; dout[b*3+1] = e1*is; dout[b*3+2] = e2*is;
  }
}

// ---------------- host launch ----------------
extern "C" void kernel_launch(void* const* d_in, const int* in_sizes, int n_in,
                              void* d_out, int out_size) {
  const float* x_enc      = (const float*)d_in[0];
  const float* x_mark_enc = (const float*)d_in[1];
  const float* x_dec      = (const float*)d_in[2];
  const float* x_mark_dec = (const float*)d_in[3];
  const float* conv_w     = (const float*)d_in[4];
  const float* timef_w    = (const float*)d_in[5];
  const float* Wqk        = (const float*)d_in[6];
  const float* Wv         = (const float*)d_in[7];
  const float* Wo         = (const float*)d_in[8];
  const float* bo         = (const float*)d_in[9];
  const float* rot        = (const float*)d_in[10];
  const float* ln1_g      = (const float*)d_in[11];
  const float* ln1_b      = (const float*)d_in[12];
  const float* ln2_g      = (const float*)d_in[13];
  const float* ln2_b      = (const float*)d_in[14];
  const float* w1         = (const float*)d_in[15];
  const float* b1         = (const float*)d_in[16];
  const float* w2         = (const float*)d_in[17];
  const float* b2         = (const float*)d_in[18];
  const float* lnf_g      = (const float*)d_in[19];
  const float* lnf_b      = (const float*)d_in[20];
  const float* proj_w     = (const float*)d_in[21];
  const float* proj_b     = (const float*)d_in[22];
  const float* fc1_w      = (const float*)d_in[23];
  const float* fc1_b      = (const float*)d_in[24];
  (void)in_sizes; (void)n_in; (void)out_size;

  void* p;
  cudaGetSymbolAddress(&p, g_h);    float* ph    = (float*)p;
  cudaGetSymbolAddress(&p, g_res);  float* pres  = (float*)p;
  cudaGetSymbolAddress(&p, g_ff);   float* pff   = (float*)p;
  cudaGetSymbolAddress(&p, g_qk);   float* pqk   = (float*)p;
  cudaGetSymbolAddress(&p, g_v);    float* pv    = (float*)p;
  cudaGetSymbolAddress(&p, g_attn); float* pattn = (float*)p;

  const int attn_smem = ATTN_SMEM_WORDS * 4;
  cudaFuncSetAttribute(attn_kernel, cudaFuncAttributeMaxDynamicSharedMemorySize, attn_smem);

  embed_kernel<<<MROWS, 128>>>(x_enc, x_mark_enc, x_dec, x_mark_dec, conv_w, timef_w);

  for (int l = 0; l < NLAYERS; l++) {
    const float* Wqk_l = Wqk + (long)l*DMODEL*DMODEL;
    const float* Wv_l  = Wv  + (long)l*DMODEL*DMODEL;
    const float* Wo_l  = Wo  + (long)l*DMODEL*DMODEL;
    const float* bo_l  = bo  + l*DMODEL;
    const float* rot_l = rot + (long)l*DHEAD*NHASH*(NBUCK/2);
    const float* w1_l  = w1 + (long)l*DMODEL*DFF;
    const float* b1_l  = b1 + l*DFF;
    const float* w2_l  = w2 + (long)l*DFF*DMODEL;
    const float* b2_l  = b2 + l*DMODEL;

    // qk projection fp32 (bucket-critical), v tf32
    gemm128<1><<<dim3(1,256), 256>>>(ph, Wqk_l, pqk, MROWS, DMODEL, DMODEL);
    gemm_tf32<0,1><<<dim3(1,256), 256>>>(ph, Wv_l, nullptr, nullptr, nullptr, nullptr, pv, MROWS, DMODEL, DMODEL);

    // fused rotation + argmax (fp32)
    rot_argmax_kernel<<<BHN*TLEN/8, 256>>>(rot_l);

    hist_kernel<<<BHN, 256>>>();
    place_kernel<<<BHN*NHASH, 1024>>>();

    attn_kernel<<<BHN*NCHUNK, 128, attn_smem>>>();
    combine_kernel<<<BHN*TLEN/4, 128>>>();

    gemm_tf32<1,0><<<dim3(1,256), 256>>>(pattn, Wo_l, bo_l, ph, ln1_g + l*DMODEL, ln1_b + l*DMODEL,
                                         ph, MROWS, DMODEL, DMODEL);
    gemm_tf32<3,0><<<dim3(4,256), 256>>>(ph, w1_l, b1_l, nullptr, nullptr, nullptr, pff, MROWS, DFF, DMODEL);
    gemm_tf32<1,0><<<dim3(1,256), 256>>>(pff, w2_l, b2_l, ph, ln2_g + l*DMODEL, ln2_b + l*DMODEL,
                                         ph, MROWS, DMODEL, DFF);
  }

  ln_kernel<<<MROWS, 128>>>(ph, pres, lnf_g, lnf_b);
  head_kernel<<<BSZ, 128>>>(proj_w, proj_b, fc1_w, fc1_b, (float*)d_out);
}

// round 6
// speedup vs baseline: 3.8119x; 1.0680x over previous
#include <cuda_runtime.h>
#include <math.h>
#include <stdint.h>

// ---------------- problem constants ----------------
#define BSZ     8
#define SENC    3072
#define PRED    1024
#define ENCIN   40
#define DMODEL  128
#define NHEADS  4
#define DHEAD   32
#define NHASH   4
#define NBUCK   64
#define BUCKETSZ 64
#define NLAYERS 2
#define DFF     512
#define COUT    4
#define NCLASS  3
#define MARK    4
#define TLEN    4096
#define BHN     (BSZ*NHEADS)          // 32
#define MROWS   (BSZ*TLEN)            // 32768
#define NCHUNK  (NHASH*TLEN/BUCKETSZ) // 256
#define ITEMS   (NHASH*TLEN)          // 16384 per bh
#define ATTN_SCALE 0.17677669529663689f

// ---------------- scratch ----------------
__device__ float g_h[MROWS*DMODEL];
__device__ float g_res[MROWS*DMODEL];
__device__ float g_ff[MROWS*DFF];
__device__ float g_qk[BHN*TLEN*DHEAD];
__device__ float g_v[BHN*TLEN*DHEAD];
__device__ float g_so[(long)BHN*ITEMS*DHEAD];
__device__ float g_lse[BHN*ITEMS];
__device__ int   g_st[BHN*ITEMS];
__device__ int   g_pos[BHN*ITEMS];
__device__ unsigned char g_bkt[BHN*ITEMS];
__device__ int   g_base[BHN*256];
__device__ float g_attn[MROWS*DMODEL];

// ---------------- tf32 helpers ----------------
__device__ __forceinline__ uint32_t f2tf(float x) {
  uint32_t u; asm("cvt.rna.tf32.f32 %0, %1;" : "=r"(u) : "f"(x)); return u;
}
__device__ __forceinline__ void mma_tf32(float* c, const uint32_t* a, const uint32_t* b) {
  asm volatile(
    "mma.sync.aligned.m16n8k8.row.col.f32.tf32.tf32.f32 "
    "{%0,%1,%2,%3}, {%4,%5,%6,%7}, {%8,%9}, {%0,%1,%2,%3};\n"
    : "+f"(c[0]), "+f"(c[1]), "+f"(c[2]), "+f"(c[3])
    : "r"(a[0]), "r"(a[1]), "r"(a[2]), "r"(a[3]), "r"(b[0]), "r"(b[1]));
}

// ---------------- embedding ----------------
__global__ void embed_kernel(const float* __restrict__ xe, const float* __restrict__ xme,
                             const float* __restrict__ xd, const float* __restrict__ xmd,
                             const float* __restrict__ convw, const float* __restrict__ tw) {
  int bt = blockIdx.x; int b = bt / TLEN; int t = bt % TLEN;
  int d = threadIdx.x;
  __shared__ float sx[3][ENCIN];
  __shared__ float sm[MARK];
  for (int i = d; i < 3*ENCIN; i += 128) {
    int k = i / ENCIN, c = i % ENCIN;
    int tt = t - 1 + k; tt = (tt + TLEN) % TLEN;
    float v = (tt < SENC) ? xe[(b*SENC + tt)*ENCIN + c]
                          : xd[(b*PRED + (tt - SENC))*ENCIN + c];
    sx[k][c] = v;
  }
  if (d < MARK)
    sm[d] = (t < SENC) ? xme[(b*SENC + t)*MARK + d]
                       : xmd[(b*PRED + (t - SENC))*MARK + d];
  __syncthreads();
  float acc = 0.f;
  #pragma unroll
  for (int k = 0; k < 3; k++)
    #pragma unroll
    for (int c = 0; c < ENCIN; c++)
      acc += sx[k][c] * convw[(k*ENCIN + c)*DMODEL + d];
  #pragma unroll
  for (int m = 0; m < MARK; m++) acc += sm[m] * tw[m*DMODEL + d];
  int i2 = (d >> 1) * 2;
  float div = expf((float)i2 * (-logf(10000.f) / (float)DMODEL));
  float ang = (float)t * div;
  acc += (d & 1) ? cosf(ang) : sinf(ang);
  g_h[(bt)*DMODEL + d] = acc;
}

// ---------------- fp32 GEMM 128x128 (bucket-critical qk projection) ----------------
template<int SPLIT>
__global__ void __launch_bounds__(256) gemm128(
    const float* __restrict__ A, const float* __restrict__ B,
    float* __restrict__ C, int M, int N, int K) {
  __shared__ __align__(16) float As[2][16][132];
  __shared__ __align__(16) float Bs[2][16][128];
  int tid = threadIdx.x;
  int bm = blockIdx.y * 128, bn = blockIdx.x * 128;
  int tx = tid & 15, ty = tid >> 4;
  int ar = tid >> 2, ac = tid & 3;
  int br = tid >> 5, bc = tid & 31;
  const float* Ap0 = A + (long)(bm + ar) * K + ac * 4;
  const float* Ap1 = A + (long)(bm + ar + 64) * K + ac * 4;
  const float* Bp  = B + (long)br * N + bn + bc * 4;
  float acc[8][8] = {};
  int ntiles = K >> 4;
  float4 a0, a1, b0, b1;
  a0 = *(const float4*)(Ap0);
  a1 = *(const float4*)(Ap1);
  b0 = *(const float4*)(Bp);
  b1 = *(const float4*)(Bp + 8 * (long)N);
  int buf = 0;
  for (int t = 0; t < ntiles; t++) {
    As[buf][ac*4+0][ar] = a0.x; As[buf][ac*4+1][ar] = a0.y;
    As[buf][ac*4+2][ar] = a0.z; As[buf][ac*4+3][ar] = a0.w;
    As[buf][ac*4+0][ar+64] = a1.x; As[buf][ac*4+1][ar+64] = a1.y;
    As[buf][ac*4+2][ar+64] = a1.z; As[buf][ac*4+3][ar+64] = a1.w;
    *(float4*)&Bs[buf][br][bc*4] = b0;
    *(float4*)&Bs[buf][br+8][bc*4] = b1;
    __syncthreads();
    if (t + 1 < ntiles) {
      a0 = *(const float4*)(Ap0 + (t+1)*16);
      a1 = *(const float4*)(Ap1 + (t+1)*16);
      b0 = *(const float4*)(Bp + (long)((t+1)*16) * N);
      b1 = *(const float4*)(Bp + (long)((t+1)*16 + 8) * N);
    }
    #pragma unroll
    for (int kk = 0; kk < 16; kk++) {
      float4 av0 = *(const float4*)&As[buf][kk][ty*4];
      float4 av1 = *(const float4*)&As[buf][kk][ty*4+64];
      float4 bv0 = *(const float4*)&Bs[buf][kk][tx*4];
      float4 bv1 = *(const float4*)&Bs[buf][kk][tx*4+64];
      float am[8] = {av0.x,av0.y,av0.z,av0.w,av1.x,av1.y,av1.z,av1.w};
      float bm_[8] = {bv0.x,bv0.y,bv0.z,bv0.w,bv1.x,bv1.y,bv1.z,bv1.w};
      #pragma unroll
      for (int i = 0; i < 8; i++)
        #pragma unroll
        for (int j = 0; j < 8; j++)
          acc[i][j] += am[i] * bm_[j];
    }
    buf ^= 1;
  }
  #pragma unroll
  for (int ih = 0; ih < 2; ih++) {
    #pragma unroll
    for (int qi = 0; qi < 4; qi++) {
      int r = bm + ty*4 + qi + ih*64;
      #pragma unroll
      for (int jh = 0; jh < 2; jh++) {
        int cb = bn + tx*4 + jh*64;
        float4 v;
        v.x = acc[ih*4+qi][jh*4+0];
        v.y = acc[ih*4+qi][jh*4+1];
        v.z = acc[ih*4+qi][jh*4+2];
        v.w = acc[ih*4+qi][jh*4+3];
        if (SPLIT) {
          int b = r / TLEN, t = r % TLEN;
          int hd = cb >> 5, dh = cb & 31;
          *(float4*)&C[(((long)b*NHEADS + hd)*TLEN + t)*DHEAD + dh] = v;
        } else {
          *(float4*)&C[(long)r*N + cb] = v;
        }
      }
    }
  }
}

// ---------------- TF32 tensor-core GEMM 128x128 ----------------
#define AS_STRIDE 20
#define BS_STRIDE 136
template<int EPI, int SPLIT>
__global__ void __launch_bounds__(256, 2) gemm_tf32(
    const float* __restrict__ A, const float* __restrict__ B,
    const float* __restrict__ bias, const float* __restrict__ R,
    const float* __restrict__ lng, const float* __restrict__ lnb,
    float* __restrict__ C, int M, int N, int K) {
  __shared__ uint32_t As[2][128][AS_STRIDE];
  __shared__ uint32_t Bs[2][16][BS_STRIDE];
  int tid = threadIdx.x;
  int warp = tid >> 5, lane = tid & 31;
  int wm = warp >> 2, wn = warp & 3;
  int m_warp = wm * 64, n_warp = wn * 32;
  int g = lane >> 2, l4 = lane & 3;
  int bm = blockIdx.y * 128, bn = blockIdx.x * 128;

  int ar = tid >> 1, ac = (tid & 1) * 8;
  int bk = tid >> 5, bnn = (tid & 31) * 4;
  const float* Ap = A + (long)(bm + ar) * K + ac;
  const float* Bp = B + (long)bk * N + bn + bnn;

  float acc[4][4][4] = {};
  int ntiles = K >> 4;
  float4 fa0, fa1, fb0, fb1;
  fa0 = *(const float4*)(Ap);
  fa1 = *(const float4*)(Ap + 4);
  fb0 = *(const float4*)(Bp);
  fb1 = *(const float4*)(Bp + 8 * (long)N);
  int buf = 0;
  for (int t = 0; t < ntiles; t++) {
    As[buf][ar][ac+0] = f2tf(fa0.x); As[buf][ar][ac+1] = f2tf(fa0.y);
    As[buf][ar][ac+2] = f2tf(fa0.z); As[buf][ar][ac+3] = f2tf(fa0.w);
    As[buf][ar][ac+4] = f2tf(fa1.x); As[buf][ar][ac+5] = f2tf(fa1.y);
    As[buf][ar][ac+6] = f2tf(fa1.z); As[buf][ar][ac+7] = f2tf(fa1.w);
    Bs[buf][bk][bnn+0] = f2tf(fb0.x); Bs[buf][bk][bnn+1] = f2tf(fb0.y);
    Bs[buf][bk][bnn+2] = f2tf(fb0.z); Bs[buf][bk][bnn+3] = f2tf(fb0.w);
    Bs[buf][bk+8][bnn+0] = f2tf(fb1.x); Bs[buf][bk+8][bnn+1] = f2tf(fb1.y);
    Bs[buf][bk+8][bnn+2] = f2tf(fb1.z); Bs[buf][bk+8][bnn+3] = f2tf(fb1.w);
    __syncthreads();
    if (t + 1 < ntiles) {
      fa0 = *(const float4*)(Ap + (t+1)*16);
      fa1 = *(const float4*)(Ap + (t+1)*16 + 4);
      fb0 = *(const float4*)(Bp + (long)((t+1)*16) * N);
      fb1 = *(const float4*)(Bp + (long)((t+1)*16 + 8) * N);
    }
    #pragma unroll
    for (int k8 = 0; k8 < 16; k8 += 8) {
      uint32_t afr[4][4], bfr[4][2];
      #pragma unroll
      for (int mf = 0; mf < 4; mf++) {
        int mr = m_warp + mf*16 + g;
        afr[mf][0] = As[buf][mr    ][k8 + l4];
        afr[mf][1] = As[buf][mr + 8][k8 + l4];
        afr[mf][2] = As[buf][mr    ][k8 + l4 + 4];
        afr[mf][3] = As[buf][mr + 8][k8 + l4 + 4];
      }
      #pragma unroll
      for (int nf = 0; nf < 4; nf++) {
        int nc = n_warp + nf*8 + g;
        bfr[nf][0] = Bs[buf][k8 + l4    ][nc];
        bfr[nf][1] = Bs[buf][k8 + l4 + 4][nc];
      }
      #pragma unroll
      for (int mf = 0; mf < 4; mf++)
        #pragma unroll
        for (int nf = 0; nf < 4; nf++)
          mma_tf32(acc[mf][nf], afr[mf], bfr[nf]);
    }
    buf ^= 1;
  }

  if (EPI == 1) {
    float* Ssum = (float*)As;
    float* Ssq  = ((float*)As) + 512;
    __syncthreads();
    float psum[4][2], psq[4][2];
    #pragma unroll
    for (int mf = 0; mf < 4; mf++) {
      #pragma unroll
      for (int hf = 0; hf < 2; hf++) {
        int r = bm + m_warp + mf*16 + g + hf*8;
        float s = 0.f, sq = 0.f;
        #pragma unroll
        for (int nf = 0; nf < 4; nf++) {
          int c = n_warp + nf*8 + 2*l4;
          #pragma unroll
          for (int p = 0; p < 2; p++) {
            float v = acc[mf][nf][hf*2+p] + bias[c+p] + R[(long)r*N + c + p];
            acc[mf][nf][hf*2+p] = v;
            s += v; sq += v*v;
          }
        }
        s  += __shfl_xor_sync(0xffffffffu, s, 1);
        s  += __shfl_xor_sync(0xffffffffu, s, 2);
        sq += __shfl_xor_sync(0xffffffffu, sq, 1);
        sq += __shfl_xor_sync(0xffffffffu, sq, 2);
        psum[mf][hf] = s; psq[mf][hf] = sq;
      }
    }
    if (l4 == 0) {
      #pragma unroll
      for (int mf = 0; mf < 4; mf++)
        #pragma unroll
        for (int hf = 0; hf < 2; hf++) {
          int rl = m_warp + mf*16 + g + hf*8;
          Ssum[rl*4 + wn] = psum[mf][hf];
          Ssq [rl*4 + wn] = psq[mf][hf];
        }
    }
    __syncthreads();
    #pragma unroll
    for (int mf = 0; mf < 4; mf++) {
      #pragma unroll
      for (int hf = 0; hf < 2; hf++) {
        int rl = m_warp + mf*16 + g + hf*8;
        int r = bm + rl;
        float s  = Ssum[rl*4+0] + Ssum[rl*4+1] + Ssum[rl*4+2] + Ssum[rl*4+3];
        float sq = Ssq [rl*4+0] + Ssq [rl*4+1] + Ssq [rl*4+2] + Ssq [rl*4+3];
        float mean = s * (1.f/128.f);
        float var = sq * (1.f/128.f) - mean*mean;
        float rstd = rsqrtf(var + 1e-5f);
        #pragma unroll
        for (int nf = 0; nf < 4; nf++) {
          int c = n_warp + nf*8 + 2*l4;
          float2 o;
          o.x = (acc[mf][nf][hf*2+0] - mean)*rstd*lng[c+0] + lnb[c+0];
          o.y = (acc[mf][nf][hf*2+1] - mean)*rstd*lng[c+1] + lnb[c+1];
          *(float2*)&C[(long)r*N + c] = o;
        }
      }
    }
  } else {
    #pragma unroll
    for (int mf = 0; mf < 4; mf++) {
      #pragma unroll
      for (int hf = 0; hf < 2; hf++) {
        int r = bm + m_warp + mf*16 + g + hf*8;
        #pragma unroll
        for (int nf = 0; nf < 4; nf++) {
          int c = bn + n_warp + nf*8 + 2*l4;
          float vx = acc[mf][nf][hf*2+0];
          float vy = acc[mf][nf][hf*2+1];
          if (EPI == 3) {
            vx += bias[c+0]; vy += bias[c+1];
            vx = 0.5f*vx*(1.f + erff(vx*0.70710678118f));
            vy = 0.5f*vy*(1.f + erff(vy*0.70710678118f));
          }
          if (SPLIT) {
            int b = r / TLEN, t = r % TLEN;
            int hd = c >> 5, dh = c & 31;
            *(float2*)&C[(((long)b*NHEADS + hd)*TLEN + t)*DHEAD + dh] = make_float2(vx, vy);
          } else {
            *(float2*)&C[(long)r*N + c] = make_float2(vx, vy);
          }
        }
      }
    }
  }
}

// ---------------- fused rotation + argmax, register-tiled ----------------
#define ROT_ROWS 32
__global__ void __launch_bounds__(128) rot_argmax_kernel(const float* __restrict__ rot_l) {
  __shared__ __align__(16) float qT[32][ROT_ROWS + 4];   // [d][row]
  int tid = threadIdx.x, lane = tid & 31, h = tid >> 5;
  long row0 = (long)blockIdx.x * ROT_ROWS;   // in bh*TLEN + t space
  int bh = (int)(row0 >> 12);
  int t0 = (int)(row0 & (TLEN - 1));

  // rot column -> registers (rot_l layout: [d][h][32])
  float rcol[32];
  #pragma unroll
  for (int d = 0; d < 32; d++) rcol[d] = rot_l[d*128 + tid];

  // stage 32 rows of qk, transposed
  {
    const float* gq = g_qk + (row0 + (tid & (ROT_ROWS-1)))*DHEAD;
    if (tid < ROT_ROWS) {
      #pragma unroll
      for (int f = 0; f < 8; f++) {
        float4 v = *(const float4*)(gq + f*4);
        qT[f*4+0][tid] = v.x; qT[f*4+1][tid] = v.y;
        qT[f*4+2][tid] = v.z; qT[f*4+3][tid] = v.w;
      }
    }
  }
  __syncthreads();

  unsigned char* bp = g_bkt + (bh*NHASH + h)*TLEN + t0;
  #pragma unroll
  for (int rg = 0; rg < ROT_ROWS/4; rg++) {
    float a0 = 0.f, a1 = 0.f, a2 = 0.f, a3 = 0.f;
    #pragma unroll
    for (int d = 0; d < 32; d++) {
      float4 q4 = *(const float4*)&qT[d][rg*4];
      float r = rcol[d];
      a0 += q4.x * r; a1 += q4.y * r; a2 += q4.z * r; a3 += q4.w * r;
    }
    #pragma unroll
    for (int rr = 0; rr < 4; rr++) {
      float v = (rr == 0) ? a0 : (rr == 1) ? a1 : (rr == 2) ? a2 : a3;
      float val; int bi;
      if (v >= -v) { val = v; bi = lane; } else { val = -v; bi = lane + 32; }
      #pragma unroll
      for (int off = 16; off; off >>= 1) {
        float ov = __shfl_xor_sync(0xffffffffu, val, off);
        int   oi = __shfl_xor_sync(0xffffffffu, bi,  off);
        if (ov > val || (ov == val && oi < bi)) { val = ov; bi = oi; }
      }
      if (lane == 0) bp[rg*4 + rr] = (unsigned char)bi;
    }
  }
}

// ---------------- counting sort ----------------
__global__ void hist_kernel() {
  __shared__ int cnt[256];
  int bh = blockIdx.x, tid = threadIdx.x;
  cnt[tid] = 0; __syncthreads();
  const unsigned char* bp = g_bkt + bh*ITEMS;
  for (int i = tid; i < ITEMS; i += 256) {
    int gb = ((i >> 12) << 6) + bp[i];
    atomicAdd(&cnt[gb], 1);
  }
  __syncthreads();
  if (tid == 0) {
    int s = 0;
    #pragma unroll 8
    for (int j = 0; j < 256; j++) { g_base[bh*256 + j] = s; s += cnt[j]; }
  }
}

__global__ void __launch_bounds__(1024) place_kernel() {
  int bhh = blockIdx.x;
  int bh = bhh >> 2, h = bhh & 3;
  int warp = threadIdx.x >> 5, lane = threadIdx.x & 31;
  const unsigned char* bp = g_bkt + (bh*NHASH + h)*TLEN;
  #pragma unroll
  for (int s = 0; s < 2; s++) {
    int lb = warp*2 + s;
    int base = g_base[bh*256 + h*64 + lb];
    for (int t0 = 0; t0 < TLEN; t0 += 32) {
      int my = bp[t0 + lane];
      unsigned mask = __ballot_sync(0xffffffffu, my == lb);
      if (my == lb) {
        int p = base + __popc(mask & ((1u << lane) - 1u));
        g_st[bh*ITEMS + p] = t0 + lane;
        g_pos[(bh*NHASH + h)*TLEN + t0 + lane] = p;
      }
      base += __popc(mask);
    }
  }
}

// ---------------- tensor-core LSH attention ----------------
#define ATTN_SMEM_WORDS 19904
__global__ void __launch_bounds__(128, 2) attn_kernel() {
  extern __shared__ __align__(16) uint32_t smw[];
  uint32_t* qS  = smw;
  uint32_t* kTd = smw + 2304;
  uint32_t* vS  = smw + 6656;
  uint32_t* pS  = smw + 11264;
  int* sQt = (int*)(smw + 19712);
  int* sKt = (int*)(smw + 19776);

  int bh = blockIdx.x >> 8;
  int c  = blockIdx.x & 255;
  int pc = (c + 255) & 255;
  int tid = threadIdx.x;
  int lane = tid & 31, warp = tid >> 5;
  int g = lane >> 2, l4 = lane & 3;

  {
    int p = (tid < 64) ? (c*64 + tid) : (pc*64 + (tid - 64));
    sKt[tid] = g_st[bh*ITEMS + p];
    if (tid < 64) sQt[tid] = sKt[tid];
  }
  __syncthreads();

  {
    int j = tid;
    int t = sKt[j];
    const float* gk = g_qk + ((long)bh*TLEN + t)*DHEAD;
    const float* gv = g_v  + ((long)bh*TLEN + t)*DHEAD;
    float4 kr[8];
    float ss = 0.f;
    #pragma unroll
    for (int f = 0; f < 8; f++) {
      kr[f] = *(const float4*)(gk + f*4);
      ss += kr[f].x*kr[f].x + kr[f].y*kr[f].y + kr[f].z*kr[f].z + kr[f].w*kr[f].w;
    }
    float inv = ATTN_SCALE / fmaxf(sqrtf(ss), 1e-12f);
    #pragma unroll
    for (int f = 0; f < 8; f++) {
      kTd[(f*4+0)*136 + j] = f2tf(kr[f].x * inv);
      kTd[(f*4+1)*136 + j] = f2tf(kr[f].y * inv);
      kTd[(f*4+2)*136 + j] = f2tf(kr[f].z * inv);
      kTd[(f*4+3)*136 + j] = f2tf(kr[f].w * inv);
    }
    #pragma unroll
    for (int f = 0; f < 8; f++) {
      float4 vv = *(const float4*)(gv + f*4);
      uint4 u;
      u.x = f2tf(vv.x); u.y = f2tf(vv.y); u.z = f2tf(vv.z); u.w = f2tf(vv.w);
      *(uint4*)&vS[j*36 + f*4] = u;
    }
  }
  if (tid < 64) {
    const float* gq = g_qk + ((long)bh*TLEN + sQt[tid])*DHEAD;
    #pragma unroll
    for (int f = 0; f < 8; f++) {
      float4 qq = *(const float4*)(gq + f*4);
      uint4 u;
      u.x = f2tf(qq.x); u.y = f2tf(qq.y); u.z = f2tf(qq.z); u.w = f2tf(qq.w);
      *(uint4*)&qS[tid*36 + f*4] = u;
    }
  }
  __syncthreads();

  int mb = warp * 16;
  float s[16][4];
  #pragma unroll
  for (int nt = 0; nt < 16; nt++)
    #pragma unroll
    for (int p = 0; p < 4; p++) s[nt][p] = 0.f;
  #pragma unroll
  for (int k8 = 0; k8 < 32; k8 += 8) {
    uint32_t afr[4];
    afr[0] = qS[(mb + g    )*36 + k8 + l4];
    afr[1] = qS[(mb + g + 8)*36 + k8 + l4];
    afr[2] = qS[(mb + g    )*36 + k8 + l4 + 4];
    afr[3] = qS[(mb + g + 8)*36 + k8 + l4 + 4];
    #pragma unroll
    for (int nt = 0; nt < 16; nt++) {
      uint32_t bfr[2];
      bfr[0] = kTd[(k8 + l4    )*136 + nt*8 + g];
      bfr[1] = kTd[(k8 + l4 + 4)*136 + nt*8 + g];
      mma_tf32(s[nt], afr, bfr);
    }
  }

  int r0 = mb + g, r1 = mb + g + 8;
  int qt0 = sQt[r0], qt1 = sQt[r1];
  float m0 = -1e30f, m1 = -1e30f;
  #pragma unroll
  for (int nt = 0; nt < 16; nt++) {
    int j0 = nt*8 + 2*l4;
    int kt0 = sKt[j0], kt1 = sKt[j0+1];
    if (kt0 == qt0) s[nt][0] = -5e4f;
    if (kt1 == qt0) s[nt][1] = -5e4f;
    if (kt0 == qt1) s[nt][2] = -5e4f;
    if (kt1 == qt1) s[nt][3] = -5e4f;
    m0 = fmaxf(m0, fmaxf(s[nt][0], s[nt][1]));
    m1 = fmaxf(m1, fmaxf(s[nt][2], s[nt][3]));
  }
  m0 = fmaxf(m0, __shfl_xor_sync(0xffffffffu, m0, 1));
  m0 = fmaxf(m0, __shfl_xor_sync(0xffffffffu, m0, 2));
  m1 = fmaxf(m1, __shfl_xor_sync(0xffffffffu, m1, 1));
  m1 = fmaxf(m1, __shfl_xor_sync(0xffffffffu, m1, 2));
  float sum0 = 0.f, sum1 = 0.f;
  #pragma unroll
  for (int nt = 0; nt < 16; nt++) {
    int j0 = nt*8 + 2*l4;
    uint32_t e00 = f2tf(__expf(s[nt][0] - m0));
    uint32_t e01 = f2tf(__expf(s[nt][1] - m0));
    uint32_t e10 = f2tf(__expf(s[nt][2] - m1));
    uint32_t e11 = f2tf(__expf(s[nt][3] - m1));
    sum0 += __uint_as_float(e00) + __uint_as_float(e01);
    sum1 += __uint_as_float(e10) + __uint_as_float(e11);
    *(uint2*)&pS[r0*132 + j0] = make_uint2(e00, e01);
    *(uint2*)&pS[r1*132 + j0] = make_uint2(e10, e11);
  }
  sum0 += __shfl_xor_sync(0xffffffffu, sum0, 1);
  sum0 += __shfl_xor_sync(0xffffffffu, sum0, 2);
  sum1 += __shfl_xor_sync(0xffffffffu, sum1, 1);
  sum1 += __shfl_xor_sync(0xffffffffu, sum1, 2);
  if (l4 == 0) {
    g_lse[bh*ITEMS + c*64 + r0] = m0 + __logf(sum0);
    g_lse[bh*ITEMS + c*64 + r1] = m1 + __logf(sum1);
  }
  __syncthreads();

  float o[4][4];
  #pragma unroll
  for (int nt = 0; nt < 4; nt++)
    #pragma unroll
    for (int p = 0; p < 4; p++) o[nt][p] = 0.f;
  #pragma unroll
  for (int k8 = 0; k8 < 128; k8 += 8) {
    uint32_t afr[4];
    afr[0] = pS[(mb + g    )*132 + k8 + l4];
    afr[1] = pS[(mb + g + 8)*132 + k8 + l4];
    afr[2] = pS[(mb + g    )*132 + k8 + l4 + 4];
    afr[3] = pS[(mb + g + 8)*132 + k8 + l4 + 4];
    #pragma unroll
    for (int nt = 0; nt < 4; nt++) {
      uint32_t bfr[2];
      bfr[0] = vS[(k8 + l4    )*36 + nt*8 + g];
      bfr[1] = vS[(k8 + l4 + 4)*36 + nt*8 + g];
      mma_tf32(o[nt], afr, bfr);
    }
  }
  float inv0 = 1.f / sum0, inv1 = 1.f / sum1;
  float* outp = g_so + ((long)bh*ITEMS + (long)c*64)*DHEAD;
  #pragma unroll
  for (int nt = 0; nt < 4; nt++) {
    int d0 = nt*8 + 2*l4;
    *(float2*)&outp[r0*DHEAD + d0] = make_float2(o[nt][0]*inv0, o[nt][1]*inv0);
    *(float2*)&outp[r1*DHEAD + d0] = make_float2(o[nt][2]*inv1, o[nt][3]*inv1);
  }
}

// ---------------- cross-hash combine ----------------
__global__ void combine_kernel() {
  int tid = threadIdx.x;
  int lane = tid & 31;
  long gw = (long)blockIdx.x * 4 + (tid >> 5);
  int bh = (int)(gw >> 12);
  int t  = (int)(gw & (TLEN - 1));
  float lse[NHASH], val[NHASH];
  int pidx[NHASH];
  #pragma unroll
  for (int h = 0; h < NHASH; h++) {
    pidx[h] = g_pos[(bh*NHASH + h)*TLEN + t];
    lse[h]  = g_lse[bh*ITEMS + pidx[h]];
    val[h]  = g_so[((long)bh*ITEMS + pidx[h])*DHEAD + lane];
  }
  float m = lse[0];
  #pragma unroll
  for (int h = 1; h < NHASH; h++) m = fmaxf(m, lse[h]);
  float acc = 0.f, wsum = 0.f;
  #pragma unroll
  for (int h = 0; h < NHASH; h++) {
    float w = __expf(lse[h] - m);
    acc += w * val[h]; wsum += w;
  }
  int b = bh >> 2, head = bh & 3;
  g_attn[((long)b*TLEN + t)*DMODEL + head*DHEAD + lane] = acc / wsum;
}

// ---------------- layernorm (final only) ----------------
__global__ void ln_kernel(const float* __restrict__ in, float* __restrict__ out,
                          const float* __restrict__ g, const float* __restrict__ bb) {
  int row = blockIdx.x, d = threadIdx.x;
  __shared__ float red[4];
  float x = in[(long)row*DMODEL + d];
  float s = x;
  #pragma unroll
  for (int off = 16; off; off >>= 1) s += __shfl_xor_sync(0xffffffffu, s, off);
  if ((d & 31) == 0) red[d >> 5] = s;
  __syncthreads();
  float mean = (red[0]+red[1]+red[2]+red[3]) * (1.f/DMODEL);
  float dv = x - mean;
  float s2 = dv*dv;
  #pragma unroll
  for (int off = 16; off; off >>= 1) s2 += __shfl_xor_sync(0xffffffffu, s2, off);
  __syncthreads();
  if ((d & 31) == 0) red[d >> 5] = s2;
  __syncthreads();
  float var = (red[0]+red[1]+red[2]+red[3]) * (1.f/DMODEL);
  out[(long)row*DMODEL + d] = dv * rsqrtf(var + 1e-5f) * g[d] + bb[d];
}

// ---------------- final head ----------------
__global__ void head_kernel(const float* __restrict__ projw, const float* __restrict__ projb,
                            const float* __restrict__ fcw, const float* __restrict__ fcb,
                            float* __restrict__ dout) {
  int b = blockIdx.x, tid = threadIdx.x;
  float lg0 = 0.f, lg1 = 0.f, lg2 = 0.f;
  for (int tt = tid; tt < PRED; tt += 128) {
    const float* hh = g_res + ((long)b*TLEN + SENC + tt)*DMODEL;
    float o4[4];
    #pragma unroll
    for (int cc = 0; cc < 4; cc++) {
      float a = projb[cc];
      #pragma unroll 8
      for (int d = 0; d < DMODEL; d++) a += hh[d]*projw[d*4 + cc];
      o4[cc] = a;
    }
    #pragma unroll
    for (int cc = 0; cc < 4; cc++) {
      int idx = (tt*4 + cc)*3;
      lg0 += o4[cc]*fcw[idx+0];
      lg1 += o4[cc]*fcw[idx+1];
      lg2 += o4[cc]*fcw[idx+2];
    }
  }
  __shared__ float red[3][128];
  red[0][tid] = lg0; red[1][tid] = lg1; red[2][tid] = lg2;
  __syncthreads();
  for (int off = 64; off; off >>= 1) {
    if (tid < off) {
      red[0][tid] += red[0][tid+off];
      red[1][tid] += red[1][tid+off];
      red[2][tid] += red[2][tid+off];
    }
    __syncthreads();
  }
  if (tid == 0) {
    float l0 = red[0][0]+fcb[0], l1 = red[1][0]+fcb[1], l2 = red[2][0]+fcb[2];
    float mx = fmaxf(l0, fmaxf(l1, l2));
    float e0 = expf(l0-mx), e1 = expf(l1-mx), e2 = expf(l2-mx);
    float is = 1.f/(e0+e1+e2);
    dout[b*3+0] = e0*is; dout[b*3+1] = e1*is; dout[b*3+2] = e2*is;
  }
}

// ---------------- host launch ----------------
extern "C" void kernel_launch(void* const* d_in, const int* in_sizes, int n_in,
                              void* d_out, int out_size) {
  const float* x_enc      = (const float*)d_in[0];
  const float* x_mark_enc = (const float*)d_in[1];
  const float* x_dec      = (const float*)d_in[2];
  const float* x_mark_dec = (const float*)d_in[3];
  const float* conv_w     = (const float*)d_in[4];
  const float* timef_w    = (const float*)d_in[5];
  const float* Wqk        = (const float*)d_in[6];
  const float* Wv         = (const float*)d_in[7];
  const float* Wo         = (const float*)d_in[8];
  const float* bo         = (const float*)d_in[9];
  const float* rot        = (const float*)d_in[10];
  const float* ln1_g      = (const float*)d_in[11];
  const float* ln1_b      = (const float*)d_in[12];
  const float* ln2_g      = (const float*)d_in[13];
  const float* ln2_b      = (const float*)d_in[14];
  const float* w1         = (const float*)d_in[15];
  const float* b1         = (const float*)d_in[16];
  const float* w2         = (const float*)d_in[17];
  const float* b2         = (const float*)d_in[18];
  const float* lnf_g      = (const float*)d_in[19];
  const float* lnf_b      = (const float*)d_in[20];
  const float* proj_w     = (const float*)d_in[21];
  const float* proj_b     = (const float*)d_in[22];
  const float* fc1_w      = (const float*)d_in[23];
  const float* fc1_b      = (const float*)d_in[24];
  (void)in_sizes; (void)n_in; (void)out_size;

  void* p;
  cudaGetSymbolAddress(&p, g_h);    float* ph    = (float*)p;
  cudaGetSymbolAddress(&p, g_res);  float* pres  = (float*)p;
  cudaGetSymbolAddress(&p, g_ff);   float* pff   = (float*)p;
  cudaGetSymbolAddress(&p, g_qk);   float* pqk   = (float*)p;
  cudaGetSymbolAddress(&p, g_v);    float* pv    = (float*)p;
  cudaGetSymbolAddress(&p, g_attn); float* pattn = (float*)p;

  const int attn_smem = ATTN_SMEM_WORDS * 4;
  cudaFuncSetAttribute(attn_kernel, cudaFuncAttributeMaxDynamicSharedMemorySize, attn_smem);

  embed_kernel<<<MROWS, 128>>>(x_enc, x_mark_enc, x_dec, x_mark_dec, conv_w, timef_w);

  for (int l = 0; l < NLAYERS; l++) {
    const float* Wqk_l = Wqk + (long)l*DMODEL*DMODEL;
    const float* Wv_l  = Wv  + (long)l*DMODEL*DMODEL;
    const float* Wo_l  = Wo  + (long)l*DMODEL*DMODEL;
    const float* bo_l  = bo  + l*DMODEL;
    const float* rot_l = rot + (long)l*DHEAD*NHASH*(NBUCK/2);
    const float* w1_l  = w1 + (long)l*DMODEL*DFF;
    const float* b1_l  = b1 + l*DFF;
    const float* w2_l  = w2 + (long)l*DFF*DMODEL;
    const float* b2_l  = b2 + l*DMODEL;

    gemm128<1><<<dim3(1,256), 256>>>(ph, Wqk_l, pqk, MROWS, DMODEL, DMODEL);
    gemm_tf32<0,1><<<dim3(1,256), 256>>>(ph, Wv_l, nullptr, nullptr, nullptr, nullptr, pv, MROWS, DMODEL, DMODEL);

    rot_argmax_kernel<<<BHN*TLEN/ROT_ROWS, 128>>>(rot_l);

    hist_kernel<<<BHN, 256>>>();
    place_kernel<<<BHN*NHASH, 1024>>>();

    attn_kernel<<<BHN*NCHUNK, 128, attn_smem>>>();
    combine_kernel<<<BHN*TLEN/4, 128>>>();

    gemm_tf32<1,0><<<dim3(1,256), 256>>>(pattn, Wo_l, bo_l, ph, ln1_g + l*DMODEL, ln1_b + l*DMODEL,
                                         ph, MROWS, DMODEL, DMODEL);
    gemm_tf32<3,0><<<dim3(4,256), 256>>>(ph, w1_l, b1_l, nullptr, nullptr, nullptr, pff, MROWS, DFF, DMODEL);
    gemm_tf32<1,0><<<dim3(1,256), 256>>>(pff, w2_l, b2_l, ph, ln2_g + l*DMODEL, ln2_b + l*DMODEL,
                                         ph, MROWS, DMODEL, DFF);
  }

  ln_kernel<<<MROWS, 128>>>(ph, pres, lnf_g, lnf_b);
  head_kernel<<<BSZ, 128>>>(proj_w, proj_b, fc1_w, fc1_b, (float*)d_out);
}

// round 8
// speedup vs baseline: 3.9758x; 1.0430x over previous
#include <cuda_runtime.h>
#include <math.h>
#include <stdint.h>

// ---------------- problem constants ----------------
#define BSZ     8
#define SENC    3072
#define PRED    1024
#define ENCIN   40
#define DMODEL  128
#define NHEADS  4
#define DHEAD   32
#define NHASH   4
#define NBUCK   64
#define BUCKETSZ 64
#define NLAYERS 2
#define DFF     512
#define COUT    4
#define NCLASS  3
#define MARK    4
#define TLEN    4096
#define BHN     (BSZ*NHEADS)          // 32
#define MROWS   (BSZ*TLEN)            // 32768
#define NCHUNK  (NHASH*TLEN/BUCKETSZ) // 256
#define ITEMS   (NHASH*TLEN)          // 16384 per bh
#define ATTN_SCALE 0.17677669529663689f

// ---------------- scratch ----------------
__device__ float g_h[MROWS*DMODEL];
__device__ float g_res[MROWS*DMODEL];
__device__ float g_ff[MROWS*DFF];
__device__ float g_qk[BHN*TLEN*DHEAD];
__device__ float g_v[BHN*TLEN*DHEAD];
__device__ float g_so[(long)BHN*ITEMS*DHEAD];
__device__ float g_lse[BHN*ITEMS];
__device__ int   g_st[BHN*ITEMS];
__device__ int   g_pos[BHN*ITEMS];
__device__ unsigned char g_bkt[BHN*ITEMS];
__device__ int   g_base[BHN*256];
__device__ float g_attn[MROWS*DMODEL];

// ---------------- tf32 helpers ----------------
__device__ __forceinline__ uint32_t f2tf(float x) {
  uint32_t u; asm("cvt.rna.tf32.f32 %0, %1;" : "=r"(u) : "f"(x)); return u;
}
__device__ __forceinline__ void split_tf(float x, uint32_t& hi, uint32_t& lo) {
  hi = f2tf(x);
  lo = f2tf(x - __uint_as_float(hi));
}
__device__ __forceinline__ void mma_tf32(float* c, const uint32_t* a, const uint32_t* b) {
  asm volatile(
    "mma.sync.aligned.m16n8k8.row.col.f32.tf32.tf32.f32 "
    "{%0,%1,%2,%3}, {%4,%5,%6,%7}, {%8,%9}, {%0,%1,%2,%3};\n"
    : "+f"(c[0]), "+f"(c[1]), "+f"(c[2]), "+f"(c[3])
    : "r"(a[0]), "r"(a[1]), "r"(a[2]), "r"(a[3]), "r"(b[0]), "r"(b[1]));
}

// ---------------- embedding ----------------
__global__ void embed_kernel(const float* __restrict__ xe, const float* __restrict__ xme,
                             const float* __restrict__ xd, const float* __restrict__ xmd,
                             const float* __restrict__ convw, const float* __restrict__ tw) {
  int bt = blockIdx.x; int b = bt / TLEN; int t = bt % TLEN;
  int d = threadIdx.x;
  __shared__ float sx[3][ENCIN];
  __shared__ float sm[MARK];
  for (int i = d; i < 3*ENCIN; i += 128) {
    int k = i / ENCIN, c = i % ENCIN;
    int tt = t - 1 + k; tt = (tt + TLEN) % TLEN;
    float v = (tt < SENC) ? xe[(b*SENC + tt)*ENCIN + c]
                          : xd[(b*PRED + (tt - SENC))*ENCIN + c];
    sx[k][c] = v;
  }
  if (d < MARK)
    sm[d] = (t < SENC) ? xme[(b*SENC + t)*MARK + d]
                       : xmd[(b*PRED + (t - SENC))*MARK + d];
  __syncthreads();
  float acc = 0.f;
  #pragma unroll
  for (int k = 0; k < 3; k++)
    #pragma unroll
    for (int c = 0; c < ENCIN; c++)
      acc += sx[k][c] * convw[(k*ENCIN + c)*DMODEL + d];
  #pragma unroll
  for (int m = 0; m < MARK; m++) acc += sm[m] * tw[m*DMODEL + d];
  int i2 = (d >> 1) * 2;
  float div = expf((float)i2 * (-logf(10000.f) / (float)DMODEL));
  float ang = (float)t * div;
  acc += (d & 1) ? cosf(ang) : sinf(ang);
  g_h[(bt)*DMODEL + d] = acc;
}

#define AS_STRIDE 20
#define BS_STRIDE 136

// ---------------- error-corrected TF32x3 GEMM (qk projection; ~fp32 accuracy) ----------------
// Single-buffered smem (fits 48KB static). C = A @ B with head-split scatter. N == 128.
__global__ void __launch_bounds__(256, 2) gemm_qk_tf32x3(
    const float* __restrict__ A, const float* __restrict__ B,
    float* __restrict__ C, int M, int N, int K) {
  __shared__ uint32_t Ash[128][AS_STRIDE];
  __shared__ uint32_t Asl[128][AS_STRIDE];
  __shared__ uint32_t Bsh[16][BS_STRIDE];
  __shared__ uint32_t Bsl[16][BS_STRIDE];
  int tid = threadIdx.x;
  int warp = tid >> 5, lane = tid & 31;
  int wm = warp >> 2, wn = warp & 3;
  int m_warp = wm * 64, n_warp = wn * 32;
  int g = lane >> 2, l4 = lane & 3;
  int bm = blockIdx.y * 128, bn = blockIdx.x * 128;

  int ar = tid >> 1, ac = (tid & 1) * 8;
  int bk = tid >> 5, bnn = (tid & 31) * 4;
  const float* Ap = A + (long)(bm + ar) * K + ac;
  const float* Bp = B + (long)bk * N + bn + bnn;

  float acc[4][4][4] = {};
  int ntiles = K >> 4;
  float4 fa0, fa1, fb0, fb1;
  fa0 = *(const float4*)(Ap);
  fa1 = *(const float4*)(Ap + 4);
  fb0 = *(const float4*)(Bp);
  fb1 = *(const float4*)(Bp + 8 * (long)N);
  for (int t = 0; t < ntiles; t++) {
    float av[8] = {fa0.x,fa0.y,fa0.z,fa0.w,fa1.x,fa1.y,fa1.z,fa1.w};
    #pragma unroll
    for (int i = 0; i < 8; i++) {
      uint32_t hi, lo; split_tf(av[i], hi, lo);
      Ash[ar][ac+i] = hi; Asl[ar][ac+i] = lo;
    }
    float bv0[4] = {fb0.x,fb0.y,fb0.z,fb0.w};
    float bv1[4] = {fb1.x,fb1.y,fb1.z,fb1.w};
    #pragma unroll
    for (int i = 0; i < 4; i++) {
      uint32_t hi, lo; split_tf(bv0[i], hi, lo);
      Bsh[bk][bnn+i] = hi; Bsl[bk][bnn+i] = lo;
      split_tf(bv1[i], hi, lo);
      Bsh[bk+8][bnn+i] = hi; Bsl[bk+8][bnn+i] = lo;
    }
    __syncthreads();
    if (t + 1 < ntiles) {
      fa0 = *(const float4*)(Ap + (t+1)*16);
      fa1 = *(const float4*)(Ap + (t+1)*16 + 4);
      fb0 = *(const float4*)(Bp + (long)((t+1)*16) * N);
      fb1 = *(const float4*)(Bp + (long)((t+1)*16 + 8) * N);
    }
    #pragma unroll
    for (int k8 = 0; k8 < 16; k8 += 8) {
      uint32_t ah[4][4], al[4][4], bh[4][2], bl[4][2];
      #pragma unroll
      for (int mf = 0; mf < 4; mf++) {
        int mr = m_warp + mf*16 + g;
        ah[mf][0] = Ash[mr    ][k8 + l4];
        ah[mf][1] = Ash[mr + 8][k8 + l4];
        ah[mf][2] = Ash[mr    ][k8 + l4 + 4];
        ah[mf][3] = Ash[mr + 8][k8 + l4 + 4];
        al[mf][0] = Asl[mr    ][k8 + l4];
        al[mf][1] = Asl[mr + 8][k8 + l4];
        al[mf][2] = Asl[mr    ][k8 + l4 + 4];
        al[mf][3] = Asl[mr + 8][k8 + l4 + 4];
      }
      #pragma unroll
      for (int nf = 0; nf < 4; nf++) {
        int nc = n_warp + nf*8 + g;
        bh[nf][0] = Bsh[k8 + l4    ][nc];
        bh[nf][1] = Bsh[k8 + l4 + 4][nc];
        bl[nf][0] = Bsl[k8 + l4    ][nc];
        bl[nf][1] = Bsl[k8 + l4 + 4][nc];
      }
      #pragma unroll
      for (int mf = 0; mf < 4; mf++)
        #pragma unroll
        for (int nf = 0; nf < 4; nf++) {
          mma_tf32(acc[mf][nf], al[mf], bh[nf]);
          mma_tf32(acc[mf][nf], ah[mf], bl[nf]);
          mma_tf32(acc[mf][nf], ah[mf], bh[nf]);
        }
    }
    __syncthreads();
  }
  #pragma unroll
  for (int mf = 0; mf < 4; mf++) {
    #pragma unroll
    for (int hf = 0; hf < 2; hf++) {
      int r = bm + m_warp + mf*16 + g + hf*8;
      #pragma unroll
      for (int nf = 0; nf < 4; nf++) {
        int c = bn + n_warp + nf*8 + 2*l4;
        float vx = acc[mf][nf][hf*2+0];
        float vy = acc[mf][nf][hf*2+1];
        int b = r / TLEN, t = r % TLEN;
        int hd = c >> 5, dh = c & 31;
        *(float2*)&C[(((long)b*NHEADS + hd)*TLEN + t)*DHEAD + dh] = make_float2(vx, vy);
      }
    }
  }
}

// ---------------- TF32 tensor-core GEMM 128x128 ----------------
// EPI: 0 none, 1 = +bias +residual +LayerNorm (N==128, grid.x==1, C may alias R), 3 = +bias +GELU
template<int EPI, int SPLIT>
__global__ void __launch_bounds__(256, 2) gemm_tf32(
    const float* __restrict__ A, const float* __restrict__ B,
    const float* __restrict__ bias, const float* __restrict__ R,
    const float* __restrict__ lng, const float* __restrict__ lnb,
    float* __restrict__ C, int M, int N, int K) {
  __shared__ uint32_t As[2][128][AS_STRIDE];
  __shared__ uint32_t Bs[2][16][BS_STRIDE];
  int tid = threadIdx.x;
  int warp = tid >> 5, lane = tid & 31;
  int wm = warp >> 2, wn = warp & 3;
  int m_warp = wm * 64, n_warp = wn * 32;
  int g = lane >> 2, l4 = lane & 3;
  int bm = blockIdx.y * 128, bn = blockIdx.x * 128;

  int ar = tid >> 1, ac = (tid & 1) * 8;
  int bk = tid >> 5, bnn = (tid & 31) * 4;
  const float* Ap = A + (long)(bm + ar) * K + ac;
  const float* Bp = B + (long)bk * N + bn + bnn;

  float acc[4][4][4] = {};
  int ntiles = K >> 4;
  float4 fa0, fa1, fb0, fb1;
  fa0 = *(const float4*)(Ap);
  fa1 = *(const float4*)(Ap + 4);
  fb0 = *(const float4*)(Bp);
  fb1 = *(const float4*)(Bp + 8 * (long)N);
  int buf = 0;
  for (int t = 0; t < ntiles; t++) {
    As[buf][ar][ac+0] = f2tf(fa0.x); As[buf][ar][ac+1] = f2tf(fa0.y);
    As[buf][ar][ac+2] = f2tf(fa0.z); As[buf][ar][ac+3] = f2tf(fa0.w);
    As[buf][ar][ac+4] = f2tf(fa1.x); As[buf][ar][ac+5] = f2tf(fa1.y);
    As[buf][ar][ac+6] = f2tf(fa1.z); As[buf][ar][ac+7] = f2tf(fa1.w);
    Bs[buf][bk][bnn+0] = f2tf(fb0.x); Bs[buf][bk][bnn+1] = f2tf(fb0.y);
    Bs[buf][bk][bnn+2] = f2tf(fb0.z); Bs[buf][bk][bnn+3] = f2tf(fb0.w);
    Bs[buf][bk+8][bnn+0] = f2tf(fb1.x); Bs[buf][bk+8][bnn+1] = f2tf(fb1.y);
    Bs[buf][bk+8][bnn+2] = f2tf(fb1.z); Bs[buf][bk+8][bnn+3] = f2tf(fb1.w);
    __syncthreads();
    if (t + 1 < ntiles) {
      fa0 = *(const float4*)(Ap + (t+1)*16);
      fa1 = *(const float4*)(Ap + (t+1)*16 + 4);
      fb0 = *(const float4*)(Bp + (long)((t+1)*16) * N);
      fb1 = *(const float4*)(Bp + (long)((t+1)*16 + 8) * N);
    }
    #pragma unroll
    for (int k8 = 0; k8 < 16; k8 += 8) {
      uint32_t afr[4][4], bfr[4][2];
      #pragma unroll
      for (int mf = 0; mf < 4; mf++) {
        int mr = m_warp + mf*16 + g;
        afr[mf][0] = As[buf][mr    ][k8 + l4];
        afr[mf][1] = As[buf][mr + 8][k8 + l4];
        afr[mf][2] = As[buf][mr    ][k8 + l4 + 4];
        afr[mf][3] = As[buf][mr + 8][k8 + l4 + 4];
      }
      #pragma unroll
      for (int nf = 0; nf < 4; nf++) {
        int nc = n_warp + nf*8 + g;
        bfr[nf][0] = Bs[buf][k8 + l4    ][nc];
        bfr[nf][1] = Bs[buf][k8 + l4 + 4][nc];
      }
      #pragma unroll
      for (int mf = 0; mf < 4; mf++)
        #pragma unroll
        for (int nf = 0; nf < 4; nf++)
          mma_tf32(acc[mf][nf], afr[mf], bfr[nf]);
    }
    buf ^= 1;
  }

  if (EPI == 1) {
    float* Ssum = (float*)As;
    float* Ssq  = ((float*)As) + 512;
    __syncthreads();
    float psum[4][2], psq[4][2];
    #pragma unroll
    for (int mf = 0; mf < 4; mf++) {
      #pragma unroll
      for (int hf = 0; hf < 2; hf++) {
        int r = bm + m_warp + mf*16 + g + hf*8;
        float s = 0.f, sq = 0.f;
        #pragma unroll
        for (int nf = 0; nf < 4; nf++) {
          int c = n_warp + nf*8 + 2*l4;
          #pragma unroll
          for (int p = 0; p < 2; p++) {
            float v = acc[mf][nf][hf*2+p] + bias[c+p] + R[(long)r*N + c + p];
            acc[mf][nf][hf*2+p] = v;
            s += v; sq += v*v;
          }
        }
        s  += __shfl_xor_sync(0xffffffffu, s, 1);
        s  += __shfl_xor_sync(0xffffffffu, s, 2);
        sq += __shfl_xor_sync(0xffffffffu, sq, 1);
        sq += __shfl_xor_sync(0xffffffffu, sq, 2);
        psum[mf][hf] = s; psq[mf][hf] = sq;
      }
    }
    if (l4 == 0) {
      #pragma unroll
      for (int mf = 0; mf < 4; mf++)
        #pragma unroll
        for (int hf = 0; hf < 2; hf++) {
          int rl = m_warp + mf*16 + g + hf*8;
          Ssum[rl*4 + wn] = psum[mf][hf];
          Ssq [rl*4 + wn] = psq[mf][hf];
        }
    }
    __syncthreads();
    #pragma unroll
    for (int mf = 0; mf < 4; mf++) {
      #pragma unroll
      for (int hf = 0; hf < 2; hf++) {
        int rl = m_warp + mf*16 + g + hf*8;
        int r = bm + rl;
        float s  = Ssum[rl*4+0] + Ssum[rl*4+1] + Ssum[rl*4+2] + Ssum[rl*4+3];
        float sq = Ssq [rl*4+0] + Ssq [rl*4+1] + Ssq [rl*4+2] + Ssq [rl*4+3];
        float mean = s * (1.f/128.f);
        float var = sq * (1.f/128.f) - mean*mean;
        float rstd = rsqrtf(var + 1e-5f);
        #pragma unroll
        for (int nf = 0; nf < 4; nf++) {
          int c = n_warp + nf*8 + 2*l4;
          float2 o;
          o.x = (acc[mf][nf][hf*2+0] - mean)*rstd*lng[c+0] + lnb[c+0];
          o.y = (acc[mf][nf][hf*2+1] - mean)*rstd*lng[c+1] + lnb[c+1];
          *(float2*)&C[(long)r*N + c] = o;
        }
      }
    }
  } else {
    #pragma unroll
    for (int mf = 0; mf < 4; mf++) {
      #pragma unroll
      for (int hf = 0; hf < 2; hf++) {
        int r = bm + m_warp + mf*16 + g + hf*8;
        #pragma unroll
        for (int nf = 0; nf < 4; nf++) {
          int c = bn + n_warp + nf*8 + 2*l4;
          float vx = acc[mf][nf][hf*2+0];
          float vy = acc[mf][nf][hf*2+1];
          if (EPI == 3) {
            vx += bias[c+0]; vy += bias[c+1];
            vx = 0.5f*vx*(1.f + erff(vx*0.70710678118f));
            vy = 0.5f*vy*(1.f + erff(vy*0.70710678118f));
          }
          if (SPLIT) {
            int b = r / TLEN, t = r % TLEN;
            int hd = c >> 5, dh = c & 31;
            *(float2*)&C[(((long)b*NHEADS + hd)*TLEN + t)*DHEAD + dh] = make_float2(vx, vy);
          } else {
            *(float2*)&C[(long)r*N + c] = make_float2(vx, vy);
          }
        }
      }
    }
  }
}

// ---------------- fused rotation + argmax: REDUX-based ----------------
#define ROT_ROWS 64
__global__ void __launch_bounds__(128) rot_argmax_kernel(const float* __restrict__ rot_l) {
  __shared__ __align__(16) float qT[32][ROT_ROWS + 4];   // [d][row]
  int tid = threadIdx.x, lane = tid & 31, h = tid >> 5;
  long row0 = (long)blockIdx.x * ROT_ROWS;   // in bh*TLEN + t space
  int bh = (int)(row0 >> 12);
  int t0 = (int)(row0 & (TLEN - 1));

  float rcol[32];
  #pragma unroll
  for (int d = 0; d < 32; d++) rcol[d] = rot_l[d*128 + tid];

  {
    int r = tid >> 1;
    int half = (tid & 1) * 16;
    const float* gq = g_qk + (row0 + r)*DHEAD + half;
    #pragma unroll
    for (int f = 0; f < 4; f++) {
      float4 v = *(const float4*)(gq + f*4);
      qT[half + f*4 + 0][r] = v.x; qT[half + f*4 + 1][r] = v.y;
      qT[half + f*4 + 2][r] = v.z; qT[half + f*4 + 3][r] = v.w;
    }
  }
  __syncthreads();

  unsigned char* bp = g_bkt + (bh*NHASH + h)*TLEN + t0;
  #pragma unroll 4
  for (int rg = 0; rg < ROT_ROWS/4; rg++) {
    float a0 = 0.f, a1 = 0.f, a2 = 0.f, a3 = 0.f;
    #pragma unroll
    for (int d = 0; d < 32; d++) {
      float4 q4 = *(const float4*)&qT[d][rg*4];
      float r = rcol[d];
      a0 += q4.x * r; a1 += q4.y * r; a2 += q4.z * r; a3 += q4.w * r;
    }
    #pragma unroll
    for (int rr = 0; rr < 4; rr++) {
      float v = (rr == 0) ? a0 : (rr == 1) ? a1 : (rr == 2) ? a2 : a3;
      uint32_t key = __float_as_uint(fabsf(v));
      uint32_t mx = __reduce_max_sync(0xffffffffu, key);
      bool eq = (key == mx);
      bool pos = (v >= -v);
      unsigned bpos = __ballot_sync(0xffffffffu, eq && pos);
      unsigned bneg = __ballot_sync(0xffffffffu, eq && !pos);
      int bucket = bpos ? (__ffs(bpos) - 1) : (__ffs(bneg) + 31);
      if (lane == 0) bp[rg*4 + rr] = (unsigned char)bucket;
    }
  }
}

// ---------------- counting sort ----------------
__global__ void hist_kernel() {
  __shared__ int cnt[256];
  int bh = blockIdx.x, tid = threadIdx.x;
  cnt[tid] = 0; __syncthreads();
  const unsigned char* bp = g_bkt + bh*ITEMS;
  for (int i = tid; i < ITEMS; i += 256) {
    int gb = ((i >> 12) << 6) + bp[i];
    atomicAdd(&cnt[gb], 1);
  }
  __syncthreads();
  if (tid == 0) {
    int s = 0;
    #pragma unroll 8
    for (int j = 0; j < 256; j++) { g_base[bh*256 + j] = s; s += cnt[j]; }
  }
}

__global__ void __launch_bounds__(1024) place_kernel() {
  int bhh = blockIdx.x;
  int bh = bhh >> 2, h = bhh & 3;
  int warp = threadIdx.x >> 5, lane = threadIdx.x & 31;
  const unsigned char* bp = g_bkt + (bh*NHASH + h)*TLEN;
  #pragma unroll
  for (int s = 0; s < 2; s++) {
    int lb = warp*2 + s;
    int base = g_base[bh*256 + h*64 + lb];
    for (int t0 = 0; t0 < TLEN; t0 += 32) {
      int my = bp[t0 + lane];
      unsigned mask = __ballot_sync(0xffffffffu, my == lb);
      if (my == lb) {
        int p = base + __popc(mask & ((1u << lane) - 1u));
        g_st[bh*ITEMS + p] = t0 + lane;
        g_pos[(bh*NHASH + h)*TLEN + t0 + lane] = p;
      }
      base += __popc(mask);
    }
  }
}

// ---------------- tensor-core LSH attention ----------------
#define ATTN_SMEM_WORDS 19904
__global__ void __launch_bounds__(128, 2) attn_kernel() {
  extern __shared__ __align__(16) uint32_t smw[];
  uint32_t* qS  = smw;
  uint32_t* kTd = smw + 2304;
  uint32_t* vS  = smw + 6656;
  uint32_t* pS  = smw + 11264;
  int* sQt = (int*)(smw + 19712);
  int* sKt = (int*)(smw + 19776);

  int bh = blockIdx.x >> 8;
  int c  = blockIdx.x & 255;
  int pc = (c + 255) & 255;
  int tid = threadIdx.x;
  int lane = tid & 31, warp = tid >> 5;
  int g = lane >> 2, l4 = lane & 3;

  {
    int p = (tid < 64) ? (c*64 + tid) : (pc*64 + (tid - 64));
    sKt[tid] = g_st[bh*ITEMS + p];
    if (tid < 64) sQt[tid] = sKt[tid];
  }
  __syncthreads();

  {
    int j = tid;
    int t = sKt[j];
    const float* gk = g_qk + ((long)bh*TLEN + t)*DHEAD;
    const float* gv = g_v  + ((long)bh*TLEN + t)*DHEAD;
    float4 kr[8];
    float ss = 0.f;
    #pragma unroll
    for (int f = 0; f < 8; f++) {
      kr[f] = *(const float4*)(gk + f*4);
      ss += kr[f].x*kr[f].x + kr[f].y*kr[f].y + kr[f].z*kr[f].z + kr[f].w*kr[f].w;
    }
    float inv = ATTN_SCALE / fmaxf(sqrtf(ss), 1e-12f);
    #pragma unroll
    for (int f = 0; f < 8; f++) {
      kTd[(f*4+0)*136 + j] = f2tf(kr[f].x * inv);
      kTd[(f*4+1)*136 + j] = f2tf(kr[f].y * inv);
      kTd[(f*4+2)*136 + j] = f2tf(kr[f].z * inv);
      kTd[(f*4+3)*136 + j] = f2tf(kr[f].w * inv);
    }
    #pragma unroll
    for (int f = 0; f < 8; f++) {
      float4 vv = *(const float4*)(gv + f*4);
      uint4 u;
      u.x = f2tf(vv.x); u.y = f2tf(vv.y); u.z = f2tf(vv.z); u.w = f2tf(vv.w);
      *(uint4*)&vS[j*36 + f*4] = u;
    }
  }
  if (tid < 64) {
    const float* gq = g_qk + ((long)bh*TLEN + sQt[tid])*DHEAD;
    #pragma unroll
    for (int f = 0; f < 8; f++) {
      float4 qq = *(const float4*)(gq + f*4);
      uint4 u;
      u.x = f2tf(qq.x); u.y = f2tf(qq.y); u.z = f2tf(qq.z); u.w = f2tf(qq.w);
      *(uint4*)&qS[tid*36 + f*4] = u;
    }
  }
  __syncthreads();

  int mb = warp * 16;
  float s[16][4];
  #pragma unroll
  for (int nt = 0; nt < 16; nt++)
    #pragma unroll
    for (int p = 0; p < 4; p++) s[nt][p] = 0.f;
  #pragma unroll
  for (int k8 = 0; k8 < 32; k8 += 8) {
    uint32_t afr[4];
    afr[0] = qS[(mb + g    )*36 + k8 + l4];
    afr[1] = qS[(mb + g + 8)*36 + k8 + l4];
    afr[2] = qS[(mb + g    )*36 + k8 + l4 + 4];
    afr[3] = qS[(mb + g + 8)*36 + k8 + l4 + 4];
    #pragma unroll
    for (int nt = 0; nt < 16; nt++) {
      uint32_t bfr[2];
      bfr[0] = kTd[(k8 + l4    )*136 + nt*8 + g];
      bfr[1] = kTd[(k8 + l4 + 4)*136 + nt*8 + g];
      mma_tf32(s[nt], afr, bfr);
    }
  }

  int r0 = mb + g, r1 = mb + g + 8;
  int qt0 = sQt[r0], qt1 = sQt[r1];
  float m0 = -1e30f, m1 = -1e30f;
  #pragma unroll
  for (int nt = 0; nt < 16; nt++) {
    int j0 = nt*8 + 2*l4;
    int kt0 = sKt[j0], kt1 = sKt[j0+1];
    if (kt0 == qt0) s[nt][0] = -5e4f;
    if (kt1 == qt0) s[nt][1] = -5e4f;
    if (kt0 == qt1) s[nt][2] = -5e4f;
    if (kt1 == qt1) s[nt][3] = -5e4f;
    m0 = fmaxf(m0, fmaxf(s[nt][0], s[nt][1]));
    m1 = fmaxf(m1, fmaxf(s[nt][2], s[nt][3]));
  }
  m0 = fmaxf(m0, __shfl_xor_sync(0xffffffffu, m0, 1));
  m0 = fmaxf(m0, __shfl_xor_sync(0xffffffffu, m0, 2));
  m1 = fmaxf(m1, __shfl_xor_sync(0xffffffffu, m1, 1));
  m1 = fmaxf(m1, __shfl_xor_sync(0xffffffffu, m1, 2));
  float sum0 = 0.f, sum1 = 0.f;
  #pragma unroll
  for (int nt = 0; nt < 16; nt++) {
    int j0 = nt*8 + 2*l4;
    uint32_t e00 = f2tf(__expf(s[nt][0] - m0));
    uint32_t e01 = f2tf(__expf(s[nt][1] - m0));
    uint32_t e10 = f2tf(__expf(s[nt][2] - m1));
    uint32_t e11 = f2tf(__expf(s[nt][3] - m1));
    sum0 += __uint_as_float(e00) + __uint_as_float(e01);
    sum1 += __uint_as_float(e10) + __uint_as_float(e11);
    *(uint2*)&pS[r0*132 + j0] = make_uint2(e00, e01);
    *(uint2*)&pS[r1*132 + j0] = make_uint2(e10, e11);
  }
  sum0 += __shfl_xor_sync(0xffffffffu, sum0, 1);
  sum0 += __shfl_xor_sync(0xffffffffu, sum0, 2);
  sum1 += __shfl_xor_sync(0xffffffffu, sum1, 1);
  sum1 += __shfl_xor_sync(0xffffffffu, sum1, 2);
  if (l4 == 0) {
    g_lse[bh*ITEMS + c*64 + r0] = m0 + __logf(sum0);
    g_lse[bh*ITEMS + c*64 + r1] = m1 + __logf(sum1);
  }
  __syncthreads();

  float o[4][4];
  #pragma unroll
  for (int nt = 0; nt < 4; nt++)
    #pragma unroll
    for (int p = 0; p < 4; p++) o[nt][p] = 0.f;
  #pragma unroll
  for (int k8 = 0; k8 < 128; k8 += 8) {
    uint32_t afr[4];
    afr[0] = pS[(mb + g    )*132 + k8 + l4];
    afr[1] = pS[(mb + g + 8)*132 + k8 + l4];
    afr[2] = pS[(mb + g    )*132 + k8 + l4 + 4];
    afr[3] = pS[(mb + g + 8)*132 + k8 + l4 + 4];
    #pragma unroll
    for (int nt = 0; nt < 4; nt++) {
      uint32_t bfr[2];
      bfr[0] = vS[(k8 + l4    )*36 + nt*8 + g];
      bfr[1] = vS[(k8 + l4 + 4)*36 + nt*8 + g];
      mma_tf32(o[nt], afr, bfr);
    }
  }
  float inv0 = 1.f / sum0, inv1 = 1.f / sum1;
  float* outp = g_so + ((long)bh*ITEMS + (long)c*64)*DHEAD;
  #pragma unroll
  for (int nt = 0; nt < 4; nt++) {
    int d0 = nt*8 + 2*l4;
    *(float2*)&outp[r0*DHEAD + d0] = make_float2(o[nt][0]*inv0, o[nt][1]*inv0);
    *(float2*)&outp[r1*DHEAD + d0] = make_float2(o[nt][2]*inv1, o[nt][3]*inv1);
  }
}

// ---------------- cross-hash combine ----------------
__global__ void combine_kernel() {
  int tid = threadIdx.x;
  int lane = tid & 31;
  long gw = (long)blockIdx.x * 4 + (tid >> 5);
  int bh = (int)(gw >> 12);
  int t  = (int)(gw & (TLEN - 1));
  float lse[NHASH], val[NHASH];
  int pidx[NHASH];
  #pragma unroll
  for (int h = 0; h < NHASH; h++) {
    pidx[h] = g_pos[(bh*NHASH + h)*TLEN + t];
    lse[h]  = g_lse[bh*ITEMS + pidx[h]];
    val[h]  = g_so[((long)bh*ITEMS + pidx[h])*DHEAD + lane];
  }
  float m = lse[0];
  #pragma unroll
  for (int h = 1; h < NHASH; h++) m = fmaxf(m, lse[h]);
  float acc = 0.f, wsum = 0.f;
  #pragma unroll
  for (int h = 0; h < NHASH; h++) {
    float w = __expf(lse[h] - m);
    acc += w * val[h]; wsum += w;
  }
  int b = bh >> 2, head = bh & 3;
  g_attn[((long)b*TLEN + t)*DMODEL + head*DHEAD + lane] = acc / wsum;
}

// ---------------- layernorm (final only) ----------------
__global__ void ln_kernel(const float* __restrict__ in, float* __restrict__ out,
                          const float* __restrict__ g, const float* __restrict__ bb) {
  int row = blockIdx.x, d = threadIdx.x;
  __shared__ float red[4];
  float x = in[(long)row*DMODEL + d];
  float s = x;
  #pragma unroll
  for (int off = 16; off; off >>= 1) s += __shfl_xor_sync(0xffffffffu, s, off);
  if ((d & 31) == 0) red[d >> 5] = s;
  __syncthreads();
  float mean = (red[0]+red[1]+red[2]+red[3]) * (1.f/DMODEL);
  float dv = x - mean;
  float s2 = dv*dv;
  #pragma unroll
  for (int off = 16; off; off >>= 1) s2 += __shfl_xor_sync(0xffffffffu, s2, off);
  __syncthreads();
  if ((d & 31) == 0) red[d >> 5] = s2;
  __syncthreads();
  float var = (red[0]+red[1]+red[2]+red[3]) * (1.f/DMODEL);
  out[(long)row*DMODEL + d] = dv * rsqrtf(var + 1e-5f) * g[d] + bb[d];
}

// ---------------- final head ----------------
__global__ void head_kernel(const float* __restrict__ projw, const float* __restrict__ projb,
                            const float* __restrict__ fcw, const float* __restrict__ fcb,
                            float* __restrict__ dout) {
  int b = blockIdx.x, tid = threadIdx.x;
  float lg0 = 0.f, lg1 = 0.f, lg2 = 0.f;
  for (int tt = tid; tt < PRED; tt += 128) {
    const float* hh = g_res + ((long)b*TLEN + SENC + tt)*DMODEL;
    float o4[4];
    #pragma unroll
    for (int cc = 0; cc < 4; cc++) {
      float a = projb[cc];
      #pragma unroll 8
      for (int d = 0; d < DMODEL; d++) a += hh[d]*projw[d*4 + cc];
      o4[cc] = a;
    }
    #pragma unroll
    for (int cc = 0; cc < 4; cc++) {
      int idx = (tt*4 + cc)*3;
      lg0 += o4[cc]*fcw[idx+0];
      lg1 += o4[cc]*fcw[idx+1];
      lg2 += o4[cc]*fcw[idx+2];
    }
  }
  __shared__ float red[3][128];
  red[0][tid] = lg0; red[1][tid] = lg1; red[2][tid] = lg2;
  __syncthreads();
  for (int off = 64; off; off >>= 1) {
    if (tid < off) {
      red[0][tid] += red[0][tid+off];
      red[1][tid] += red[1][tid+off];
      red[2][tid] += red[2][tid+off];
    }
    __syncthreads();
  }
  if (tid == 0) {
    float l0 = red[0][0]+fcb[0], l1 = red[1][0]+fcb[1], l2 = red[2][0]+fcb[2];
    float mx = fmaxf(l0, fmaxf(l1, l2));
    float e0 = expf(l0-mx), e1 = expf(l1-mx), e2 = expf(l2-mx);
    float is = 1.f/(e0+e1+e2);
    dout[b*3+0] = e0*is; dout[b*3+1] = e1*is; dout[b*3+2] = e2*is;
  }
}

// ---------------- host launch ----------------
extern "C" void kernel_launch(void* const* d_in, const int* in_sizes, int n_in,
                              void* d_out, int out_size) {
  const float* x_enc      = (const float*)d_in[0];
  const float* x_mark_enc = (const float*)d_in[1];
  const float* x_dec      = (const float*)d_in[2];
  const float* x_mark_dec = (const float*)d_in[3];
  const float* conv_w     = (const float*)d_in[4];
  const float* timef_w    = (const float*)d_in[5];
  const float* Wqk        = (const float*)d_in[6];
  const float* Wv         = (const float*)d_in[7];
  const float* Wo         = (const float*)d_in[8];
  const float* bo         = (const float*)d_in[9];
  const float* rot        = (const float*)d_in[10];
  const float* ln1_g      = (const float*)d_in[11];
  const float* ln1_b      = (const float*)d_in[12];
  const float* ln2_g      = (const float*)d_in[13];
  const float* ln2_b      = (const float*)d_in[14];
  const float* w1         = (const float*)d_in[15];
  const float* b1         = (const float*)d_in[16];
  const float* w2         = (const float*)d_in[17];
  const float* b2         = (const float*)d_in[18];
  const float* lnf_g      = (const float*)d_in[19];
  const float* lnf_b      = (const float*)d_in[20];
  const float* proj_w     = (const float*)d_in[21];
  const float* proj_b     = (const float*)d_in[22];
  const float* fc1_w      = (const float*)d_in[23];
  const float* fc1_b      = (const float*)d_in[24];
  (void)in_sizes; (void)n_in; (void)out_size;

  void* p;
  cudaGetSymbolAddress(&p, g_h);    float* ph    = (float*)p;
  cudaGetSymbolAddress(&p, g_res);  float* pres  = (float*)p;
  cudaGetSymbolAddress(&p, g_ff);   float* pff   = (float*)p;
  cudaGetSymbolAddress(&p, g_qk);   float* pqk   = (float*)p;
  cudaGetSymbolAddress(&p, g_v);    float* pv    = (float*)p;
  cudaGetSymbolAddress(&p, g_attn); float* pattn = (float*)p;

  const int attn_smem = ATTN_SMEM_WORDS * 4;
  cudaFuncSetAttribute(attn_kernel, cudaFuncAttributeMaxDynamicSharedMemorySize, attn_smem);

  embed_kernel<<<MROWS, 128>>>(x_enc, x_mark_enc, x_dec, x_mark_dec, conv_w, timef_w);

  for (int l = 0; l < NLAYERS; l++) {
    const float* Wqk_l = Wqk + (long)l*DMODEL*DMODEL;
    const float* Wv_l  = Wv  + (long)l*DMODEL*DMODEL;
    const float* Wo_l  = Wo  + (long)l*DMODEL*DMODEL;
    const float* bo_l  = bo  + l*DMODEL;
    const float* rot_l = rot + (long)l*DHEAD*NHASH*(NBUCK/2);
    const float* w1_l  = w1 + (long)l*DMODEL*DFF;
    const float* b1_l  = b1 + l*DFF;
    const float* w2_l  = w2 + (long)l*DFF*DMODEL;
    const float* b2_l  = b2 + l*DMODEL;

    // qk projection: error-corrected tf32x3 (~fp32 accuracy, tensor pipe)
    gemm_qk_tf32x3<<<dim3(1,256), 256>>>(ph, Wqk_l, pqk, MROWS, DMODEL, DMODEL);
    gemm_tf32<0,1><<<dim3(1,256), 256>>>(ph, Wv_l, nullptr, nullptr, nullptr, nullptr, pv, MROWS, DMODEL, DMODEL);

    rot_argmax_kernel<<<BHN*TLEN/ROT_ROWS, 128>>>(rot_l);

    hist_kernel<<<BHN, 256>>>();
    place_kernel<<<BHN*NHASH, 1024>>>();

    attn_kernel<<<BHN*NCHUNK, 128, attn_smem>>>();
    combine_kernel<<<BHN*TLEN/4, 128>>>();

    gemm_tf32<1,0><<<dim3(1,256), 256>>>(pattn, Wo_l, bo_l, ph, ln1_g + l*DMODEL, ln1_b + l*DMODEL,
                                         ph, MROWS, DMODEL, DMODEL);
    gemm_tf32<3,0><<<dim3(4,256), 256>>>(ph, w1_l, b1_l, nullptr, nullptr, nullptr, pff, MROWS, DFF, DMODEL);
    gemm_tf32<1,0><<<dim3(1,256), 256>>>(pff, w2_l, b2_l, ph, ln2_g + l*DMODEL, ln2_b + l*DMODEL,
                                         ph, MROWS, DMODEL, DFF);
  }

  ln_kernel<<<MROWS, 128>>>(ph, pres, lnf_g, lnf_b);
  head_kernel<<<BSZ, 128>>>(proj_w, proj_b, fc1_w, fc1_b, (float*)d_out);
}

// round 9
// speedup vs baseline: 4.1536x; 1.0447x over previous
#include <cuda_runtime.h>
#include <math.h>
#include <stdint.h>

// ---------------- problem constants ----------------
#define BSZ     8
#define SENC    3072
#define PRED    1024
#define ENCIN   40
#define DMODEL  128
#define NHEADS  4
#define DHEAD   32
#define NHASH   4
#define NBUCK   64
#define BUCKETSZ 64
#define NLAYERS 2
#define DFF     512
#define COUT    4
#define NCLASS  3
#define MARK    4
#define TLEN    4096
#define BHN     (BSZ*NHEADS)          // 32
#define MROWS   (BSZ*TLEN)            // 32768
#define NCHUNK  (NHASH*TLEN/BUCKETSZ) // 256
#define ITEMS   (NHASH*TLEN)          // 16384 per bh
#define ATTN_SCALE 0.17677669529663689f

// ---------------- scratch ----------------
__device__ float g_h[MROWS*DMODEL];
__device__ float g_res[MROWS*DMODEL];
__device__ float g_ff[MROWS*DFF];
__device__ float g_qk[BHN*TLEN*DHEAD];
__device__ float g_v[BHN*TLEN*DHEAD];
__device__ float g_so[(long)BHN*ITEMS*DHEAD];
__device__ float g_lse[BHN*ITEMS];
__device__ int   g_st[BHN*ITEMS];
__device__ int   g_pos[BHN*ITEMS];
__device__ unsigned char g_bkt[BHN*ITEMS];
__device__ int   g_base[BHN*256];
__device__ float g_attn[MROWS*DMODEL];

// ---------------- tf32 helpers ----------------
__device__ __forceinline__ uint32_t f2tf(float x) {
  uint32_t u; asm("cvt.rna.tf32.f32 %0, %1;" : "=r"(u) : "f"(x)); return u;
}
__device__ __forceinline__ void split_tf(float x, uint32_t& hi, uint32_t& lo) {
  hi = f2tf(x);
  lo = f2tf(x - __uint_as_float(hi));
}
__device__ __forceinline__ void mma_tf32(float* c, const uint32_t* a, const uint32_t* b) {
  asm volatile(
    "mma.sync.aligned.m16n8k8.row.col.f32.tf32.tf32.f32 "
    "{%0,%1,%2,%3}, {%4,%5,%6,%7}, {%8,%9}, {%0,%1,%2,%3};\n"
    : "+f"(c[0]), "+f"(c[1]), "+f"(c[2]), "+f"(c[3])
    : "r"(a[0]), "r"(a[1]), "r"(a[2]), "r"(a[3]), "r"(b[0]), "r"(b[1]));
}

// ---------------- embedding ----------------
__global__ void embed_kernel(const float* __restrict__ xe, const float* __restrict__ xme,
                             const float* __restrict__ xd, const float* __restrict__ xmd,
                             const float* __restrict__ convw, const float* __restrict__ tw) {
  int bt = blockIdx.x; int b = bt / TLEN; int t = bt % TLEN;
  int d = threadIdx.x;
  __shared__ float sx[3][ENCIN];
  __shared__ float sm[MARK];
  for (int i = d; i < 3*ENCIN; i += 128) {
    int k = i / ENCIN, c = i % ENCIN;
    int tt = t - 1 + k; tt = (tt + TLEN) % TLEN;
    float v = (tt < SENC) ? xe[(b*SENC + tt)*ENCIN + c]
                          : xd[(b*PRED + (tt - SENC))*ENCIN + c];
    sx[k][c] = v;
  }
  if (d < MARK)
    sm[d] = (t < SENC) ? xme[(b*SENC + t)*MARK + d]
                       : xmd[(b*PRED + (t - SENC))*MARK + d];
  __syncthreads();
  float acc = 0.f;
  #pragma unroll
  for (int k = 0; k < 3; k++)
    #pragma unroll
    for (int c = 0; c < ENCIN; c++)
      acc += sx[k][c] * convw[(k*ENCIN + c)*DMODEL + d];
  #pragma unroll
  for (int m = 0; m < MARK; m++) acc += sm[m] * tw[m*DMODEL + d];
  int i2 = (d >> 1) * 2;
  float div = expf((float)i2 * (-logf(10000.f) / (float)DMODEL));
  float ang = (float)t * div;
  acc += (d & 1) ? cosf(ang) : sinf(ang);
  g_h[(bt)*DMODEL + d] = acc;
}

#define AS_STRIDE 20
#define BS_STRIDE 136

// ---------------- error-corrected TF32x3 GEMM (qk projection; ~fp32 accuracy) ----------------
__global__ void __launch_bounds__(256, 2) gemm_qk_tf32x3(
    const float* __restrict__ A, const float* __restrict__ B,
    float* __restrict__ C, int M, int N, int K) {
  __shared__ uint32_t Ash[128][AS_STRIDE];
  __shared__ uint32_t Asl[128][AS_STRIDE];
  __shared__ uint32_t Bsh[16][BS_STRIDE];
  __shared__ uint32_t Bsl[16][BS_STRIDE];
  int tid = threadIdx.x;
  int warp = tid >> 5, lane = tid & 31;
  int wm = warp >> 2, wn = warp & 3;
  int m_warp = wm * 64, n_warp = wn * 32;
  int g = lane >> 2, l4 = lane & 3;
  int bm = blockIdx.y * 128, bn = blockIdx.x * 128;

  int ar = tid >> 1, ac = (tid & 1) * 8;
  int bk = tid >> 5, bnn = (tid & 31) * 4;
  const float* Ap = A + (long)(bm + ar) * K + ac;
  const float* Bp = B + (long)bk * N + bn + bnn;

  float acc[4][4][4] = {};
  int ntiles = K >> 4;
  float4 fa0, fa1, fb0, fb1;
  fa0 = *(const float4*)(Ap);
  fa1 = *(const float4*)(Ap + 4);
  fb0 = *(const float4*)(Bp);
  fb1 = *(const float4*)(Bp + 8 * (long)N);
  for (int t = 0; t < ntiles; t++) {
    float av[8] = {fa0.x,fa0.y,fa0.z,fa0.w,fa1.x,fa1.y,fa1.z,fa1.w};
    #pragma unroll
    for (int i = 0; i < 8; i++) {
      uint32_t hi, lo; split_tf(av[i], hi, lo);
      Ash[ar][ac+i] = hi; Asl[ar][ac+i] = lo;
    }
    float bv0[4] = {fb0.x,fb0.y,fb0.z,fb0.w};
    float bv1[4] = {fb1.x,fb1.y,fb1.z,fb1.w};
    #pragma unroll
    for (int i = 0; i < 4; i++) {
      uint32_t hi, lo; split_tf(bv0[i], hi, lo);
      Bsh[bk][bnn+i] = hi; Bsl[bk][bnn+i] = lo;
      split_tf(bv1[i], hi, lo);
      Bsh[bk+8][bnn+i] = hi; Bsl[bk+8][bnn+i] = lo;
    }
    __syncthreads();
    if (t + 1 < ntiles) {
      fa0 = *(const float4*)(Ap + (t+1)*16);
      fa1 = *(const float4*)(Ap + (t+1)*16 + 4);
      fb0 = *(const float4*)(Bp + (long)((t+1)*16) * N);
      fb1 = *(const float4*)(Bp + (long)((t+1)*16 + 8) * N);
    }
    #pragma unroll
    for (int k8 = 0; k8 < 16; k8 += 8) {
      uint32_t ah[4][4], al[4][4], bh[4][2], bl[4][2];
      #pragma unroll
      for (int mf = 0; mf < 4; mf++) {
        int mr = m_warp + mf*16 + g;
        ah[mf][0] = Ash[mr    ][k8 + l4];
        ah[mf][1] = Ash[mr + 8][k8 + l4];
        ah[mf][2] = Ash[mr    ][k8 + l4 + 4];
        ah[mf][3] = Ash[mr + 8][k8 + l4 + 4];
        al[mf][0] = Asl[mr    ][k8 + l4];
        al[mf][1] = Asl[mr + 8][k8 + l4];
        al[mf][2] = Asl[mr    ][k8 + l4 + 4];
        al[mf][3] = Asl[mr + 8][k8 + l4 + 4];
      }
      #pragma unroll
      for (int nf = 0; nf < 4; nf++) {
        int nc = n_warp + nf*8 + g;
        bh[nf][0] = Bsh[k8 + l4    ][nc];
        bh[nf][1] = Bsh[k8 + l4 + 4][nc];
        bl[nf][0] = Bsl[k8 + l4    ][nc];
        bl[nf][1] = Bsl[k8 + l4 + 4][nc];
      }
      #pragma unroll
      for (int mf = 0; mf < 4; mf++)
        #pragma unroll
        for (int nf = 0; nf < 4; nf++) {
          mma_tf32(acc[mf][nf], al[mf], bh[nf]);
          mma_tf32(acc[mf][nf], ah[mf], bl[nf]);
          mma_tf32(acc[mf][nf], ah[mf], bh[nf]);
        }
    }
    __syncthreads();
  }
  #pragma unroll
  for (int mf = 0; mf < 4; mf++) {
    #pragma unroll
    for (int hf = 0; hf < 2; hf++) {
      int r = bm + m_warp + mf*16 + g + hf*8;
      #pragma unroll
      for (int nf = 0; nf < 4; nf++) {
        int c = bn + n_warp + nf*8 + 2*l4;
        float vx = acc[mf][nf][hf*2+0];
        float vy = acc[mf][nf][hf*2+1];
        int b = r / TLEN, t = r % TLEN;
        int hd = c >> 5, dh = c & 31;
        *(float2*)&C[(((long)b*NHEADS + hd)*TLEN + t)*DHEAD + dh] = make_float2(vx, vy);
      }
    }
  }
}

// ---------------- TF32 tensor-core GEMM 128x128 ----------------
// EPI: 0 none, 1 = +bias +residual +LayerNorm (N==128, grid.x==1, C may alias R), 3 = +bias +GELU
template<int EPI, int SPLIT>
__global__ void __launch_bounds__(256, 2) gemm_tf32(
    const float* __restrict__ A, const float* __restrict__ B,
    const float* __restrict__ bias, const float* __restrict__ R,
    const float* __restrict__ lng, const float* __restrict__ lnb,
    float* __restrict__ C, int M, int N, int K) {
  __shared__ uint32_t As[2][128][AS_STRIDE];
  __shared__ uint32_t Bs[2][16][BS_STRIDE];
  int tid = threadIdx.x;
  int warp = tid >> 5, lane = tid & 31;
  int wm = warp >> 2, wn = warp & 3;
  int m_warp = wm * 64, n_warp = wn * 32;
  int g = lane >> 2, l4 = lane & 3;
  int bm = blockIdx.y * 128, bn = blockIdx.x * 128;

  int ar = tid >> 1, ac = (tid & 1) * 8;
  int bk = tid >> 5, bnn = (tid & 31) * 4;
  const float* Ap = A + (long)(bm + ar) * K + ac;
  const float* Bp = B + (long)bk * N + bn + bnn;

  float acc[4][4][4] = {};
  int ntiles = K >> 4;
  float4 fa0, fa1, fb0, fb1;
  fa0 = *(const float4*)(Ap);
  fa1 = *(const float4*)(Ap + 4);
  fb0 = *(const float4*)(Bp);
  fb1 = *(const float4*)(Bp + 8 * (long)N);
  int buf = 0;
  for (int t = 0; t < ntiles; t++) {
    As[buf][ar][ac+0] = f2tf(fa0.x); As[buf][ar][ac+1] = f2tf(fa0.y);
    As[buf][ar][ac+2] = f2tf(fa0.z); As[buf][ar][ac+3] = f2tf(fa0.w);
    As[buf][ar][ac+4] = f2tf(fa1.x); As[buf][ar][ac+5] = f2tf(fa1.y);
    As[buf][ar][ac+6] = f2tf(fa1.z); As[buf][ar][ac+7] = f2tf(fa1.w);
    Bs[buf][bk][bnn+0] = f2tf(fb0.x); Bs[buf][bk][bnn+1] = f2tf(fb0.y);
    Bs[buf][bk][bnn+2] = f2tf(fb0.z); Bs[buf][bk][bnn+3] = f2tf(fb0.w);
    Bs[buf][bk+8][bnn+0] = f2tf(fb1.x); Bs[buf][bk+8][bnn+1] = f2tf(fb1.y);
    Bs[buf][bk+8][bnn+2] = f2tf(fb1.z); Bs[buf][bk+8][bnn+3] = f2tf(fb1.w);
    __syncthreads();
    if (t + 1 < ntiles) {
      fa0 = *(const float4*)(Ap + (t+1)*16);
      fa1 = *(const float4*)(Ap + (t+1)*16 + 4);
      fb0 = *(const float4*)(Bp + (long)((t+1)*16) * N);
      fb1 = *(const float4*)(Bp + (long)((t+1)*16 + 8) * N);
    }
    #pragma unroll
    for (int k8 = 0; k8 < 16; k8 += 8) {
      uint32_t afr[4][4], bfr[4][2];
      #pragma unroll
      for (int mf = 0; mf < 4; mf++) {
        int mr = m_warp + mf*16 + g;
        afr[mf][0] = As[buf][mr    ][k8 + l4];
        afr[mf][1] = As[buf][mr + 8][k8 + l4];
        afr[mf][2] = As[buf][mr    ][k8 + l4 + 4];
        afr[mf][3] = As[buf][mr + 8][k8 + l4 + 4];
      }
      #pragma unroll
      for (int nf = 0; nf < 4; nf++) {
        int nc = n_warp + nf*8 + g;
        bfr[nf][0] = Bs[buf][k8 + l4    ][nc];
        bfr[nf][1] = Bs[buf][k8 + l4 + 4][nc];
      }
      #pragma unroll
      for (int mf = 0; mf < 4; mf++)
        #pragma unroll
        for (int nf = 0; nf < 4; nf++)
          mma_tf32(acc[mf][nf], afr[mf], bfr[nf]);
    }
    buf ^= 1;
  }

  if (EPI == 1) {
    float* Ssum = (float*)As;
    float* Ssq  = ((float*)As) + 512;
    __syncthreads();
    float psum[4][2], psq[4][2];
    #pragma unroll
    for (int mf = 0; mf < 4; mf++) {
      #pragma unroll
      for (int hf = 0; hf < 2; hf++) {
        int r = bm + m_warp + mf*16 + g + hf*8;
        float s = 0.f, sq = 0.f;
        #pragma unroll
        for (int nf = 0; nf < 4; nf++) {
          int c = n_warp + nf*8 + 2*l4;
          #pragma unroll
          for (int p = 0; p < 2; p++) {
            float v = acc[mf][nf][hf*2+p] + bias[c+p] + R[(long)r*N + c + p];
            acc[mf][nf][hf*2+p] = v;
            s += v; sq += v*v;
          }
        }
        s  += __shfl_xor_sync(0xffffffffu, s, 1);
        s  += __shfl_xor_sync(0xffffffffu, s, 2);
        sq += __shfl_xor_sync(0xffffffffu, sq, 1);
        sq += __shfl_xor_sync(0xffffffffu, sq, 2);
        psum[mf][hf] = s; psq[mf][hf] = sq;
      }
    }
    if (l4 == 0) {
      #pragma unroll
      for (int mf = 0; mf < 4; mf++)
        #pragma unroll
        for (int hf = 0; hf < 2; hf++) {
          int rl = m_warp + mf*16 + g + hf*8;
          Ssum[rl*4 + wn] = psum[mf][hf];
          Ssq [rl*4 + wn] = psq[mf][hf];
        }
    }
    __syncthreads();
    #pragma unroll
    for (int mf = 0; mf < 4; mf++) {
      #pragma unroll
      for (int hf = 0; hf < 2; hf++) {
        int rl = m_warp + mf*16 + g + hf*8;
        int r = bm + rl;
        float s  = Ssum[rl*4+0] + Ssum[rl*4+1] + Ssum[rl*4+2] + Ssum[rl*4+3];
        float sq = Ssq [rl*4+0] + Ssq [rl*4+1] + Ssq [rl*4+2] + Ssq [rl*4+3];
        float mean = s * (1.f/128.f);
        float var = sq * (1.f/128.f) - mean*mean;
        float rstd = rsqrtf(var + 1e-5f);
        #pragma unroll
        for (int nf = 0; nf < 4; nf++) {
          int c = n_warp + nf*8 + 2*l4;
          float2 o;
          o.x = (acc[mf][nf][hf*2+0] - mean)*rstd*lng[c+0] + lnb[c+0];
          o.y = (acc[mf][nf][hf*2+1] - mean)*rstd*lng[c+1] + lnb[c+1];
          *(float2*)&C[(long)r*N + c] = o;
        }
      }
    }
  } else {
    #pragma unroll
    for (int mf = 0; mf < 4; mf++) {
      #pragma unroll
      for (int hf = 0; hf < 2; hf++) {
        int r = bm + m_warp + mf*16 + g + hf*8;
        #pragma unroll
        for (int nf = 0; nf < 4; nf++) {
          int c = bn + n_warp + nf*8 + 2*l4;
          float vx = acc[mf][nf][hf*2+0];
          float vy = acc[mf][nf][hf*2+1];
          if (EPI == 3) {
            vx += bias[c+0]; vy += bias[c+1];
            vx = 0.5f*vx*(1.f + erff(vx*0.70710678118f));
            vy = 0.5f*vy*(1.f + erff(vy*0.70710678118f));
          }
          if (SPLIT) {
            int b = r / TLEN, t = r % TLEN;
            int hd = c >> 5, dh = c & 31;
            *(float2*)&C[(((long)b*NHEADS + hd)*TLEN + t)*DHEAD + dh] = make_float2(vx, vy);
          } else {
            *(float2*)&C[(long)r*N + c] = make_float2(vx, vy);
          }
        }
      }
    }
  }
}

// ---------------- fused rotation + argmax: REDUX-based ----------------
#define ROT_ROWS 64
__global__ void __launch_bounds__(128) rot_argmax_kernel(const float* __restrict__ rot_l) {
  __shared__ __align__(16) float qT[32][ROT_ROWS + 4];   // [d][row]
  int tid = threadIdx.x, lane = tid & 31, h = tid >> 5;
  long row0 = (long)blockIdx.x * ROT_ROWS;   // in bh*TLEN + t space
  int bh = (int)(row0 >> 12);
  int t0 = (int)(row0 & (TLEN - 1));

  float rcol[32];
  #pragma unroll
  for (int d = 0; d < 32; d++) rcol[d] = rot_l[d*128 + tid];

  {
    int r = tid >> 1;
    int half = (tid & 1) * 16;
    const float* gq = g_qk + (row0 + r)*DHEAD + half;
    #pragma unroll
    for (int f = 0; f < 4; f++) {
      float4 v = *(const float4*)(gq + f*4);
      qT[half + f*4 + 0][r] = v.x; qT[half + f*4 + 1][r] = v.y;
      qT[half + f*4 + 2][r] = v.z; qT[half + f*4 + 3][r] = v.w;
    }
  }
  __syncthreads();

  unsigned char* bp = g_bkt + (bh*NHASH + h)*TLEN + t0;
  #pragma unroll 4
  for (int rg = 0; rg < ROT_ROWS/4; rg++) {
    float a0 = 0.f, a1 = 0.f, a2 = 0.f, a3 = 0.f;
    #pragma unroll
    for (int d = 0; d < 32; d++) {
      float4 q4 = *(const float4*)&qT[d][rg*4];
      float r = rcol[d];
      a0 += q4.x * r; a1 += q4.y * r; a2 += q4.z * r; a3 += q4.w * r;
    }
    #pragma unroll
    for (int rr = 0; rr < 4; rr++) {
      float v = (rr == 0) ? a0 : (rr == 1) ? a1 : (rr == 2) ? a2 : a3;
      uint32_t key = __float_as_uint(fabsf(v));
      uint32_t mx = __reduce_max_sync(0xffffffffu, key);
      bool eq = (key == mx);
      bool pos = (v >= -v);
      unsigned bpos = __ballot_sync(0xffffffffu, eq && pos);
      unsigned bneg = __ballot_sync(0xffffffffu, eq && !pos);
      int bucket = bpos ? (__ffs(bpos) - 1) : (__ffs(bneg) + 31);
      if (lane == 0) bp[rg*4 + rr] = (unsigned char)bucket;
    }
  }
}

// ---------------- counting sort ----------------
__global__ void hist_kernel() {
  __shared__ int cnt[256];
  int bh = blockIdx.x, tid = threadIdx.x;
  cnt[tid] = 0; __syncthreads();
  const unsigned char* bp = g_bkt + bh*ITEMS;
  for (int i = tid; i < ITEMS; i += 256) {
    int gb = ((i >> 12) << 6) + bp[i];
    atomicAdd(&cnt[gb], 1);
  }
  __syncthreads();
  if (tid == 0) {
    int s = 0;
    #pragma unroll 8
    for (int j = 0; j < 256; j++) { g_base[bh*256 + j] = s; s += cnt[j]; }
  }
}

__global__ void __launch_bounds__(1024) place_kernel() {
  int bhh = blockIdx.x;
  int bh = bhh >> 2, h = bhh & 3;
  int warp = threadIdx.x >> 5, lane = threadIdx.x & 31;
  const unsigned char* bp = g_bkt + (bh*NHASH + h)*TLEN;
  #pragma unroll
  for (int s = 0; s < 2; s++) {
    int lb = warp*2 + s;
    int base = g_base[bh*256 + h*64 + lb];
    for (int t0 = 0; t0 < TLEN; t0 += 32) {
      int my = bp[t0 + lane];
      unsigned mask = __ballot_sync(0xffffffffu, my == lb);
      if (my == lb) {
        int p = base + __popc(mask & ((1u << lane) - 1u));
        g_st[bh*ITEMS + p] = t0 + lane;
        g_pos[(bh*NHASH + h)*TLEN + t0 + lane] = p;
      }
      base += __popc(mask);
    }
  }
}

// ---------------- tensor-core LSH attention (smem-compacted, 4 CTAs/SM) ----------------
// dyn smem (uint32 words):
//   region A @0, 8448 words: phase1 = qS[64][36] (0..2304) + kTd[32][136] (2304..6656)
//                             phase2 = pS[64][132] (aliases region A; per-warp rows only)
//   vS [128][40] @ 8448 (5120 words, stride 40 -> conflict-free PV B loads)
//   sQt[64] @ 13568, sKt[128] @ 13632
#define ATTN_SMEM_WORDS 13760
__global__ void __launch_bounds__(128, 4) attn_kernel() {
  extern __shared__ __align__(16) uint32_t smw[];
  uint32_t* qS  = smw;
  uint32_t* kTd = smw + 2304;
  uint32_t* pS  = smw;          // aliases qS/kTd after phase-1 sync
  uint32_t* vS  = smw + 8448;
  int* sQt = (int*)(smw + 13568);
  int* sKt = (int*)(smw + 13632);

  int bh = blockIdx.x >> 8;
  int c  = blockIdx.x & 255;
  int pc = (c + 255) & 255;
  int tid = threadIdx.x;
  int lane = tid & 31, warp = tid >> 5;
  int g = lane >> 2, l4 = lane & 3;

  {
    int p = (tid < 64) ? (c*64 + tid) : (pc*64 + (tid - 64));
    sKt[tid] = g_st[bh*ITEMS + p];
    if (tid < 64) sQt[tid] = sKt[tid];
  }
  __syncthreads();

  {
    int j = tid;
    int t = sKt[j];
    const float* gk = g_qk + ((long)bh*TLEN + t)*DHEAD;
    const float* gv = g_v  + ((long)bh*TLEN + t)*DHEAD;
    float4 kr[8];
    float ss = 0.f;
    #pragma unroll
    for (int f = 0; f < 8; f++) {
      kr[f] = *(const float4*)(gk + f*4);
      ss += kr[f].x*kr[f].x + kr[f].y*kr[f].y + kr[f].z*kr[f].z + kr[f].w*kr[f].w;
    }
    float inv = ATTN_SCALE / fmaxf(sqrtf(ss), 1e-12f);
    #pragma unroll
    for (int f = 0; f < 8; f++) {
      kTd[(f*4+0)*136 + j] = f2tf(kr[f].x * inv);
      kTd[(f*4+1)*136 + j] = f2tf(kr[f].y * inv);
      kTd[(f*4+2)*136 + j] = f2tf(kr[f].z * inv);
      kTd[(f*4+3)*136 + j] = f2tf(kr[f].w * inv);
    }
    #pragma unroll
    for (int f = 0; f < 8; f++) {
      float4 vv = *(const float4*)(gv + f*4);
      uint4 u;
      u.x = f2tf(vv.x); u.y = f2tf(vv.y); u.z = f2tf(vv.z); u.w = f2tf(vv.w);
      *(uint4*)&vS[j*40 + f*4] = u;
    }
  }
  if (tid < 64) {
    const float* gq = g_qk + ((long)bh*TLEN + sQt[tid])*DHEAD;
    #pragma unroll
    for (int f = 0; f < 8; f++) {
      float4 qq = *(const float4*)(gq + f*4);
      uint4 u;
      u.x = f2tf(qq.x); u.y = f2tf(qq.y); u.z = f2tf(qq.z); u.w = f2tf(qq.w);
      *(uint4*)&qS[tid*36 + f*4] = u;
    }
  }
  __syncthreads();

  // ---- phase 1: dots S = Q*K^T ----
  int mb = warp * 16;
  float s[16][4];
  #pragma unroll
  for (int nt = 0; nt < 16; nt++)
    #pragma unroll
    for (int p = 0; p < 4; p++) s[nt][p] = 0.f;
  #pragma unroll
  for (int k8 = 0; k8 < 32; k8 += 8) {
    uint32_t afr[4];
    afr[0] = qS[(mb + g    )*36 + k8 + l4];
    afr[1] = qS[(mb + g + 8)*36 + k8 + l4];
    afr[2] = qS[(mb + g    )*36 + k8 + l4 + 4];
    afr[3] = qS[(mb + g + 8)*36 + k8 + l4 + 4];
    #pragma unroll
    for (int nt = 0; nt < 16; nt++) {
      uint32_t bfr[2];
      bfr[0] = kTd[(k8 + l4    )*136 + nt*8 + g];
      bfr[1] = kTd[(k8 + l4 + 4)*136 + nt*8 + g];
      mma_tf32(s[nt], afr, bfr);
    }
  }
  __syncthreads();   // all phase-1 reads of qS/kTd done -> pS may alias them

  // ---- self-mask + softmax; write P (per-warp rows only) ----
  int r0 = mb + g, r1 = mb + g + 8;
  int qt0 = sQt[r0], qt1 = sQt[r1];
  float m0 = -1e30f, m1 = -1e30f;
  #pragma unroll
  for (int nt = 0; nt < 16; nt++) {
    int j0 = nt*8 + 2*l4;
    int kt0 = sKt[j0], kt1 = sKt[j0+1];
    if (kt0 == qt0) s[nt][0] = -5e4f;
    if (kt1 == qt0) s[nt][1] = -5e4f;
    if (kt0 == qt1) s[nt][2] = -5e4f;
    if (kt1 == qt1) s[nt][3] = -5e4f;
    m0 = fmaxf(m0, fmaxf(s[nt][0], s[nt][1]));
    m1 = fmaxf(m1, fmaxf(s[nt][2], s[nt][3]));
  }
  m0 = fmaxf(m0, __shfl_xor_sync(0xffffffffu, m0, 1));
  m0 = fmaxf(m0, __shfl_xor_sync(0xffffffffu, m0, 2));
  m1 = fmaxf(m1, __shfl_xor_sync(0xffffffffu, m1, 1));
  m1 = fmaxf(m1, __shfl_xor_sync(0xffffffffu, m1, 2));
  float sum0 = 0.f, sum1 = 0.f;
  #pragma unroll
  for (int nt = 0; nt < 16; nt++) {
    int j0 = nt*8 + 2*l4;
    uint32_t e00 = f2tf(__expf(s[nt][0] - m0));
    uint32_t e01 = f2tf(__expf(s[nt][1] - m0));
    uint32_t e10 = f2tf(__expf(s[nt][2] - m1));
    uint32_t e11 = f2tf(__expf(s[nt][3] - m1));
    sum0 += __uint_as_float(e00) + __uint_as_float(e01);
    sum1 += __uint_as_float(e10) + __uint_as_float(e11);
    *(uint2*)&pS[r0*132 + j0] = make_uint2(e00, e01);
    *(uint2*)&pS[r1*132 + j0] = make_uint2(e10, e11);
  }
  sum0 += __shfl_xor_sync(0xffffffffu, sum0, 1);
  sum0 += __shfl_xor_sync(0xffffffffu, sum0, 2);
  sum1 += __shfl_xor_sync(0xffffffffu, sum1, 1);
  sum1 += __shfl_xor_sync(0xffffffffu, sum1, 2);
  if (l4 == 0) {
    g_lse[bh*ITEMS + c*64 + r0] = m0 + __logf(sum0);
    g_lse[bh*ITEMS + c*64 + r1] = m1 + __logf(sum1);
  }
  __syncwarp();   // pS rows are per-warp; only warp-level visibility needed

  // ---- phase 2: PV ----
  float o[4][4];
  #pragma unroll
  for (int nt = 0; nt < 4; nt++)
    #pragma unroll
    for (int p = 0; p < 4; p++) o[nt][p] = 0.f;
  #pragma unroll
  for (int k8 = 0; k8 < 128; k8 += 8) {
    uint32_t afr[4];
    afr[0] = pS[(mb + g    )*132 + k8 + l4];
    afr[1] = pS[(mb + g + 8)*132 + k8 + l4];
    afr[2] = pS[(mb + g    )*132 + k8 + l4 + 4];
    afr[3] = pS[(mb + g + 8)*132 + k8 + l4 + 4];
    #pragma unroll
    for (int nt = 0; nt < 4; nt++) {
      uint32_t bfr[2];
      bfr[0] = vS[(k8 + l4    )*40 + nt*8 + g];
      bfr[1] = vS[(k8 + l4 + 4)*40 + nt*8 + g];
      mma_tf32(o[nt], afr, bfr);
    }
  }
  float inv0 = 1.f / sum0, inv1 = 1.f / sum1;
  float* outp = g_so + ((long)bh*ITEMS + (long)c*64)*DHEAD;
  #pragma unroll
  for (int nt = 0; nt < 4; nt++) {
    int d0 = nt*8 + 2*l4;
    *(float2*)&outp[r0*DHEAD + d0] = make_float2(o[nt][0]*inv0, o[nt][1]*inv0);
    *(float2*)&outp[r1*DHEAD + d0] = make_float2(o[nt][2]*inv1, o[nt][3]*inv1);
  }
}

// ---------------- cross-hash combine ----------------
__global__ void combine_kernel() {
  int tid = threadIdx.x;
  int lane = tid & 31;
  long gw = (long)blockIdx.x * 4 + (tid >> 5);
  int bh = (int)(gw >> 12);
  int t  = (int)(gw & (TLEN - 1));
  float lse[NHASH], val[NHASH];
  int pidx[NHASH];
  #pragma unroll
  for (int h = 0; h < NHASH; h++) {
    pidx[h] = g_pos[(bh*NHASH + h)*TLEN + t];
    lse[h]  = g_lse[bh*ITEMS + pidx[h]];
    val[h]  = g_so[((long)bh*ITEMS + pidx[h])*DHEAD + lane];
  }
  float m = lse[0];
  #pragma unroll
  for (int h = 1; h < NHASH; h++) m = fmaxf(m, lse[h]);
  float acc = 0.f, wsum = 0.f;
  #pragma unroll
  for (int h = 0; h < NHASH; h++) {
    float w = __expf(lse[h] - m);
    acc += w * val[h]; wsum += w;
  }
  int b = bh >> 2, head = bh & 3;
  g_attn[((long)b*TLEN + t)*DMODEL + head*DHEAD + lane] = acc / wsum;
}

// ---------------- layernorm (final only) ----------------
__global__ void ln_kernel(const float* __restrict__ in, float* __restrict__ out,
                          const float* __restrict__ g, const float* __restrict__ bb) {
  int row = blockIdx.x, d = threadIdx.x;
  __shared__ float red[4];
  float x = in[(long)row*DMODEL + d];
  float s = x;
  #pragma unroll
  for (int off = 16; off; off >>= 1) s += __shfl_xor_sync(0xffffffffu, s, off);
  if ((d & 31) == 0) red[d >> 5] = s;
  __syncthreads();
  float mean = (red[0]+red[1]+red[2]+red[3]) * (1.f/DMODEL);
  float dv = x - mean;
  float s2 = dv*dv;
  #pragma unroll
  for (int off = 16; off; off >>= 1) s2 += __shfl_xor_sync(0xffffffffu, s2, off);
  __syncthreads();
  if ((d & 31) == 0) red[d >> 5] = s2;
  __syncthreads();
  float var = (red[0]+red[1]+red[2]+red[3]) * (1.f/DMODEL);
  out[(long)row*DMODEL + d] = dv * rsqrtf(var + 1e-5f) * g[d] + bb[d];
}

// ---------------- final head ----------------
__global__ void head_kernel(const float* __restrict__ projw, const float* __restrict__ projb,
                            const float* __restrict__ fcw, const float* __restrict__ fcb,
                            float* __restrict__ dout) {
  int b = blockIdx.x, tid = threadIdx.x;
  float lg0 = 0.f, lg1 = 0.f, lg2 = 0.f;
  for (int tt = tid; tt < PRED; tt += 128) {
    const float* hh = g_res + ((long)b*TLEN + SENC + tt)*DMODEL;
    float o4[4];
    #pragma unroll
    for (int cc = 0; cc < 4; cc++) {
      float a = projb[cc];
      #pragma unroll 8
      for (int d = 0; d < DMODEL; d++) a += hh[d]*projw[d*4 + cc];
      o4[cc] = a;
    }
    #pragma unroll
    for (int cc = 0; cc < 4; cc++) {
      int idx = (tt*4 + cc)*3;
      lg0 += o4[cc]*fcw[idx+0];
      lg1 += o4[cc]*fcw[idx+1];
      lg2 += o4[cc]*fcw[idx+2];
    }
  }
  __shared__ float red[3][128];
  red[0][tid] = lg0; red[1][tid] = lg1; red[2][tid] = lg2;
  __syncthreads();
  for (int off = 64; off; off >>= 1) {
    if (tid < off) {
      red[0][tid] += red[0][tid+off];
      red[1][tid] += red[1][tid+off];
      red[2][tid] += red[2][tid+off];
    }
    __syncthreads();
  }
  if (tid == 0) {
    float l0 = red[0][0]+fcb[0], l1 = red[1][0]+fcb[1], l2 = red[2][0]+fcb[2];
    float mx = fmaxf(l0, fmaxf(l1, l2));
    float e0 = expf(l0-mx), e1 = expf(l1-mx), e2 = expf(l2-mx);
    float is = 1.f/(e0+e1+e2);
    dout[b*3+0] = e0*is; dout[b*3+1] = e1*is; dout[b*3+2] = e2*is;
  }
}

// ---------------- host launch ----------------
extern "C" void kernel_launch(void* const* d_in, const int* in_sizes, int n_in,
                              void* d_out, int out_size) {
  const float* x_enc      = (const float*)d_in[0];
  const float* x_mark_enc = (const float*)d_in[1];
  const float* x_dec      = (const float*)d_in[2];
  const float* x_mark_dec = (const float*)d_in[3];
  const float* conv_w     = (const float*)d_in[4];
  const float* timef_w    = (const float*)d_in[5];
  const float* Wqk        = (const float*)d_in[6];
  const float* Wv         = (const float*)d_in[7];
  const float* Wo         = (const float*)d_in[8];
  const float* bo         = (const float*)d_in[9];
  const float* rot        = (const float*)d_in[10];
  const float* ln1_g      = (const float*)d_in[11];
  const float* ln1_b      = (const float*)d_in[12];
  const float* ln2_g      = (const float*)d_in[13];
  const float* ln2_b      = (const float*)d_in[14];
  const float* w1         = (const float*)d_in[15];
  const float* b1         = (const float*)d_in[16];
  const float* w2         = (const float*)d_in[17];
  const float* b2         = (const float*)d_in[18];
  const float* lnf_g      = (const float*)d_in[19];
  const float* lnf_b      = (const float*)d_in[20];
  const float* proj_w     = (const float*)d_in[21];
  const float* proj_b     = (const float*)d_in[22];
  const float* fc1_w      = (const float*)d_in[23];
  const float* fc1_b      = (const float*)d_in[24];
  (void)in_sizes; (void)n_in; (void)out_size;

  void* p;
  cudaGetSymbolAddress(&p, g_h);    float* ph    = (float*)p;
  cudaGetSymbolAddress(&p, g_res);  float* pres  = (float*)p;
  cudaGetSymbolAddress(&p, g_ff);   float* pff   = (float*)p;
  cudaGetSymbolAddress(&p, g_qk);   float* pqk   = (float*)p;
  cudaGetSymbolAddress(&p, g_v);    float* pv    = (float*)p;
  cudaGetSymbolAddress(&p, g_attn); float* pattn = (float*)p;

  const int attn_smem = ATTN_SMEM_WORDS * 4;
  cudaFuncSetAttribute(attn_kernel, cudaFuncAttributeMaxDynamicSharedMemorySize, attn_smem);

  embed_kernel<<<MROWS, 128>>>(x_enc, x_mark_enc, x_dec, x_mark_dec, conv_w, timef_w);

  for (int l = 0; l < NLAYERS; l++) {
    const float* Wqk_l = Wqk + (long)l*DMODEL*DMODEL;
    const float* Wv_l  = Wv  + (long)l*DMODEL*DMODEL;
    const float* Wo_l  = Wo  + (long)l*DMODEL*DMODEL;
    const float* bo_l  = bo  + l*DMODEL;
    const float* rot_l = rot + (long)l*DHEAD*NHASH*(NBUCK/2);
    const float* w1_l  = w1 + (long)l*DMODEL*DFF;
    const float* b1_l  = b1 + l*DFF;
    const float* w2_l  = w2 + (long)l*DFF*DMODEL;
    const float* b2_l  = b2 + l*DMODEL;

    gemm_qk_tf32x3<<<dim3(1,256), 256>>>(ph, Wqk_l, pqk, MROWS, DMODEL, DMODEL);
    gemm_tf32<0,1><<<dim3(1,256), 256>>>(ph, Wv_l, nullptr, nullptr, nullptr, nullptr, pv, MROWS, DMODEL, DMODEL);

    rot_argmax_kernel<<<BHN*TLEN/ROT_ROWS, 128>>>(rot_l);

    hist_kernel<<<BHN, 256>>>();
    place_kernel<<<BHN*NHASH, 1024>>>();

    attn_kernel<<<BHN*NCHUNK, 128, attn_smem>>>();
    combine_kernel<<<BHN*TLEN/4, 128>>>();

    gemm_tf32<1,0><<<dim3(1,256), 256>>>(pattn, Wo_l, bo_l, ph, ln1_g + l*DMODEL, ln1_b + l*DMODEL,
                                         ph, MROWS, DMODEL, DMODEL);
    gemm_tf32<3,0><<<dim3(4,256), 256>>>(ph, w1_l, b1_l, nullptr, nullptr, nullptr, pff, MROWS, DFF, DMODEL);
    gemm_tf32<1,0><<<dim3(1,256), 256>>>(pff, w2_l, b2_l, ph, ln2_g + l*DMODEL, ln2_b + l*DMODEL,
                                         ph, MROWS, DMODEL, DFF);
  }

  ln_kernel<<<MROWS, 128>>>(ph, pres, lnf_g, lnf_b);
  head_kernel<<<BSZ, 128>>>(proj_w, proj_b, fc1_w, fc1_b, (float*)d_out);
}

// round 10
// speedup vs baseline: 4.3041x; 1.0362x over previous
#include <cuda_runtime.h>
#include <cuda_fp16.h>
#include <math.h>
#include <stdint.h>

// ---------------- problem constants ----------------
#define BSZ     8
#define SENC    3072
#define PRED    1024
#define ENCIN   40
#define DMODEL  128
#define NHEADS  4
#define DHEAD   32
#define NHASH   4
#define NBUCK   64
#define BUCKETSZ 64
#define NLAYERS 2
#define DFF     512
#define COUT    4
#define NCLASS  3
#define MARK    4
#define TLEN    4096
#define BHN     (BSZ*NHEADS)          // 32
#define MROWS   (BSZ*TLEN)            // 32768
#define NCHUNK  (NHASH*TLEN/BUCKETSZ) // 256
#define ITEMS   (NHASH*TLEN)          // 16384 per bh
#define ATTN_SCALE 0.17677669529663689f

// ---------------- scratch ----------------
__device__ float g_h[MROWS*DMODEL];
__device__ float g_res[MROWS*DMODEL];
__device__ float g_ff[MROWS*DFF];
__device__ float g_qk[BHN*TLEN*DHEAD];
__device__ float g_v[BHN*TLEN*DHEAD];
__device__ __half g_so16[(long)BHN*ITEMS*DHEAD];
__device__ float g_lse[BHN*ITEMS];
__device__ int   g_st[BHN*ITEMS];
__device__ int   g_pos[BHN*ITEMS];
__device__ unsigned char g_bkt[BHN*ITEMS];
__device__ int   g_base[BHN*256];
__device__ float g_attn[MROWS*DMODEL];

// ---------------- tf32 helpers ----------------
__device__ __forceinline__ uint32_t f2tf(float x) {
  uint32_t u; asm("cvt.rna.tf32.f32 %0, %1;" : "=r"(u) : "f"(x)); return u;
}
__device__ __forceinline__ void split_tf(float x, uint32_t& hi, uint32_t& lo) {
  hi = f2tf(x);
  lo = f2tf(x - __uint_as_float(hi));
}
__device__ __forceinline__ void mma_tf32(float* c, const uint32_t* a, const uint32_t* b) {
  asm volatile(
    "mma.sync.aligned.m16n8k8.row.col.f32.tf32.tf32.f32 "
    "{%0,%1,%2,%3}, {%4,%5,%6,%7}, {%8,%9}, {%0,%1,%2,%3};\n"
    : "+f"(c[0]), "+f"(c[1]), "+f"(c[2]), "+f"(c[3])
    : "r"(a[0]), "r"(a[1]), "r"(a[2]), "r"(a[3]), "r"(b[0]), "r"(b[1]));
}

// ---------------- embedding ----------------
__global__ void embed_kernel(const float* __restrict__ xe, const float* __restrict__ xme,
                             const float* __restrict__ xd, const float* __restrict__ xmd,
                             const float* __restrict__ convw, const float* __restrict__ tw) {
  int bt = blockIdx.x; int b = bt / TLEN; int t = bt % TLEN;
  int d = threadIdx.x;
  __shared__ float sx[3][ENCIN];
  __shared__ float sm[MARK];
  for (int i = d; i < 3*ENCIN; i += 128) {
    int k = i / ENCIN, c = i % ENCIN;
    int tt = t - 1 + k; tt = (tt + TLEN) % TLEN;
    float v = (tt < SENC) ? xe[(b*SENC + tt)*ENCIN + c]
                          : xd[(b*PRED + (tt - SENC))*ENCIN + c];
    sx[k][c] = v;
  }
  if (d < MARK)
    sm[d] = (t < SENC) ? xme[(b*SENC + t)*MARK + d]
                       : xmd[(b*PRED + (t - SENC))*MARK + d];
  __syncthreads();
  float acc = 0.f;
  #pragma unroll
  for (int k = 0; k < 3; k++)
    #pragma unroll
    for (int c = 0; c < ENCIN; c++)
      acc += sx[k][c] * convw[(k*ENCIN + c)*DMODEL + d];
  #pragma unroll
  for (int m = 0; m < MARK; m++) acc += sm[m] * tw[m*DMODEL + d];
  int i2 = (d >> 1) * 2;
  float div = expf((float)i2 * (-logf(10000.f) / (float)DMODEL));
  float ang = (float)t * div;
  acc += (d & 1) ? cosf(ang) : sinf(ang);
  g_h[(bt)*DMODEL + d] = acc;
}

#define AS_STRIDE 20
#define BS_STRIDE 136

// ---------------- error-corrected TF32x3 GEMM (qk projection; ~fp32 accuracy) ----------------
__global__ void __launch_bounds__(256, 2) gemm_qk_tf32x3(
    const float* __restrict__ A, const float* __restrict__ B,
    float* __restrict__ C, int M, int N, int K) {
  __shared__ uint32_t Ash[128][AS_STRIDE];
  __shared__ uint32_t Asl[128][AS_STRIDE];
  __shared__ uint32_t Bsh[16][BS_STRIDE];
  __shared__ uint32_t Bsl[16][BS_STRIDE];
  int tid = threadIdx.x;
  int warp = tid >> 5, lane = tid & 31;
  int wm = warp >> 2, wn = warp & 3;
  int m_warp = wm * 64, n_warp = wn * 32;
  int g = lane >> 2, l4 = lane & 3;
  int bm = blockIdx.y * 128, bn = blockIdx.x * 128;

  int ar = tid >> 1, ac = (tid & 1) * 8;
  int bk = tid >> 5, bnn = (tid & 31) * 4;
  const float* Ap = A + (long)(bm + ar) * K + ac;
  const float* Bp = B + (long)bk * N + bn + bnn;

  float acc[4][4][4] = {};
  int ntiles = K >> 4;
  float4 fa0, fa1, fb0, fb1;
  fa0 = *(const float4*)(Ap);
  fa1 = *(const float4*)(Ap + 4);
  fb0 = *(const float4*)(Bp);
  fb1 = *(const float4*)(Bp + 8 * (long)N);
  for (int t = 0; t < ntiles; t++) {
    float av[8] = {fa0.x,fa0.y,fa0.z,fa0.w,fa1.x,fa1.y,fa1.z,fa1.w};
    #pragma unroll
    for (int i = 0; i < 8; i++) {
      uint32_t hi, lo; split_tf(av[i], hi, lo);
      Ash[ar][ac+i] = hi; Asl[ar][ac+i] = lo;
    }
    float bv0[4] = {fb0.x,fb0.y,fb0.z,fb0.w};
    float bv1[4] = {fb1.x,fb1.y,fb1.z,fb1.w};
    #pragma unroll
    for (int i = 0; i < 4; i++) {
      uint32_t hi, lo; split_tf(bv0[i], hi, lo);
      Bsh[bk][bnn+i] = hi; Bsl[bk][bnn+i] = lo;
      split_tf(bv1[i], hi, lo);
      Bsh[bk+8][bnn+i] = hi; Bsl[bk+8][bnn+i] = lo;
    }
    __syncthreads();
    if (t + 1 < ntiles) {
      fa0 = *(const float4*)(Ap + (t+1)*16);
      fa1 = *(const float4*)(Ap + (t+1)*16 + 4);
      fb0 = *(const float4*)(Bp + (long)((t+1)*16) * N);
      fb1 = *(const float4*)(Bp + (long)((t+1)*16 + 8) * N);
    }
    #pragma unroll
    for (int k8 = 0; k8 < 16; k8 += 8) {
      uint32_t ah[4][4], al[4][4], bh[4][2], bl[4][2];
      #pragma unroll
      for (int mf = 0; mf < 4; mf++) {
        int mr = m_warp + mf*16 + g;
        ah[mf][0] = Ash[mr    ][k8 + l4];
        ah[mf][1] = Ash[mr + 8][k8 + l4];
        ah[mf][2] = Ash[mr    ][k8 + l4 + 4];
        ah[mf][3] = Ash[mr + 8][k8 + l4 + 4];
        al[mf][0] = Asl[mr    ][k8 + l4];
        al[mf][1] = Asl[mr + 8][k8 + l4];
        al[mf][2] = Asl[mr    ][k8 + l4 + 4];
        al[mf][3] = Asl[mr + 8][k8 + l4 + 4];
      }
      #pragma unroll
      for (int nf = 0; nf < 4; nf++) {
        int nc = n_warp + nf*8 + g;
        bh[nf][0] = Bsh[k8 + l4    ][nc];
        bh[nf][1] = Bsh[k8 + l4 + 4][nc];
        bl[nf][0] = Bsl[k8 + l4    ][nc];
        bl[nf][1] = Bsl[k8 + l4 + 4][nc];
      }
      #pragma unroll
      for (int mf = 0; mf < 4; mf++)
        #pragma unroll
        for (int nf = 0; nf < 4; nf++) {
          mma_tf32(acc[mf][nf], al[mf], bh[nf]);
          mma_tf32(acc[mf][nf], ah[mf], bl[nf]);
          mma_tf32(acc[mf][nf], ah[mf], bh[nf]);
        }
    }
    __syncthreads();
  }
  #pragma unroll
  for (int mf = 0; mf < 4; mf++) {
    #pragma unroll
    for (int hf = 0; hf < 2; hf++) {
      int r = bm + m_warp + mf*16 + g + hf*8;
      #pragma unroll
      for (int nf = 0; nf < 4; nf++) {
        int c = bn + n_warp + nf*8 + 2*l4;
        float vx = acc[mf][nf][hf*2+0];
        float vy = acc[mf][nf][hf*2+1];
        int b = r / TLEN, t = r % TLEN;
        int hd = c >> 5, dh = c & 31;
        *(float2*)&C[(((long)b*NHEADS + hd)*TLEN + t)*DHEAD + dh] = make_float2(vx, vy);
      }
    }
  }
}

// ---------------- TF32 tensor-core GEMM 128x128 ----------------
// EPI: 0 none, 1 = +bias +residual +LayerNorm (N==128, grid.x==1, C may alias R), 3 = +bias +GELU
template<int EPI, int SPLIT>
__global__ void __launch_bounds__(256, 2) gemm_tf32(
    const float* __restrict__ A, const float* __restrict__ B,
    const float* __restrict__ bias, const float* __restrict__ R,
    const float* __restrict__ lng, const float* __restrict__ lnb,
    float* __restrict__ C, int M, int N, int K) {
  __shared__ uint32_t As[2][128][AS_STRIDE];
  __shared__ uint32_t Bs[2][16][BS_STRIDE];
  int tid = threadIdx.x;
  int warp = tid >> 5, lane = tid & 31;
  int wm = warp >> 2, wn = warp & 3;
  int m_warp = wm * 64, n_warp = wn * 32;
  int g = lane >> 2, l4 = lane & 3;
  int bm = blockIdx.y * 128, bn = blockIdx.x * 128;

  int ar = tid >> 1, ac = (tid & 1) * 8;
  int bk = tid >> 5, bnn = (tid & 31) * 4;
  const float* Ap = A + (long)(bm + ar) * K + ac;
  const float* Bp = B + (long)bk * N + bn + bnn;

  float acc[4][4][4] = {};
  int ntiles = K >> 4;
  float4 fa0, fa1, fb0, fb1;
  fa0 = *(const float4*)(Ap);
  fa1 = *(const float4*)(Ap + 4);
  fb0 = *(const float4*)(Bp);
  fb1 = *(const float4*)(Bp + 8 * (long)N);
  int buf = 0;
  for (int t = 0; t < ntiles; t++) {
    As[buf][ar][ac+0] = f2tf(fa0.x); As[buf][ar][ac+1] = f2tf(fa0.y);
    As[buf][ar][ac+2] = f2tf(fa0.z); As[buf][ar][ac+3] = f2tf(fa0.w);
    As[buf][ar][ac+4] = f2tf(fa1.x); As[buf][ar][ac+5] = f2tf(fa1.y);
    As[buf][ar][ac+6] = f2tf(fa1.z); As[buf][ar][ac+7] = f2tf(fa1.w);
    Bs[buf][bk][bnn+0] = f2tf(fb0.x); Bs[buf][bk][bnn+1] = f2tf(fb0.y);
    Bs[buf][bk][bnn+2] = f2tf(fb0.z); Bs[buf][bk][bnn+3] = f2tf(fb0.w);
    Bs[buf][bk+8][bnn+0] = f2tf(fb1.x); Bs[buf][bk+8][bnn+1] = f2tf(fb1.y);
    Bs[buf][bk+8][bnn+2] = f2tf(fb1.z); Bs[buf][bk+8][bnn+3] = f2tf(fb1.w);
    __syncthreads();
    if (t + 1 < ntiles) {
      fa0 = *(const float4*)(Ap + (t+1)*16);
      fa1 = *(const float4*)(Ap + (t+1)*16 + 4);
      fb0 = *(const float4*)(Bp + (long)((t+1)*16) * N);
      fb1 = *(const float4*)(Bp + (long)((t+1)*16 + 8) * N);
    }
    #pragma unroll
    for (int k8 = 0; k8 < 16; k8 += 8) {
      uint32_t afr[4][4], bfr[4][2];
      #pragma unroll
      for (int mf = 0; mf < 4; mf++) {
        int mr = m_warp + mf*16 + g;
        afr[mf][0] = As[buf][mr    ][k8 + l4];
        afr[mf][1] = As[buf][mr + 8][k8 + l4];
        afr[mf][2] = As[buf][mr    ][k8 + l4 + 4];
        afr[mf][3] = As[buf][mr + 8][k8 + l4 + 4];
      }
      #pragma unroll
      for (int nf = 0; nf < 4; nf++) {
        int nc = n_warp + nf*8 + g;
        bfr[nf][0] = Bs[buf][k8 + l4    ][nc];
        bfr[nf][1] = Bs[buf][k8 + l4 + 4][nc];
      }
      #pragma unroll
      for (int mf = 0; mf < 4; mf++)
        #pragma unroll
        for (int nf = 0; nf < 4; nf++)
          mma_tf32(acc[mf][nf], afr[mf], bfr[nf]);
    }
    buf ^= 1;
  }

  if (EPI == 1) {
    float* Ssum = (float*)As;
    float* Ssq  = ((float*)As) + 512;
    __syncthreads();
    float psum[4][2], psq[4][2];
    #pragma unroll
    for (int mf = 0; mf < 4; mf++) {
      #pragma unroll
      for (int hf = 0; hf < 2; hf++) {
        int r = bm + m_warp + mf*16 + g + hf*8;
        float s = 0.f, sq = 0.f;
        #pragma unroll
        for (int nf = 0; nf < 4; nf++) {
          int c = n_warp + nf*8 + 2*l4;
          #pragma unroll
          for (int p = 0; p < 2; p++) {
            float v = acc[mf][nf][hf*2+p] + bias[c+p] + R[(long)r*N + c + p];
            acc[mf][nf][hf*2+p] = v;
            s += v; sq += v*v;
          }
        }
        s  += __shfl_xor_sync(0xffffffffu, s, 1);
        s  += __shfl_xor_sync(0xffffffffu, s, 2);
        sq += __shfl_xor_sync(0xffffffffu, sq, 1);
        sq += __shfl_xor_sync(0xffffffffu, sq, 2);
        psum[mf][hf] = s; psq[mf][hf] = sq;
      }
    }
    if (l4 == 0) {
      #pragma unroll
      for (int mf = 0; mf < 4; mf++)
        #pragma unroll
        for (int hf = 0; hf < 2; hf++) {
          int rl = m_warp + mf*16 + g + hf*8;
          Ssum[rl*4 + wn] = psum[mf][hf];
          Ssq [rl*4 + wn] = psq[mf][hf];
        }
    }
    __syncthreads();
    #pragma unroll
    for (int mf = 0; mf < 4; mf++) {
      #pragma unroll
      for (int hf = 0; hf < 2; hf++) {
        int rl = m_warp + mf*16 + g + hf*8;
        int r = bm + rl;
        float s  = Ssum[rl*4+0] + Ssum[rl*4+1] + Ssum[rl*4+2] + Ssum[rl*4+3];
        float sq = Ssq [rl*4+0] + Ssq [rl*4+1] + Ssq [rl*4+2] + Ssq [rl*4+3];
        float mean = s * (1.f/128.f);
        float var = sq * (1.f/128.f) - mean*mean;
        float rstd = rsqrtf(var + 1e-5f);
        #pragma unroll
        for (int nf = 0; nf < 4; nf++) {
          int c = n_warp + nf*8 + 2*l4;
          float2 o;
          o.x = (acc[mf][nf][hf*2+0] - mean)*rstd*lng[c+0] + lnb[c+0];
          o.y = (acc[mf][nf][hf*2+1] - mean)*rstd*lng[c+1] + lnb[c+1];
          *(float2*)&C[(long)r*N + c] = o;
        }
      }
    }
  } else {
    #pragma unroll
    for (int mf = 0; mf < 4; mf++) {
      #pragma unroll
      for (int hf = 0; hf < 2; hf++) {
        int r = bm + m_warp + mf*16 + g + hf*8;
        #pragma unroll
        for (int nf = 0; nf < 4; nf++) {
          int c = bn + n_warp + nf*8 + 2*l4;
          float vx = acc[mf][nf][hf*2+0];
          float vy = acc[mf][nf][hf*2+1];
          if (EPI == 3) {
            vx += bias[c+0]; vy += bias[c+1];
            vx = 0.5f*vx*(1.f + erff(vx*0.70710678118f));
            vy = 0.5f*vy*(1.f + erff(vy*0.70710678118f));
          }
          if (SPLIT) {
            int b = r / TLEN, t = r % TLEN;
            int hd = c >> 5, dh = c & 31;
            *(float2*)&C[(((long)b*NHEADS + hd)*TLEN + t)*DHEAD + dh] = make_float2(vx, vy);
          } else {
            *(float2*)&C[(long)r*N + c] = make_float2(vx, vy);
          }
        }
      }
    }
  }
}

// ---------------- fused rotation + argmax: REDUX-based ----------------
#define ROT_ROWS 64
__global__ void __launch_bounds__(128) rot_argmax_kernel(const float* __restrict__ rot_l) {
  __shared__ __align__(16) float qT[32][ROT_ROWS + 4];   // [d][row]
  int tid = threadIdx.x, lane = tid & 31, h = tid >> 5;
  long row0 = (long)blockIdx.x * ROT_ROWS;   // in bh*TLEN + t space
  int bh = (int)(row0 >> 12);
  int t0 = (int)(row0 & (TLEN - 1));

  float rcol[32];
  #pragma unroll
  for (int d = 0; d < 32; d++) rcol[d] = rot_l[d*128 + tid];

  {
    int r = tid >> 1;
    int half = (tid & 1) * 16;
    const float* gq = g_qk + (row0 + r)*DHEAD + half;
    #pragma unroll
    for (int f = 0; f < 4; f++) {
      float4 v = *(const float4*)(gq + f*4);
      qT[half + f*4 + 0][r] = v.x; qT[half + f*4 + 1][r] = v.y;
      qT[half + f*4 + 2][r] = v.z; qT[half + f*4 + 3][r] = v.w;
    }
  }
  __syncthreads();

  unsigned char* bp = g_bkt + (bh*NHASH + h)*TLEN + t0;
  #pragma unroll 4
  for (int rg = 0; rg < ROT_ROWS/4; rg++) {
    float a0 = 0.f, a1 = 0.f, a2 = 0.f, a3 = 0.f;
    #pragma unroll
    for (int d = 0; d < 32; d++) {
      float4 q4 = *(const float4*)&qT[d][rg*4];
      float r = rcol[d];
      a0 += q4.x * r; a1 += q4.y * r; a2 += q4.z * r; a3 += q4.w * r;
    }
    #pragma unroll
    for (int rr = 0; rr < 4; rr++) {
      float v = (rr == 0) ? a0 : (rr == 1) ? a1 : (rr == 2) ? a2 : a3;
      uint32_t key = __float_as_uint(fabsf(v));
      uint32_t mx = __reduce_max_sync(0xffffffffu, key);
      bool eq = (key == mx);
      bool pos = (v >= -v);
      unsigned bpos = __ballot_sync(0xffffffffu, eq && pos);
      unsigned bneg = __ballot_sync(0xffffffffu, eq && !pos);
      int bucket = bpos ? (__ffs(bpos) - 1) : (__ffs(bneg) + 31);
      if (lane == 0) bp[rg*4 + rr] = (unsigned char)bucket;
    }
  }
}

// ---------------- counting sort ----------------
__global__ void hist_kernel() {
  __shared__ int cnt[256];
  int bh = blockIdx.x, tid = threadIdx.x;
  cnt[tid] = 0; __syncthreads();
  const unsigned char* bp = g_bkt + bh*ITEMS;
  for (int i = tid; i < ITEMS; i += 256) {
    int gb = ((i >> 12) << 6) + bp[i];
    atomicAdd(&cnt[gb], 1);
  }
  __syncthreads();
  if (tid == 0) {
    int s = 0;
    #pragma unroll 8
    for (int j = 0; j < 256; j++) { g_base[bh*256 + j] = s; s += cnt[j]; }
  }
}

__global__ void __launch_bounds__(1024) place_kernel() {
  int bhh = blockIdx.x;
  int bh = bhh >> 2, h = bhh & 3;
  int warp = threadIdx.x >> 5, lane = threadIdx.x & 31;
  const unsigned char* bp = g_bkt + (bh*NHASH + h)*TLEN;
  #pragma unroll
  for (int s = 0; s < 2; s++) {
    int lb = warp*2 + s;
    int base = g_base[bh*256 + h*64 + lb];
    for (int t0 = 0; t0 < TLEN; t0 += 32) {
      int my = bp[t0 + lane];
      unsigned mask = __ballot_sync(0xffffffffu, my == lb);
      if (my == lb) {
        int p = base + __popc(mask & ((1u << lane) - 1u));
        g_st[bh*ITEMS + p] = t0 + lane;
        g_pos[(bh*NHASH + h)*TLEN + t0 + lane] = p;
      }
      base += __popc(mask);
    }
  }
}

// ---------------- tensor-core LSH attention (fp16 output, merged Q/K load) ----------------
// dyn smem (uint32 words):
//   region A @0, 8448 words: phase1 = qS[64][36] (0..2304) + kTd[32][136] (2304..6656)
//                             phase2 = pS[64][132] (aliases region A; per-warp rows only)
//   vS [128][40] @ 8448 (5120 words, stride 40 -> conflict-free PV B loads)
//   sQt[64] @ 13568, sKt[128] @ 13632
#define ATTN_SMEM_WORDS 13760
__global__ void __launch_bounds__(128, 4) attn_kernel() {
  extern __shared__ __align__(16) uint32_t smw[];
  uint32_t* qS  = smw;
  uint32_t* kTd = smw + 2304;
  uint32_t* pS  = smw;          // aliases qS/kTd after phase-1 sync
  uint32_t* vS  = smw + 8448;
  int* sQt = (int*)(smw + 13568);
  int* sKt = (int*)(smw + 13632);

  int bh = blockIdx.x >> 8;
  int c  = blockIdx.x & 255;
  int pc = (c + 255) & 255;
  int tid = threadIdx.x;
  int lane = tid & 31, warp = tid >> 5;
  int g = lane >> 2, l4 = lane & 3;

  {
    int p = (tid < 64) ? (c*64 + tid) : (pc*64 + (tid - 64));
    sKt[tid] = g_st[bh*ITEMS + p];
    if (tid < 64) sQt[tid] = sKt[tid];
  }
  __syncthreads();

  {
    int j = tid;
    int t = sKt[j];
    const float* gk = g_qk + ((long)bh*TLEN + t)*DHEAD;
    const float* gv = g_v  + ((long)bh*TLEN + t)*DHEAD;
    float4 kr[8];
    float ss = 0.f;
    #pragma unroll
    for (int f = 0; f < 8; f++) {
      kr[f] = *(const float4*)(gk + f*4);
      ss += kr[f].x*kr[f].x + kr[f].y*kr[f].y + kr[f].z*kr[f].z + kr[f].w*kr[f].w;
    }
    // Q (raw) for the first 64 rows: same data, reuse the load
    if (j < 64) {
      #pragma unroll
      for (int f = 0; f < 8; f++) {
        uint4 u;
        u.x = f2tf(kr[f].x); u.y = f2tf(kr[f].y); u.z = f2tf(kr[f].z); u.w = f2tf(kr[f].w);
        *(uint4*)&qS[j*36 + f*4] = u;
      }
    }
    float inv = ATTN_SCALE / fmaxf(sqrtf(ss), 1e-12f);
    #pragma unroll
    for (int f = 0; f < 8; f++) {
      kTd[(f*4+0)*136 + j] = f2tf(kr[f].x * inv);
      kTd[(f*4+1)*136 + j] = f2tf(kr[f].y * inv);
      kTd[(f*4+2)*136 + j] = f2tf(kr[f].z * inv);
      kTd[(f*4+3)*136 + j] = f2tf(kr[f].w * inv);
    }
    #pragma unroll
    for (int f = 0; f < 8; f++) {
      float4 vv = *(const float4*)(gv + f*4);
      uint4 u;
      u.x = f2tf(vv.x); u.y = f2tf(vv.y); u.z = f2tf(vv.z); u.w = f2tf(vv.w);
      *(uint4*)&vS[j*40 + f*4] = u;
    }
  }
  __syncthreads();

  // ---- phase 1: dots S = Q*K^T ----
  int mb = warp * 16;
  float s[16][4];
  #pragma unroll
  for (int nt = 0; nt < 16; nt++)
    #pragma unroll
    for (int p = 0; p < 4; p++) s[nt][p] = 0.f;
  #pragma unroll
  for (int k8 = 0; k8 < 32; k8 += 8) {
    uint32_t afr[4];
    afr[0] = qS[(mb + g    )*36 + k8 + l4];
    afr[1] = qS[(mb + g + 8)*36 + k8 + l4];
    afr[2] = qS[(mb + g    )*36 + k8 + l4 + 4];
    afr[3] = qS[(mb + g + 8)*36 + k8 + l4 + 4];
    #pragma unroll
    for (int nt = 0; nt < 16; nt++) {
      uint32_t bfr[2];
      bfr[0] = kTd[(k8 + l4    )*136 + nt*8 + g];
      bfr[1] = kTd[(k8 + l4 + 4)*136 + nt*8 + g];
      mma_tf32(s[nt], afr, bfr);
    }
  }
  __syncthreads();   // all phase-1 reads of qS/kTd done -> pS may alias them

  // ---- self-mask + softmax; write P (per-warp rows only) ----
  int r0 = mb + g, r1 = mb + g + 8;
  int qt0 = sQt[r0], qt1 = sQt[r1];
  float m0 = -1e30f, m1 = -1e30f;
  #pragma unroll
  for (int nt = 0; nt < 16; nt++) {
    int j0 = nt*8 + 2*l4;
    int kt0 = sKt[j0], kt1 = sKt[j0+1];
    if (kt0 == qt0) s[nt][0] = -5e4f;
    if (kt1 == qt0) s[nt][1] = -5e4f;
    if (kt0 == qt1) s[nt][2] = -5e4f;
    if (kt1 == qt1) s[nt][3] = -5e4f;
    m0 = fmaxf(m0, fmaxf(s[nt][0], s[nt][1]));
    m1 = fmaxf(m1, fmaxf(s[nt][2], s[nt][3]));
  }
  m0 = fmaxf(m0, __shfl_xor_sync(0xffffffffu, m0, 1));
  m0 = fmaxf(m0, __shfl_xor_sync(0xffffffffu, m0, 2));
  m1 = fmaxf(m1, __shfl_xor_sync(0xffffffffu, m1, 1));
  m1 = fmaxf(m1, __shfl_xor_sync(0xffffffffu, m1, 2));
  float sum0 = 0.f, sum1 = 0.f;
  #pragma unroll
  for (int nt = 0; nt < 16; nt++) {
    int j0 = nt*8 + 2*l4;
    uint32_t e00 = f2tf(__expf(s[nt][0] - m0));
    uint32_t e01 = f2tf(__expf(s[nt][1] - m0));
    uint32_t e10 = f2tf(__expf(s[nt][2] - m1));
    uint32_t e11 = f2tf(__expf(s[nt][3] - m1));
    sum0 += __uint_as_float(e00) + __uint_as_float(e01);
    sum1 += __uint_as_float(e10) + __uint_as_float(e11);
    *(uint2*)&pS[r0*132 + j0] = make_uint2(e00, e01);
    *(uint2*)&pS[r1*132 + j0] = make_uint2(e10, e11);
  }
  sum0 += __shfl_xor_sync(0xffffffffu, sum0, 1);
  sum0 += __shfl_xor_sync(0xffffffffu, sum0, 2);
  sum1 += __shfl_xor_sync(0xffffffffu, sum1, 1);
  sum1 += __shfl_xor_sync(0xffffffffu, sum1, 2);
  if (l4 == 0) {
    g_lse[bh*ITEMS + c*64 + r0] = m0 + __logf(sum0);
    g_lse[bh*ITEMS + c*64 + r1] = m1 + __logf(sum1);
  }
  __syncwarp();   // pS rows are per-warp; only warp-level visibility needed

  // ---- phase 2: PV ----
  float o[4][4];
  #pragma unroll
  for (int nt = 0; nt < 4; nt++)
    #pragma unroll
    for (int p = 0; p < 4; p++) o[nt][p] = 0.f;
  #pragma unroll
  for (int k8 = 0; k8 < 128; k8 += 8) {
    uint32_t afr[4];
    afr[0] = pS[(mb + g    )*132 + k8 + l4];
    afr[1] = pS[(mb + g + 8)*132 + k8 + l4];
    afr[2] = pS[(mb + g    )*132 + k8 + l4 + 4];
    afr[3] = pS[(mb + g + 8)*132 + k8 + l4 + 4];
    #pragma unroll
    for (int nt = 0; nt < 4; nt++) {
      uint32_t bfr[2];
      bfr[0] = vS[(k8 + l4    )*40 + nt*8 + g];
      bfr[1] = vS[(k8 + l4 + 4)*40 + nt*8 + g];
      mma_tf32(o[nt], afr, bfr);
    }
  }
  float inv0 = 1.f / sum0, inv1 = 1.f / sum1;
  __half* outp = g_so16 + ((long)bh*ITEMS + (long)c*64)*DHEAD;
  #pragma unroll
  for (int nt = 0; nt < 4; nt++) {
    int d0 = nt*8 + 2*l4;
    *(__half2*)&outp[r0*DHEAD + d0] = __floats2half2_rn(o[nt][0]*inv0, o[nt][1]*inv0);
    *(__half2*)&outp[r1*DHEAD + d0] = __floats2half2_rn(o[nt][2]*inv1, o[nt][3]*inv1);
  }
}

// ---------------- cross-hash combine ----------------
__global__ void combine_kernel() {
  int tid = threadIdx.x;
  int lane = tid & 31;
  long gw = (long)blockIdx.x * 4 + (tid >> 5);
  int bh = (int)(gw >> 12);
  int t  = (int)(gw & (TLEN - 1));
  float lse[NHASH], val[NHASH];
  int pidx[NHASH];
  #pragma unroll
  for (int h = 0; h < NHASH; h++) {
    pidx[h] = g_pos[(bh*NHASH + h)*TLEN + t];
    lse[h]  = g_lse[bh*ITEMS + pidx[h]];
    val[h]  = __half2float(g_so16[((long)bh*ITEMS + pidx[h])*DHEAD + lane]);
  }
  float m = lse[0];
  #pragma unroll
  for (int h = 1; h < NHASH; h++) m = fmaxf(m, lse[h]);
  float acc = 0.f, wsum = 0.f;
  #pragma unroll
  for (int h = 0; h < NHASH; h++) {
    float w = __expf(lse[h] - m);
    acc += w * val[h]; wsum += w;
  }
  int b = bh >> 2, head = bh & 3;
  g_attn[((long)b*TLEN + t)*DMODEL + head*DHEAD + lane] = acc / wsum;
}

// ---------------- layernorm (final only) ----------------
__global__ void ln_kernel(const float* __restrict__ in, float* __restrict__ out,
                          const float* __restrict__ g, const float* __restrict__ bb) {
  int row = blockIdx.x, d = threadIdx.x;
  __shared__ float red[4];
  float x = in[(long)row*DMODEL + d];
  float s = x;
  #pragma unroll
  for (int off = 16; off; off >>= 1) s += __shfl_xor_sync(0xffffffffu, s, off);
  if ((d & 31) == 0) red[d >> 5] = s;
  __syncthreads();
  float mean = (red[0]+red[1]+red[2]+red[3]) * (1.f/DMODEL);
  float dv = x - mean;
  float s2 = dv*dv;
  #pragma unroll
  for (int off = 16; off; off >>= 1) s2 += __shfl_xor_sync(0xffffffffu, s2, off);
  __syncthreads();
  if ((d & 31) == 0) red[d >> 5] = s2;
  __syncthreads();
  float var = (red[0]+red[1]+red[2]+red[3]) * (1.f/DMODEL);
  out[(long)row*DMODEL + d] = dv * rsqrtf(var + 1e-5f) * g[d] + bb[d];
}

// ---------------- final head ----------------
__global__ void head_kernel(const float* __restrict__ projw, const float* __restrict__ projb,
                            const float* __restrict__ fcw, const float* __restrict__ fcb,
                            float* __restrict__ dout) {
  int b = blockIdx.x, tid = threadIdx.x;
  float lg0 = 0.f, lg1 = 0.f, lg2 = 0.f;
  for (int tt = tid; tt < PRED; tt += 128) {
    const float* hh = g_res + ((long)b*TLEN + SENC + tt)*DMODEL;
    float o4[4];
    #pragma unroll
    for (int cc = 0; cc < 4; cc++) {
      float a = projb[cc];
      #pragma unroll 8
      for (int d = 0; d < DMODEL; d++) a += hh[d]*projw[d*4 + cc];
      o4[cc] = a;
    }
    #pragma unroll
    for (int cc = 0; cc < 4; cc++) {
      int idx = (tt*4 + cc)*3;
      lg0 += o4[cc]*fcw[idx+0];
      lg1 += o4[cc]*fcw[idx+1];
      lg2 += o4[cc]*fcw[idx+2];
    }
  }
  __shared__ float red[3][128];
  red[0][tid] = lg0; red[1][tid] = lg1; red[2][tid] = lg2;
  __syncthreads();
  for (int off = 64; off; off >>= 1) {
    if (tid < off) {
      red[0][tid] += red[0][tid+off];
      red[1][tid] += red[1][tid+off];
      red[2][tid] += red[2][tid+off];
    }
    __syncthreads();
  }
  if (tid == 0) {
    float l0 = red[0][0]+fcb[0], l1 = red[1][0]+fcb[1], l2 = red[2][0]+fcb[2];
    float mx = fmaxf(l0, fmaxf(l1, l2));
    float e0 = expf(l0-mx), e1 = expf(l1-mx), e2 = expf(l2-mx);
    float is = 1.f/(e0+e1+e2);
    dout[b*3+0] = e0*is; dout[b*3+1] = e1*is; dout[b*3+2] = e2*is;
  }
}

// ---------------- host launch ----------------
extern "C" void kernel_launch(void* const* d_in, const int* in_sizes, int n_in,
                              void* d_out, int out_size) {
  const float* x_enc      = (const float*)d_in[0];
  const float* x_mark_enc = (const float*)d_in[1];
  const float* x_dec      = (const float*)d_in[2];
  const float* x_mark_dec = (const float*)d_in[3];
  const float* conv_w     = (const float*)d_in[4];
  const float* timef_w    = (const float*)d_in[5];
  const float* Wqk        = (const float*)d_in[6];
  const float* Wv         = (const float*)d_in[7];
  const float* Wo         = (const float*)d_in[8];
  const float* bo         = (const float*)d_in[9];
  const float* rot        = (const float*)d_in[10];
  const float* ln1_g      = (const float*)d_in[11];
  const float* ln1_b      = (const float*)d_in[12];
  const float* ln2_g      = (const float*)d_in[13];
  const float* ln2_b      = (const float*)d_in[14];
  const float* w1         = (const float*)d_in[15];
  const float* b1         = (const float*)d_in[16];
  const float* w2         = (const float*)d_in[17];
  const float* b2         = (const float*)d_in[18];
  const float* lnf_g      = (const float*)d_in[19];
  const float* lnf_b      = (const float*)d_in[20];
  const float* proj_w     = (const float*)d_in[21];
  const float* proj_b     = (const float*)d_in[22];
  const float* fc1_w      = (const float*)d_in[23];
  const float* fc1_b      = (const float*)d_in[24];
  (void)in_sizes; (void)n_in; (void)out_size;

  void* p;
  cudaGetSymbolAddress(&p, g_h);    float* ph    = (float*)p;
  cudaGetSymbolAddress(&p, g_res);  float* pres  = (float*)p;
  cudaGetSymbolAddress(&p, g_ff);   float* pff   = (float*)p;
  cudaGetSymbolAddress(&p, g_qk);   float* pqk   = (float*)p;
  cudaGetSymbolAddress(&p, g_v);    float* pv    = (float*)p;
  cudaGetSymbolAddress(&p, g_attn); float* pattn = (float*)p;

  const int attn_smem = ATTN_SMEM_WORDS * 4;
  cudaFuncSetAttribute(attn_kernel, cudaFuncAttributeMaxDynamicSharedMemorySize, attn_smem);

  embed_kernel<<<MROWS, 128>>>(x_enc, x_mark_enc, x_dec, x_mark_dec, conv_w, timef_w);

  for (int l = 0; l < NLAYERS; l++) {
    const float* Wqk_l = Wqk + (long)l*DMODEL*DMODEL;
    const float* Wv_l  = Wv  + (long)l*DMODEL*DMODEL;
    const float* Wo_l  = Wo  + (long)l*DMODEL*DMODEL;
    const float* bo_l  = bo  + l*DMODEL;
    const float* rot_l = rot + (long)l*DHEAD*NHASH*(NBUCK/2);
    const float* w1_l  = w1 + (long)l*DMODEL*DFF;
    const float* b1_l  = b1 + l*DFF;
    const float* w2_l  = w2 + (long)l*DFF*DMODEL;
    const float* b2_l  = b2 + l*DMODEL;

    gemm_qk_tf32x3<<<dim3(1,256), 256>>>(ph, Wqk_l, pqk, MROWS, DMODEL, DMODEL);
    gemm_tf32<0,1><<<dim3(1,256), 256>>>(ph, Wv_l, nullptr, nullptr, nullptr, nullptr, pv, MROWS, DMODEL, DMODEL);

    rot_argmax_kernel<<<BHN*TLEN/ROT_ROWS, 128>>>(rot_l);

    hist_kernel<<<BHN, 256>>>();
    place_kernel<<<BHN*NHASH, 1024>>>();

    attn_kernel<<<BHN*NCHUNK, 128, attn_smem>>>();
    combine_kernel<<<BHN*TLEN/4, 128>>>();

    gemm_tf32<1,0><<<dim3(1,256), 256>>>(pattn, Wo_l, bo_l, ph, ln1_g + l*DMODEL, ln1_b + l*DMODEL,
                                         ph, MROWS, DMODEL, DMODEL);
    gemm_tf32<3,0><<<dim3(4,256), 256>>>(ph, w1_l, b1_l, nullptr, nullptr, nullptr, pff, MROWS, DFF, DMODEL);
    gemm_tf32<1,0><<<dim3(1,256), 256>>>(pff, w2_l, b2_l, ph, ln2_g + l*DMODEL, ln2_b + l*DMODEL,
                                         ph, MROWS, DMODEL, DFF);
  }

  ln_kernel<<<MROWS, 128>>>(ph, pres, lnf_g, lnf_b);
  head_kernel<<<BSZ, 128>>>(proj_w, proj_b, fc1_w, fc1_b, (float*)d_out);
}